// round 7
// baseline (speedup 1.0000x reference)
#include <cuda_runtime.h>
#include <math.h>

// ---------------- problem constants ----------------
static constexpr int Bn = 32, Cn = 32, Sn = 16, En = 1280, Rn = 256;
static constexpr int Hn = 4, HDn = 64, FFn = 512;
static constexpr int BC = Bn * Cn;               // 1024 tokens
static constexpr int HEAD_IN = Cn * Rn + 64 + 32 + 3;  // 8291
static constexpr int QKVn = 3 * Rn;              // 768

static constexpr int NBLK = 148;                 // persistent blocks (<= #SMs)
static constexpr int NTHR = 512;                 // threads per block (4 groups of 128)
static constexpr int NGRP = 4 * NBLK;            // 592 worker groups

// ---------------- device scratch ----------------
__device__ float g_aw[BC * Sn];
__device__ __align__(16) float g_agg[BC * En];
__device__ __align__(16) float g_x0p[4 * BC * Rn];    // x0 partials (split 4)
__device__ __align__(16) float g_qkvp[2 * BC * QKVn]; // qkv partials (split 2)
__device__ __align__(16) float g_att[BC * Rn];
__device__ __align__(16) float g_opp[4 * BC * Rn];    // oproj partials (split 4)
__device__ __align__(16) float g_x1[BC * Rn];
__device__ __align__(16) float g_ff1p[2 * BC * FFn];  // ff1 partials (split 2)
__device__ __align__(16) float g_fpp[4 * BC * Rn];    // ff2 partials (split 4)
__device__ __align__(16) float g_x2[BC * Rn];
__device__ __align__(16) float g_h[Bn * 128];
__device__ unsigned g_bar[16];                        // monotonic barrier counters

// ---------------- shared memory (union across phases) ----------------
struct GemmSmem { float As[2][16][32]; float Bs[2][16][64]; };          // 12 KB
struct AttnSmem { float ks[32 * 65]; float vs[32 * 65]; float qs[16 * 65]; float sc[16 * 33]; };
union SmemU {
    GemmSmem g[4];   // 48 KB
    AttnSmem a[4];   // ~89.5 KB
};

// ---------------- grid-wide barrier (monotonic, replay-safe) ----------------
__device__ __forceinline__ void gsync(int k) {
    __syncthreads();
    if (threadIdx.x == 0) {
        __threadfence();
        unsigned old = atomicAdd(&g_bar[k], 1u);
        unsigned target = (old / NBLK + 1u) * NBLK;
        volatile unsigned* p = &g_bar[k];
        while (*p < target) { }
        __threadfence();
    }
    __syncthreads();
}

// group barrier: 128 threads, named barrier id 1..4
#define GBAR(id) asm volatile("bar.sync %0, %1;" :: "r"(id), "r"(128) : "memory")

// ---------------- helpers ----------------
template <int NP, bool RELUA>
__device__ __forceinline__ float4 loadPre(const float* __restrict__ A,
                                          const float* __restrict__ ab,
                                          size_t idx, int bcol, size_t SA) {
    float4 v = *(const float4*)(A + idx);
    if (NP >= 2) {
        float4 t = *(const float4*)(A + SA + idx);
        v.x += t.x; v.y += t.y; v.z += t.z; v.w += t.w;
    }
    if (NP >= 4) {
        float4 t = *(const float4*)(A + 2 * SA + idx);
        float4 u = *(const float4*)(A + 3 * SA + idx);
        v.x += t.x + u.x; v.y += t.y + u.y; v.z += t.z + u.z; v.w += t.w + u.w;
    }
    if (NP > 0) {
        float4 bb = *(const float4*)(ab + bcol);
        v.x += bb.x; v.y += bb.y; v.z += bb.z; v.w += bb.w;
        if (RELUA) {
            v.x = fmaxf(v.x, 0.f); v.y = fmaxf(v.y, 0.f);
            v.z = fmaxf(v.z, 0.f); v.w = fmaxf(v.w, 0.f);
        }
    }
    return v;
}

__device__ __forceinline__ float4 sum2b(const float* __restrict__ P, size_t idx, size_t S,
                                        const float* __restrict__ bias, int bi) {
    float4 a = *(const float4*)(P + idx);
    float4 b = *(const float4*)(P + S + idx);
    float4 c = *(const float4*)(bias + bi);
    a.x += b.x + c.x; a.y += b.y + c.y; a.z += b.z + c.z; a.w += b.w + c.w;
    return a;
}

// ---------------- GEMM worker (128-thread group): C(part z) = A[M,K] @ B[N,K]^T ----------------
// tile 32x64, BK=16, TM=4, TN=4; double-buffered; group-strided over tiles.
template <int NP, bool RELUA>
__device__ void gemm_phase(const float* __restrict__ A, const float* __restrict__ ab,
                           const float* __restrict__ B, float* __restrict__ C,
                           int N, int K, int ntn, int nsplit, int KS, size_t SA,
                           float* __restrict__ As, float* __restrict__ Bs,
                           int ltid, int barid, int grp) {
    const int ntpz = ntn * 32;                  // tiles per split (BC/32 = 32 m-tiles)
    const int ntiles = ntpz * nsplit;
    const int tx = ltid & 15, ty = ltid >> 4;
    for (int tile = grp; tile < ntiles; tile += NGRP) {
        int z = tile / ntpz;
        int rem = tile - z * ntpz;
        int m = rem / ntn, n = rem - m * ntn;
        int bm0 = m * 32, bn0 = n * 64, k0s = z * KS;

        float acc[4][4];
        #pragma unroll
        for (int i = 0; i < 4; i++)
            #pragma unroll
            for (int j = 0; j < 4; j++) acc[i][j] = 0.f;

        // preload k-tile 0 into buffer 0 (A: 1 float4/thread, B: 2)
        {
            int rowA = ltid >> 2, c4A = (ltid & 3) * 4;
            int kcol = k0s + c4A;
            float4 v = loadPre<NP, RELUA>(A, ab, (size_t)(bm0 + rowA) * K + kcol, kcol, SA);
            As[(c4A + 0) * 32 + rowA] = v.x; As[(c4A + 1) * 32 + rowA] = v.y;
            As[(c4A + 2) * 32 + rowA] = v.z; As[(c4A + 3) * 32 + rowA] = v.w;
            #pragma unroll
            for (int it = 0; it < 2; it++) {
                int f = ltid + it * 128;
                int row = f >> 2, c4 = (f & 3) * 4;
                float4 w = *(const float4*)&B[(size_t)(bn0 + row) * K + k0s + c4];
                Bs[(c4 + 0) * 64 + row] = w.x; Bs[(c4 + 1) * 64 + row] = w.y;
                Bs[(c4 + 2) * 64 + row] = w.z; Bs[(c4 + 3) * 64 + row] = w.w;
            }
        }
        GBAR(barid);

        int p = 0;
        const int nt = KS / 16;
        for (int t = 0; t < nt; t++) {
            float4 pa, pb[2];
            const bool has = (t + 1) < nt;
            if (has) {
                int kn = k0s + (t + 1) * 16;
                int rowA = ltid >> 2, c4A = (ltid & 3) * 4;
                int kcol = kn + c4A;
                pa = loadPre<NP, RELUA>(A, ab, (size_t)(bm0 + rowA) * K + kcol, kcol, SA);
                #pragma unroll
                for (int it = 0; it < 2; it++) {
                    int f = ltid + it * 128;
                    int row = f >> 2, c4 = (f & 3) * 4;
                    pb[it] = *(const float4*)&B[(size_t)(bn0 + row) * K + kn + c4];
                }
            }
            const float* Ap = As + p * 512;
            const float* Bp = Bs + p * 1024;
            #pragma unroll
            for (int kk = 0; kk < 16; kk++) {
                float a[4], b[4];
                *(float4*)&a[0] = *(const float4*)&Ap[kk * 32 + ty * 4];
                *(float4*)&b[0] = *(const float4*)&Bp[kk * 64 + tx * 4];
                #pragma unroll
                for (int i = 0; i < 4; i++)
                    #pragma unroll
                    for (int j = 0; j < 4; j++) acc[i][j] = fmaf(a[i], b[j], acc[i][j]);
            }
            if (has) {
                float* Aq = As + (1 - p) * 512;
                float* Bq = Bs + (1 - p) * 1024;
                int rowA = ltid >> 2, c4A = (ltid & 3) * 4;
                Aq[(c4A + 0) * 32 + rowA] = pa.x; Aq[(c4A + 1) * 32 + rowA] = pa.y;
                Aq[(c4A + 2) * 32 + rowA] = pa.z; Aq[(c4A + 3) * 32 + rowA] = pa.w;
                #pragma unroll
                for (int it = 0; it < 2; it++) {
                    int f = ltid + it * 128;
                    int row = f >> 2, c4 = (f & 3) * 4;
                    Bq[(c4 + 0) * 64 + row] = pb[it].x; Bq[(c4 + 1) * 64 + row] = pb[it].y;
                    Bq[(c4 + 2) * 64 + row] = pb[it].z; Bq[(c4 + 3) * 64 + row] = pb[it].w;
                }
            }
            GBAR(barid);
            p ^= 1;
        }

        float* Cout = C + (size_t)z * BC * N;
        #pragma unroll
        for (int i = 0; i < 4; i++) {
            float4 o = make_float4(acc[i][0], acc[i][1], acc[i][2], acc[i][3]);
            *(float4*)&Cout[(size_t)(bm0 + ty * 4 + i) * N + bn0 + tx * 4] = o;
        }
    }
}

// ---------------- attention worker (128-thread group) ----------------
// unit = (b, h, qhalf): 16 query rows vs all 32 keys. qkv = sum of 2 partials + bias.
__device__ void attn_phase(AttnSmem* s, const float* __restrict__ bqkv,
                           int ltid, int barid, int grp) {
    constexpr size_t SQ = (size_t)BC * QKVn;
    for (int u = grp; u < Bn * Hn * 2; u += NGRP) {
        int b = u >> 3, h = (u >> 1) & 3, half = u & 1;
        int q0 = half * 16;
        #pragma unroll
        for (int it = 0; it < 4; it++) {
            int f = ltid + it * 128;
            int c = f >> 4, d4 = (f & 15) * 4;
            size_t base = (size_t)(b * Cn + c) * QKVn + h * HDn + d4;
            float4 kv = sum2b(g_qkvp, base + Rn, SQ, bqkv, Rn + h * HDn + d4);
            float4 vv = sum2b(g_qkvp, base + 2 * Rn, SQ, bqkv, 2 * Rn + h * HDn + d4);
            s->ks[c * 65 + d4 + 0] = kv.x; s->ks[c * 65 + d4 + 1] = kv.y;
            s->ks[c * 65 + d4 + 2] = kv.z; s->ks[c * 65 + d4 + 3] = kv.w;
            s->vs[c * 65 + d4 + 0] = vv.x; s->vs[c * 65 + d4 + 1] = vv.y;
            s->vs[c * 65 + d4 + 2] = vv.z; s->vs[c * 65 + d4 + 3] = vv.w;
        }
        #pragma unroll
        for (int it = 0; it < 2; it++) {
            int f = ltid + it * 128;
            int c = f >> 4, d4 = (f & 15) * 4;
            size_t base = (size_t)(b * Cn + q0 + c) * QKVn + h * HDn + d4;
            float4 qv = sum2b(g_qkvp, base, SQ, bqkv, h * HDn + d4);
            s->qs[c * 65 + d4 + 0] = qv.x; s->qs[c * 65 + d4 + 1] = qv.y;
            s->qs[c * 65 + d4 + 2] = qv.z; s->qs[c * 65 + d4 + 3] = qv.w;
        }
        GBAR(barid);
        #pragma unroll
        for (int r = 0; r < 4; r++) {
            int i = ltid + r * 128;
            int k = i & 31, q = i >> 5;
            float sum = 0.f;
            #pragma unroll
            for (int d = 0; d < HDn; d++) sum = fmaf(s->qs[q * 65 + d], s->ks[k * 65 + d], sum);
            s->sc[q * 33 + k] = sum * 0.125f;
        }
        GBAR(barid);
        if (ltid < 16) {
            float mx = -1e30f;
            #pragma unroll
            for (int k = 0; k < Cn; k++) mx = fmaxf(mx, s->sc[ltid * 33 + k]);
            float sum = 0.f;
            #pragma unroll
            for (int k = 0; k < Cn; k++) {
                float e = expf(s->sc[ltid * 33 + k] - mx);
                s->sc[ltid * 33 + k] = e; sum += e;
            }
            float inv = 1.f / sum;
            #pragma unroll
            for (int k = 0; k < Cn; k++) s->sc[ltid * 33 + k] *= inv;
        }
        GBAR(barid);
        #pragma unroll
        for (int r = 0; r < 8; r++) {
            int i = ltid + r * 128;
            int d = i & 63, q = i >> 6;
            float sum = 0.f;
            #pragma unroll
            for (int k = 0; k < Cn; k++) sum = fmaf(s->sc[q * 33 + k], s->vs[k * 65 + d], sum);
            g_att[(size_t)(b * Cn + q0 + q) * Rn + h * HDn + d] = sum;
        }
        GBAR(barid);   // smem reused by next unit
    }
}

// ---------------- LayerNorm worker: one warp per row ----------------
// NPA: residual partial count in a (1 = plain). NPP: partial count in p.
template <int NPA, int NPP>
__device__ void ln_phase(const float* __restrict__ a, const float* __restrict__ ab,
                         const float* __restrict__ p, const float* __restrict__ pb,
                         const float* __restrict__ g, const float* __restrict__ be,
                         float* __restrict__ out) {
    int row = blockIdx.x * (NTHR / 32) + (threadIdx.x >> 5);
    if (row >= BC) return;
    const size_t S = (size_t)BC * Rn;
    int lane = threadIdx.x & 31;
    float v[8];
    #pragma unroll
    for (int j = 0; j < 8; j++) {
        int c = lane + 32 * j;
        size_t o = (size_t)row * Rn + c;
        float x = a[o];
        if (NPA == 4) x += a[S + o] + a[2 * S + o] + a[3 * S + o] + ab[c];
        float y = p[o];
        if (NPP >= 2) y += p[S + o];
        if (NPP >= 4) y += p[2 * S + o] + p[3 * S + o];
        v[j] = x + y + pb[c];
    }
    float sum = 0.f;
    #pragma unroll
    for (int j = 0; j < 8; j++) sum += v[j];
    #pragma unroll
    for (int off = 16; off > 0; off >>= 1) sum += __shfl_xor_sync(0xffffffffu, sum, off);
    float mean = sum * (1.f / Rn);
    float q = 0.f;
    #pragma unroll
    for (int j = 0; j < 8; j++) { float d = v[j] - mean; q = fmaf(d, d, q); }
    #pragma unroll
    for (int off = 16; off > 0; off >>= 1) q += __shfl_xor_sync(0xffffffffu, q, off);
    float rstd = rsqrtf(q * (1.f / Rn) + 1e-5f);
    #pragma unroll
    for (int j = 0; j < 8; j++) {
        int c = lane + 32 * j;
        out[(size_t)row * Rn + c] = (v[j] - mean) * rstd * g[c] + be[c];
    }
}

// ---------------- megakernel ----------------
__global__ __launch_bounds__(NTHR)
void mega_kernel(const float* __restrict__ embs, const int* __restrict__ indices,
                 const int* __restrict__ mask, const float* __restrict__ host_cat,
                 const float* __restrict__ virus_cat, const float* __restrict__ extra_meta,
                 const float* __restrict__ fw,
                 const float* __restrict__ Wr, const float* __restrict__ br,
                 const float* __restrict__ Wqkv, const float* __restrict__ bqkv,
                 const float* __restrict__ Wo, const float* __restrict__ bo,
                 const float* __restrict__ ln1_g, const float* __restrict__ ln1_b,
                 const float* __restrict__ W1, const float* __restrict__ b1,
                 const float* __restrict__ W2, const float* __restrict__ b2,
                 const float* __restrict__ ln2_g, const float* __restrict__ ln2_b,
                 const float* __restrict__ Wc1, const float* __restrict__ bc1,
                 const float* __restrict__ Wc2, const float* __restrict__ bc2,
                 float* __restrict__ out) {
    __shared__ SmemU sm;
    const int tid = threadIdx.x;
    const int sub = tid >> 7;            // group in block: 0..3
    const int ltid = tid & 127;
    const int grp = blockIdx.x * 4 + sub;
    const int barid = 1 + sub;
    const int gid = blockIdx.x * NTHR + tid;

    // ---- P0: softmax weights per (b,c) segment ----
    if (gid < BC) {
        int bc = gid;
        float w[Sn]; int any = 0;
        #pragma unroll
        for (int s = 0; s < Sn; s++) {
            int m = mask[bc * Sn + s];
            any |= m;
            w[s] = m ? fw[indices[bc * Sn + s]] : -1e30f;
        }
        float mx = -1e30f;
        #pragma unroll
        for (int s = 0; s < Sn; s++) mx = fmaxf(mx, w[s]);
        float e[Sn], sum = 0.f;
        #pragma unroll
        for (int s = 0; s < Sn; s++) { e[s] = expf(w[s] - mx); sum += e[s]; }
        float inv = any ? (1.f / sum) : 0.f;
        #pragma unroll
        for (int s = 0; s < Sn; s++) g_aw[bc * Sn + s] = e[s] * inv;
    }
    gsync(0);

    // ---- P1: aggregation (HBM-bound) ----
    for (int u = gid; u < BC * (En / 4); u += NBLK * NTHR) {
        int bc = u / (En / 4);
        int col = u - bc * (En / 4);
        float aw[Sn];
        #pragma unroll
        for (int s = 0; s < Sn; s++) aw[s] = g_aw[bc * Sn + s];
        const float4* eb = (const float4*)embs + (size_t)bc * Sn * (En / 4) + col;
        float4 acc = make_float4(0.f, 0.f, 0.f, 0.f);
        #pragma unroll
        for (int s = 0; s < Sn; s++) {
            float4 v = eb[s * (En / 4)];
            acc.x = fmaf(aw[s], v.x, acc.x);
            acc.y = fmaf(aw[s], v.y, acc.y);
            acc.z = fmaf(aw[s], v.z, acc.z);
            acc.w = fmaf(aw[s], v.w, acc.w);
        }
        ((float4*)g_agg)[(size_t)bc * (En / 4) + col] = acc;
    }
    gsync(1);

    // ---- P2: x0 partials = agg @ Wr^T (split 4, KS=320) -> 512 tiles ----
    gemm_phase<0, false>(g_agg, nullptr, Wr, g_x0p, Rn, En, 4, 4, 320, 0,
                         &sm.g[sub].As[0][0][0], &sm.g[sub].Bs[0][0][0], ltid, barid, grp);
    gsync(2);

    // ---- P3: qkv partials = (sum4 x0p + br) @ Wqkv^T (split 2, KS=128) -> 768 tiles ----
    gemm_phase<4, false>(g_x0p, br, Wqkv, g_qkvp, QKVn, Rn, 12, 2, 128, (size_t)BC * Rn,
                         &sm.g[sub].As[0][0][0], &sm.g[sub].Bs[0][0][0], ltid, barid, grp);
    gsync(3);

    // ---- P4: attention ----
    attn_phase(&sm.a[sub], bqkv, ltid, barid, grp);
    gsync(4);

    // ---- P5: oproj partials = att @ Wo^T (split 4, KS=64) -> 512 tiles ----
    gemm_phase<0, false>(g_att, nullptr, Wo, g_opp, Rn, Rn, 4, 4, 64, 0,
                         &sm.g[sub].As[0][0][0], &sm.g[sub].Bs[0][0][0], ltid, barid, grp);
    gsync(5);

    // ---- P6: x1 = LN(sum4 x0p + br + sum4 opp + bo) ----
    ln_phase<4, 4>(g_x0p, br, g_opp, bo, ln1_g, ln1_b, g_x1);
    gsync(6);

    // ---- P7: ff1 partials = x1 @ W1^T (split 2, KS=128) -> 512 tiles ----
    gemm_phase<0, false>(g_x1, nullptr, W1, g_ff1p, FFn, Rn, 8, 2, 128, 0,
                         &sm.g[sub].As[0][0][0], &sm.g[sub].Bs[0][0][0], ltid, barid, grp);
    gsync(7);

    // ---- P8: ff2 partials = relu(sum2 ff1p + b1) @ W2^T (split 4, KS=128) -> 512 tiles ----
    gemm_phase<2, true>(g_ff1p, b1, W2, g_fpp, Rn, FFn, 4, 4, 128, (size_t)BC * FFn,
                        &sm.g[sub].As[0][0][0], &sm.g[sub].Bs[0][0][0], ltid, barid, grp);
    gsync(8);

    // ---- P9: x2 = LN(x1 + sum4 fpp + b2) ----
    ln_phase<1, 4>(g_x1, nullptr, g_fpp, b2, ln2_g, ln2_b, g_x2);
    gsync(9);

    // ---- P10: head layer 1: h[b][j] = relu(feat . Wc1[j] + bc1[j]) ----
    {
        int lane = ltid & 31, w = ltid >> 5;
        for (int u = grp; u < Bn * 4; u += NGRP) {
            int b = u >> 2, j0 = (u & 3) * 32;
            const float* xb = g_x2 + (size_t)b * Cn * Rn;
            const float* hc = host_cat + b * 64;
            const float* vc = virus_cat + b * 32;
            const float* mt = extra_meta + b * 3;
            for (int jj = w; jj < 32; jj += 4) {
                int j = j0 + jj;
                const float* wr = Wc1 + (size_t)j * HEAD_IN;
                float s = 0.f;
                for (int i = lane; i < Cn * Rn; i += 32) s = fmaf(wr[i], xb[i], s);
                for (int i = lane; i < 64; i += 32) s = fmaf(wr[Cn * Rn + i], hc[i], s);
                s = fmaf(wr[Cn * Rn + 64 + lane], vc[lane], s);
                if (lane < 3) s = fmaf(wr[Cn * Rn + 96 + lane], mt[lane], s);
                #pragma unroll
                for (int off = 16; off > 0; off >>= 1) s += __shfl_down_sync(0xffffffffu, s, off);
                if (lane == 0) g_h[b * 128 + j] = fmaxf(s + bc1[j], 0.f);
            }
        }
    }
    gsync(10);

    // ---- P11: logits ----
    {
        int gwarp = blockIdx.x * (NTHR / 32) + (tid >> 5);
        int lane = tid & 31;
        if (gwarp < Bn) {
            float v = 0.f;
            #pragma unroll
            for (int r = 0; r < 4; r++) {
                int i = lane + 32 * r;
                v = fmaf(g_h[gwarp * 128 + i], Wc2[i], v);
            }
            #pragma unroll
            for (int off = 16; off > 0; off >>= 1) v += __shfl_xor_sync(0xffffffffu, v, off);
            if (lane == 0) out[gwarp] = v + bc2[0];
        }
    }
}

// ---------------- launch ----------------
extern "C" void kernel_launch(void* const* d_in, const int* in_sizes, int n_in,
                              void* d_out, int out_size) {
    const float* embs        = (const float*)d_in[0];
    const int*   indices     = (const int*)d_in[1];
    const int*   mask        = (const int*)d_in[2];     // bool -> int32
    const float* host_cat    = (const float*)d_in[3];
    const float* virus_cat   = (const float*)d_in[4];
    const float* extra_meta  = (const float*)d_in[5];
    const float* func_weights= (const float*)d_in[6];
    const float* Wr          = (const float*)d_in[7];
    const float* br          = (const float*)d_in[8];
    const float* Wqkv        = (const float*)d_in[9];
    const float* bqkv        = (const float*)d_in[10];
    const float* Wo          = (const float*)d_in[11];
    const float* bo          = (const float*)d_in[12];
    const float* ln1_g       = (const float*)d_in[13];
    const float* ln1_b       = (const float*)d_in[14];
    const float* W1          = (const float*)d_in[15];
    const float* b1          = (const float*)d_in[16];
    const float* W2          = (const float*)d_in[17];
    const float* b2          = (const float*)d_in[18];
    const float* ln2_g       = (const float*)d_in[19];
    const float* ln2_b       = (const float*)d_in[20];
    const float* Wc1         = (const float*)d_in[21];
    const float* bc1         = (const float*)d_in[22];
    const float* Wc2         = (const float*)d_in[23];
    const float* bc2         = (const float*)d_in[24];
    float* out = (float*)d_out;

    mega_kernel<<<NBLK, NTHR>>>(embs, indices, mask, host_cat, virus_cat, extra_meta,
                                func_weights, Wr, br, Wqkv, bqkv, Wo, bo,
                                ln1_g, ln1_b, W1, b1, W2, b2, ln2_g, ln2_b,
                                Wc1, bc1, Wc2, bc2, out);
}

// round 8
// speedup vs baseline: 1.1313x; 1.1313x over previous
#include <cuda_runtime.h>
#include <math.h>

// ---------------- problem constants ----------------
static constexpr int Bn = 32, Cn = 32, Sn = 16, En = 1280, Rn = 256;
static constexpr int Hn = 4, HDn = 64, FFn = 512;
static constexpr int BC = Bn * Cn;               // 1024 tokens
static constexpr int HEAD_IN = Cn * Rn + 64 + 32 + 3;  // 8291
static constexpr int QKVn = 3 * Rn;              // 768

static constexpr int NBLK = 296;                 // persistent blocks (2 per SM)
static constexpr int NTHR = 256;                 // threads per block (2 groups of 128)
static constexpr int NGRP = 2 * NBLK;            // 592 worker groups

// ---------------- device scratch ----------------
__device__ float g_aw[BC * Sn];
__device__ __align__(16) float g_agg[BC * En];
__device__ __align__(16) float g_x0p[4 * BC * Rn];    // x0 partials (split 4)
__device__ __align__(16) float g_qkvp[2 * BC * QKVn]; // qkv partials (split 2)
__device__ __align__(16) float g_att[BC * Rn];
__device__ __align__(16) float g_opp[2 * BC * Rn];    // oproj partials (split 2)
__device__ __align__(16) float g_x1[BC * Rn];
__device__ __align__(16) float g_ff1p[2 * BC * FFn];  // ff1 partials (split 2)
__device__ __align__(16) float g_fpp[2 * BC * Rn];    // ff2 partials (split 2)
__device__ __align__(16) float g_x2[BC * Rn];
__device__ __align__(16) float g_h[Bn * 128];
__device__ unsigned g_bar[16];                        // monotonic barrier counters

// ---------------- shared memory (union across phases) ----------------
struct GemmSmem { float As[2][16][64]; float Bs[2][16][64]; };          // 16 KB
struct AttnSmem { float ks[32 * 65]; float vs[32 * 65]; float qs[16 * 65]; float sc[16 * 33]; };
union SmemU {
    GemmSmem g[2];   // 32 KB
    AttnSmem a[2];   // ~45.8 KB
};

// ---------------- grid-wide barrier (monotonic, replay-safe) ----------------
__device__ __forceinline__ void gsync(int k) {
    __syncthreads();
    if (threadIdx.x == 0) {
        __threadfence();
        unsigned old = atomicAdd(&g_bar[k], 1u);
        unsigned target = (old / NBLK + 1u) * NBLK;
        volatile unsigned* p = &g_bar[k];
        while (*p < target) { }
        __threadfence();
    }
    __syncthreads();
}

// group barrier: 128 threads, named barrier id 1 or 2
#define GBAR(id) asm volatile("bar.sync %0, %1;" :: "r"(id), "r"(128) : "memory")

// ---------------- helpers ----------------
template <int NP, bool RELUA>
__device__ __forceinline__ float4 loadPre(const float* __restrict__ A,
                                          const float* __restrict__ ab,
                                          size_t idx, int bcol, size_t SA) {
    float4 v = *(const float4*)(A + idx);
    if (NP >= 2) {
        float4 t = *(const float4*)(A + SA + idx);
        v.x += t.x; v.y += t.y; v.z += t.z; v.w += t.w;
    }
    if (NP >= 4) {
        float4 t = *(const float4*)(A + 2 * SA + idx);
        float4 u = *(const float4*)(A + 3 * SA + idx);
        v.x += t.x + u.x; v.y += t.y + u.y; v.z += t.z + u.z; v.w += t.w + u.w;
    }
    if (NP > 0) {
        float4 bb = *(const float4*)(ab + bcol);
        v.x += bb.x; v.y += bb.y; v.z += bb.z; v.w += bb.w;
        if (RELUA) {
            v.x = fmaxf(v.x, 0.f); v.y = fmaxf(v.y, 0.f);
            v.z = fmaxf(v.z, 0.f); v.w = fmaxf(v.w, 0.f);
        }
    }
    return v;
}

__device__ __forceinline__ float4 sum2b(const float* __restrict__ P, size_t idx, size_t S,
                                        const float* __restrict__ bias, int bi) {
    float4 a = *(const float4*)(P + idx);
    float4 b = *(const float4*)(P + S + idx);
    float4 c = *(const float4*)(bias + bi);
    a.x += b.x + c.x; a.y += b.y + c.y; a.z += b.z + c.z; a.w += b.w + c.w;
    return a;
}

// ---------------- GEMM worker (128-thread group): C(part z) = A[M,K] @ B[N,K]^T ----------------
// tile 64x64, BK=16, TM=8, TN=4; double-buffered; group-strided over tiles.
template <int NP, bool RELUA>
__device__ void gemm_phase(const float* __restrict__ A, const float* __restrict__ ab,
                           const float* __restrict__ B, float* __restrict__ C,
                           int N, int K, int ntn, int nsplit, int KS, size_t SA,
                           float* __restrict__ As, float* __restrict__ Bs,
                           int ltid, int barid, int grp) {
    const int ntiles = ntn * 16 * nsplit;
    const int tx = ltid & 15, ty = ltid >> 4;
    for (int tile = grp; tile < ntiles; tile += NGRP) {
        int z = tile / (ntn * 16);
        int rem = tile - z * (ntn * 16);
        int m = rem / ntn, n = rem - m * ntn;
        int bm0 = m * 64, bn0 = n * 64, k0s = z * KS;

        float acc[8][4];
        #pragma unroll
        for (int i = 0; i < 8; i++)
            #pragma unroll
            for (int j = 0; j < 4; j++) acc[i][j] = 0.f;

        // preload k-tile 0 into buffer 0
        #pragma unroll
        for (int it = 0; it < 2; it++) {
            int f = ltid + it * 128;
            int row = f >> 2, c4 = (f & 3) * 4;
            int kcol = k0s + c4;
            float4 v = loadPre<NP, RELUA>(A, ab, (size_t)(bm0 + row) * K + kcol, kcol, SA);
            As[(c4 + 0) * 64 + row] = v.x; As[(c4 + 1) * 64 + row] = v.y;
            As[(c4 + 2) * 64 + row] = v.z; As[(c4 + 3) * 64 + row] = v.w;
            float4 w = *(const float4*)&B[(size_t)(bn0 + row) * K + kcol];
            Bs[(c4 + 0) * 64 + row] = w.x; Bs[(c4 + 1) * 64 + row] = w.y;
            Bs[(c4 + 2) * 64 + row] = w.z; Bs[(c4 + 3) * 64 + row] = w.w;
        }
        GBAR(barid);

        int p = 0;
        const int nt = KS / 16;
        for (int t = 0; t < nt; t++) {
            float4 pa[2], pb[2];
            const bool has = (t + 1) < nt;
            if (has) {
                int kn = k0s + (t + 1) * 16;
                #pragma unroll
                for (int it = 0; it < 2; it++) {
                    int f = ltid + it * 128;
                    int row = f >> 2, c4 = (f & 3) * 4;
                    int kcol = kn + c4;
                    pa[it] = loadPre<NP, RELUA>(A, ab, (size_t)(bm0 + row) * K + kcol, kcol, SA);
                    pb[it] = *(const float4*)&B[(size_t)(bn0 + row) * K + kcol];
                }
            }
            const float* Ap = As + p * 1024;
            const float* Bp = Bs + p * 1024;
            #pragma unroll
            for (int kk = 0; kk < 16; kk++) {
                float a[8], b[4];
                #pragma unroll
                for (int i = 0; i < 8; i += 4)
                    *(float4*)&a[i] = *(const float4*)&Ap[kk * 64 + ty * 8 + i];
                *(float4*)&b[0] = *(const float4*)&Bp[kk * 64 + tx * 4];
                #pragma unroll
                for (int i = 0; i < 8; i++)
                    #pragma unroll
                    for (int j = 0; j < 4; j++) acc[i][j] = fmaf(a[i], b[j], acc[i][j]);
            }
            if (has) {
                float* Aq = As + (1 - p) * 1024;
                float* Bq = Bs + (1 - p) * 1024;
                #pragma unroll
                for (int it = 0; it < 2; it++) {
                    int f = ltid + it * 128;
                    int row = f >> 2, c4 = (f & 3) * 4;
                    Aq[(c4 + 0) * 64 + row] = pa[it].x; Aq[(c4 + 1) * 64 + row] = pa[it].y;
                    Aq[(c4 + 2) * 64 + row] = pa[it].z; Aq[(c4 + 3) * 64 + row] = pa[it].w;
                    Bq[(c4 + 0) * 64 + row] = pb[it].x; Bq[(c4 + 1) * 64 + row] = pb[it].y;
                    Bq[(c4 + 2) * 64 + row] = pb[it].z; Bq[(c4 + 3) * 64 + row] = pb[it].w;
                }
            }
            GBAR(barid);
            p ^= 1;
        }

        float* Cout = C + (size_t)z * BC * N;
        #pragma unroll
        for (int i = 0; i < 8; i++) {
            float4 o = make_float4(acc[i][0], acc[i][1], acc[i][2], acc[i][3]);
            *(float4*)&Cout[(size_t)(bm0 + ty * 8 + i) * N + bn0 + tx * 4] = o;
        }
    }
}

// ---------------- attention worker (128-thread group) ----------------
// unit = (b, h, qhalf): 16 query rows vs all 32 keys. qkv = sum of 2 partials + bias.
__device__ void attn_phase(AttnSmem* s, const float* __restrict__ bqkv,
                           int ltid, int barid, int grp) {
    constexpr size_t SQ = (size_t)BC * QKVn;
    for (int u = grp; u < Bn * Hn * 2; u += NGRP) {
        int b = u >> 3, h = (u >> 1) & 3, half = u & 1;
        int q0 = half * 16;
        #pragma unroll
        for (int it = 0; it < 4; it++) {
            int f = ltid + it * 128;
            int c = f >> 4, d4 = (f & 15) * 4;
            size_t base = (size_t)(b * Cn + c) * QKVn + h * HDn + d4;
            float4 kv = sum2b(g_qkvp, base + Rn, SQ, bqkv, Rn + h * HDn + d4);
            float4 vv = sum2b(g_qkvp, base + 2 * Rn, SQ, bqkv, 2 * Rn + h * HDn + d4);
            s->ks[c * 65 + d4 + 0] = kv.x; s->ks[c * 65 + d4 + 1] = kv.y;
            s->ks[c * 65 + d4 + 2] = kv.z; s->ks[c * 65 + d4 + 3] = kv.w;
            s->vs[c * 65 + d4 + 0] = vv.x; s->vs[c * 65 + d4 + 1] = vv.y;
            s->vs[c * 65 + d4 + 2] = vv.z; s->vs[c * 65 + d4 + 3] = vv.w;
        }
        #pragma unroll
        for (int it = 0; it < 2; it++) {
            int f = ltid + it * 128;
            int c = f >> 4, d4 = (f & 15) * 4;
            size_t base = (size_t)(b * Cn + q0 + c) * QKVn + h * HDn + d4;
            float4 qv = sum2b(g_qkvp, base, SQ, bqkv, h * HDn + d4);
            s->qs[c * 65 + d4 + 0] = qv.x; s->qs[c * 65 + d4 + 1] = qv.y;
            s->qs[c * 65 + d4 + 2] = qv.z; s->qs[c * 65 + d4 + 3] = qv.w;
        }
        GBAR(barid);
        #pragma unroll
        for (int r = 0; r < 4; r++) {
            int i = ltid + r * 128;
            int k = i & 31, q = i >> 5;
            float sum = 0.f;
            #pragma unroll
            for (int d = 0; d < HDn; d++) sum = fmaf(s->qs[q * 65 + d], s->ks[k * 65 + d], sum);
            s->sc[q * 33 + k] = sum * 0.125f;
        }
        GBAR(barid);
        if (ltid < 16) {
            float mx = -1e30f;
            #pragma unroll
            for (int k = 0; k < Cn; k++) mx = fmaxf(mx, s->sc[ltid * 33 + k]);
            float sum = 0.f;
            #pragma unroll
            for (int k = 0; k < Cn; k++) {
                float e = expf(s->sc[ltid * 33 + k] - mx);
                s->sc[ltid * 33 + k] = e; sum += e;
            }
            float inv = 1.f / sum;
            #pragma unroll
            for (int k = 0; k < Cn; k++) s->sc[ltid * 33 + k] *= inv;
        }
        GBAR(barid);
        #pragma unroll
        for (int r = 0; r < 8; r++) {
            int i = ltid + r * 128;
            int d = i & 63, q = i >> 6;
            float sum = 0.f;
            #pragma unroll
            for (int k = 0; k < Cn; k++) sum = fmaf(s->sc[q * 33 + k], s->vs[k * 65 + d], sum);
            g_att[(size_t)(b * Cn + q0 + q) * Rn + h * HDn + d] = sum;
        }
        GBAR(barid);   // smem reused by next unit
    }
}

// ---------------- LayerNorm worker: one warp per row ----------------
// NPA: residual partial count in a (1 = plain, 4 = sum4+ab). NPP: partial count in p.
template <int NPA, int NPP>
__device__ void ln_phase(const float* __restrict__ a, const float* __restrict__ ab,
                         const float* __restrict__ p, const float* __restrict__ pb,
                         const float* __restrict__ g, const float* __restrict__ be,
                         float* __restrict__ out) {
    int row = blockIdx.x * (NTHR / 32) + (threadIdx.x >> 5);
    if (row >= BC) return;
    const size_t S = (size_t)BC * Rn;
    int lane = threadIdx.x & 31;
    float v[8];
    #pragma unroll
    for (int j = 0; j < 8; j++) {
        int c = lane + 32 * j;
        size_t o = (size_t)row * Rn + c;
        float x = a[o];
        if (NPA == 4) x += a[S + o] + a[2 * S + o] + a[3 * S + o] + ab[c];
        float y = p[o];
        if (NPP >= 2) y += p[S + o];
        if (NPP >= 4) y += p[2 * S + o] + p[3 * S + o];
        v[j] = x + y + pb[c];
    }
    float sum = 0.f;
    #pragma unroll
    for (int j = 0; j < 8; j++) sum += v[j];
    #pragma unroll
    for (int off = 16; off > 0; off >>= 1) sum += __shfl_xor_sync(0xffffffffu, sum, off);
    float mean = sum * (1.f / Rn);
    float q = 0.f;
    #pragma unroll
    for (int j = 0; j < 8; j++) { float d = v[j] - mean; q = fmaf(d, d, q); }
    #pragma unroll
    for (int off = 16; off > 0; off >>= 1) q += __shfl_xor_sync(0xffffffffu, q, off);
    float rstd = rsqrtf(q * (1.f / Rn) + 1e-5f);
    #pragma unroll
    for (int j = 0; j < 8; j++) {
        int c = lane + 32 * j;
        out[(size_t)row * Rn + c] = (v[j] - mean) * rstd * g[c] + be[c];
    }
}

// ---------------- megakernel ----------------
__global__ __launch_bounds__(NTHR, 2)
void mega_kernel(const float* __restrict__ embs, const int* __restrict__ indices,
                 const int* __restrict__ mask, const float* __restrict__ host_cat,
                 const float* __restrict__ virus_cat, const float* __restrict__ extra_meta,
                 const float* __restrict__ fw,
                 const float* __restrict__ Wr, const float* __restrict__ br,
                 const float* __restrict__ Wqkv, const float* __restrict__ bqkv,
                 const float* __restrict__ Wo, const float* __restrict__ bo,
                 const float* __restrict__ ln1_g, const float* __restrict__ ln1_b,
                 const float* __restrict__ W1, const float* __restrict__ b1,
                 const float* __restrict__ W2, const float* __restrict__ b2,
                 const float* __restrict__ ln2_g, const float* __restrict__ ln2_b,
                 const float* __restrict__ Wc1, const float* __restrict__ bc1,
                 const float* __restrict__ Wc2, const float* __restrict__ bc2,
                 float* __restrict__ out) {
    __shared__ SmemU sm;
    const int tid = threadIdx.x;
    const int sub = tid >> 7;            // group in block: 0/1
    const int ltid = tid & 127;
    const int grp = blockIdx.x * 2 + sub;
    const int barid = 1 + sub;
    const int gid = blockIdx.x * NTHR + tid;

    // ---- P0: softmax weights per (b,c) segment ----
    if (gid < BC) {
        int bc = gid;
        float w[Sn]; int any = 0;
        #pragma unroll
        for (int s = 0; s < Sn; s++) {
            int m = mask[bc * Sn + s];
            any |= m;
            w[s] = m ? fw[indices[bc * Sn + s]] : -1e30f;
        }
        float mx = -1e30f;
        #pragma unroll
        for (int s = 0; s < Sn; s++) mx = fmaxf(mx, w[s]);
        float e[Sn], sum = 0.f;
        #pragma unroll
        for (int s = 0; s < Sn; s++) { e[s] = expf(w[s] - mx); sum += e[s]; }
        float inv = any ? (1.f / sum) : 0.f;
        #pragma unroll
        for (int s = 0; s < Sn; s++) g_aw[bc * Sn + s] = e[s] * inv;
    }
    gsync(0);

    // ---- P1: aggregation (HBM-bound) ----
    for (int u = gid; u < BC * (En / 4); u += NBLK * NTHR) {
        int bc = u / (En / 4);
        int col = u - bc * (En / 4);
        float aw[Sn];
        #pragma unroll
        for (int s = 0; s < Sn; s++) aw[s] = g_aw[bc * Sn + s];
        const float4* eb = (const float4*)embs + (size_t)bc * Sn * (En / 4) + col;
        float4 acc = make_float4(0.f, 0.f, 0.f, 0.f);
        #pragma unroll
        for (int s = 0; s < Sn; s++) {
            float4 v = eb[s * (En / 4)];
            acc.x = fmaf(aw[s], v.x, acc.x);
            acc.y = fmaf(aw[s], v.y, acc.y);
            acc.z = fmaf(aw[s], v.z, acc.z);
            acc.w = fmaf(aw[s], v.w, acc.w);
        }
        ((float4*)g_agg)[(size_t)bc * (En / 4) + col] = acc;
    }
    gsync(1);

    // ---- P2: x0 partials = agg @ Wr^T (split 4, KS=320) -> 256 tiles ----
    gemm_phase<0, false>(g_agg, nullptr, Wr, g_x0p, Rn, En, 4, 4, 320, 0,
                         &sm.g[sub].As[0][0][0], &sm.g[sub].Bs[0][0][0], ltid, barid, grp);
    gsync(2);

    // ---- P3: qkv partials = (sum4 x0p + br) @ Wqkv^T (split 2, KS=128) -> 384 tiles ----
    gemm_phase<4, false>(g_x0p, br, Wqkv, g_qkvp, QKVn, Rn, 12, 2, 128, (size_t)BC * Rn,
                         &sm.g[sub].As[0][0][0], &sm.g[sub].Bs[0][0][0], ltid, barid, grp);
    gsync(3);

    // ---- P4: attention (256 units) ----
    attn_phase(&sm.a[sub], bqkv, ltid, barid, grp);
    gsync(4);

    // ---- P5: oproj partials = att @ Wo^T (split 2, KS=128) -> 128 tiles ----
    gemm_phase<0, false>(g_att, nullptr, Wo, g_opp, Rn, Rn, 4, 2, 128, 0,
                         &sm.g[sub].As[0][0][0], &sm.g[sub].Bs[0][0][0], ltid, barid, grp);
    gsync(5);

    // ---- P6: x1 = LN(sum4 x0p + br + sum2 opp + bo) ----
    ln_phase<4, 2>(g_x0p, br, g_opp, bo, ln1_g, ln1_b, g_x1);
    gsync(6);

    // ---- P7: ff1 partials = x1 @ W1^T (split 2, KS=128) -> 256 tiles ----
    gemm_phase<0, false>(g_x1, nullptr, W1, g_ff1p, FFn, Rn, 8, 2, 128, 0,
                         &sm.g[sub].As[0][0][0], &sm.g[sub].Bs[0][0][0], ltid, barid, grp);
    gsync(7);

    // ---- P8: ff2 partials = relu(sum2 ff1p + b1) @ W2^T (split 2, KS=256) -> 128 tiles ----
    gemm_phase<2, true>(g_ff1p, b1, W2, g_fpp, Rn, FFn, 4, 2, 256, (size_t)BC * FFn,
                        &sm.g[sub].As[0][0][0], &sm.g[sub].Bs[0][0][0], ltid, barid, grp);
    gsync(8);

    // ---- P9: x2 = LN(x1 + sum2 fpp + b2) ----
    ln_phase<1, 2>(g_x1, nullptr, g_fpp, b2, ln2_g, ln2_b, g_x2);
    gsync(9);

    // ---- P10: head layer 1: h[b][j] = relu(feat . Wc1[j] + bc1[j]) ----
    {
        int lane = ltid & 31, w = ltid >> 5;
        for (int u = grp; u < Bn * 4; u += NGRP) {
            int b = u >> 2, j0 = (u & 3) * 32;
            const float* xb = g_x2 + (size_t)b * Cn * Rn;
            const float* hc = host_cat + b * 64;
            const float* vc = virus_cat + b * 32;
            const float* mt = extra_meta + b * 3;
            for (int jj = w; jj < 32; jj += 4) {
                int j = j0 + jj;
                const float* wr = Wc1 + (size_t)j * HEAD_IN;
                float s = 0.f;
                for (int i = lane; i < Cn * Rn; i += 32) s = fmaf(wr[i], xb[i], s);
                for (int i = lane; i < 64; i += 32) s = fmaf(wr[Cn * Rn + i], hc[i], s);
                s = fmaf(wr[Cn * Rn + 64 + lane], vc[lane], s);
                if (lane < 3) s = fmaf(wr[Cn * Rn + 96 + lane], mt[lane], s);
                #pragma unroll
                for (int off = 16; off > 0; off >>= 1) s += __shfl_down_sync(0xffffffffu, s, off);
                if (lane == 0) g_h[b * 128 + j] = fmaxf(s + bc1[j], 0.f);
            }
        }
    }
    gsync(10);

    // ---- P11: logits ----
    {
        int gwarp = blockIdx.x * (NTHR / 32) + (tid >> 5);
        int lane = tid & 31;
        if (gwarp < Bn) {
            float v = 0.f;
            #pragma unroll
            for (int r = 0; r < 4; r++) {
                int i = lane + 32 * r;
                v = fmaf(g_h[gwarp * 128 + i], Wc2[i], v);
            }
            #pragma unroll
            for (int off = 16; off > 0; off >>= 1) v += __shfl_xor_sync(0xffffffffu, v, off);
            if (lane == 0) out[gwarp] = v + bc2[0];
        }
    }
}

// ---------------- launch ----------------
extern "C" void kernel_launch(void* const* d_in, const int* in_sizes, int n_in,
                              void* d_out, int out_size) {
    const float* embs        = (const float*)d_in[0];
    const int*   indices     = (const int*)d_in[1];
    const int*   mask        = (const int*)d_in[2];     // bool -> int32
    const float* host_cat    = (const float*)d_in[3];
    const float* virus_cat   = (const float*)d_in[4];
    const float* extra_meta  = (const float*)d_in[5];
    const float* func_weights= (const float*)d_in[6];
    const float* Wr          = (const float*)d_in[7];
    const float* br          = (const float*)d_in[8];
    const float* Wqkv        = (const float*)d_in[9];
    const float* bqkv        = (const float*)d_in[10];
    const float* Wo          = (const float*)d_in[11];
    const float* bo          = (const float*)d_in[12];
    const float* ln1_g       = (const float*)d_in[13];
    const float* ln1_b       = (const float*)d_in[14];
    const float* W1          = (const float*)d_in[15];
    const float* b1          = (const float*)d_in[16];
    const float* W2          = (const float*)d_in[17];
    const float* b2          = (const float*)d_in[18];
    const float* ln2_g       = (const float*)d_in[19];
    const float* ln2_b       = (const float*)d_in[20];
    const float* Wc1         = (const float*)d_in[21];
    const float* bc1         = (const float*)d_in[22];
    const float* Wc2         = (const float*)d_in[23];
    const float* bc2         = (const float*)d_in[24];
    float* out = (float*)d_out;

    mega_kernel<<<NBLK, NTHR>>>(embs, indices, mask, host_cat, virus_cat, extra_meta,
                                func_weights, Wr, br, Wqkv, bqkv, Wo, bo,
                                ln1_g, ln1_b, W1, b1, W2, b2, ln2_g, ln2_b,
                                Wc1, bc1, Wc2, bc2, out);
}

// round 10
// speedup vs baseline: 1.2615x; 1.1151x over previous
#include <cuda_runtime.h>
#include <cuda_bf16.h>
#include <cstdint>
#include <math.h>

// ---------------- problem constants ----------------
static constexpr int Bn = 32, Cn = 32, Sn = 16, En = 1280, Rn = 256;
static constexpr int Hn = 4, HDn = 64, FFn = 512;
static constexpr int BC = Bn * Cn;               // 1024 tokens
static constexpr int HEAD_IN = Cn * Rn + 64 + 32 + 3;  // 8291
static constexpr int QKVn = 3 * Rn;              // 768

static constexpr int NBLK = 296;                 // persistent blocks (2 per SM)
static constexpr int NTHR = 256;                 // threads per block (2 groups of 128)
static constexpr int NGRP = 2 * NBLK;            // 592 worker groups

static constexpr int LDS_PAD = 40;               // bf16 elems per smem row (32 + 8 pad)

// ---------------- device scratch ----------------
__device__ float g_aw[BC * Sn];
__device__ __align__(16) float g_agg[BC * En];
__device__ __align__(16) float g_x0p[4 * BC * Rn];    // x0 partials (split 4)
__device__ __align__(16) float g_qkvp[2 * BC * QKVn]; // qkv partials (split 2)
__device__ __align__(16) float g_att[BC * Rn];
__device__ __align__(16) float g_opp[2 * BC * Rn];    // oproj partials (split 2)
__device__ __align__(16) float g_x1[BC * Rn];
__device__ __align__(16) float g_ff1p[2 * BC * FFn];  // ff1 partials (split 2)
__device__ __align__(16) float g_fpp[2 * BC * Rn];    // ff2 partials (split 2)
__device__ __align__(16) float g_x2[BC * Rn];
__device__ __align__(16) float g_h[Bn * 128];
__device__ unsigned g_bar[16];                        // monotonic barrier counters

// ---------------- shared memory (union across phases) ----------------
struct GemmSmem {
    unsigned short Ah[64 * LDS_PAD];
    unsigned short Al[64 * LDS_PAD];
    unsigned short Bh[64 * LDS_PAD];
    unsigned short Bl[64 * LDS_PAD];
};  // 20480 B per group
struct AttnSmem {
    float ks[32 * 65];
    float vs[32 * 65];
    float qs[16 * 65];
    float sc[16 * 33];
};
union SmemU {
    GemmSmem g[2];   // 40 KB
    AttnSmem a[2];   // ~44.8 KB
};

// ---------------- grid-wide barrier (monotonic, replay-safe) ----------------
__device__ __forceinline__ void gsync(int k) {
    __syncthreads();
    if (threadIdx.x == 0) {
        __threadfence();
        unsigned old = atomicAdd(&g_bar[k], 1u);
        unsigned target = (old / NBLK + 1u) * NBLK;
        volatile unsigned* p = &g_bar[k];
        while (*p < target) { }
        __threadfence();
    }
    __syncthreads();
}

// group barrier: 128 threads, named barrier id 1 or 2
#define GBAR(id) asm volatile("bar.sync %0, %1;" :: "r"(id), "r"(128) : "memory")

// ---------------- smem address helper (proven asm pattern) ----------------
__device__ __forceinline__ unsigned smem_u32(const void* p) {
    unsigned addr;
    asm("{ .reg .u64 t; cvta.to.shared.u64 t, %1; cvt.u32.u64 %0, t; }"
        : "=r"(addr) : "l"(p));
    return addr;
}

// ---------------- mma / ldmatrix helpers ----------------
__device__ __forceinline__ void ldsm4(unsigned& r0, unsigned& r1, unsigned& r2, unsigned& r3,
                                      unsigned addr) {
    asm volatile("ldmatrix.sync.aligned.m8n8.x4.shared.b16 {%0,%1,%2,%3}, [%4];"
                 : "=r"(r0), "=r"(r1), "=r"(r2), "=r"(r3) : "r"(addr));
}

__device__ __forceinline__ void mma_bf16(float& c0, float& c1, float& c2, float& c3,
                                         unsigned a0, unsigned a1, unsigned a2, unsigned a3,
                                         unsigned b0, unsigned b1) {
    asm volatile(
        "mma.sync.aligned.m16n8k16.row.col.f32.bf16.bf16.f32 "
        "{%0,%1,%2,%3}, {%4,%5,%6,%7}, {%8,%9}, {%0,%1,%2,%3};"
        : "+f"(c0), "+f"(c1), "+f"(c2), "+f"(c3)
        : "r"(a0), "r"(a1), "r"(a2), "r"(a3), "r"(b0), "r"(b1));
}

__device__ __forceinline__ unsigned bf16bits(float x) {
    return (unsigned)__bfloat16_as_ushort(__float2bfloat16_rn(x));
}

// split one float4 into hi/lo packed bf16 pairs (hi = rn(x), lo = rn(x - hi))
__device__ __forceinline__ void split4(float4 v, uint2& hi, uint2& lo) {
    unsigned h0 = bf16bits(v.x), h1 = bf16bits(v.y), h2 = bf16bits(v.z), h3 = bf16bits(v.w);
    float f0 = __bfloat162float(__ushort_as_bfloat16((unsigned short)h0));
    float f1 = __bfloat162float(__ushort_as_bfloat16((unsigned short)h1));
    float f2 = __bfloat162float(__ushort_as_bfloat16((unsigned short)h2));
    float f3 = __bfloat162float(__ushort_as_bfloat16((unsigned short)h3));
    unsigned l0 = bf16bits(v.x - f0), l1 = bf16bits(v.y - f1);
    unsigned l2 = bf16bits(v.z - f2), l3 = bf16bits(v.w - f3);
    hi.x = h0 | (h1 << 16);
    hi.y = h2 | (h3 << 16);
    lo.x = l0 | (l1 << 16);
    lo.y = l2 | (l3 << 16);
}

// ---------------- A-operand preprocessing ----------------
// NP: 0 = plain A; 2/4 = A is NP split-K partials summed + bias; RELUA applies relu after.
template <int NP, bool RELUA>
__device__ __forceinline__ float4 loadPre(const float* __restrict__ A,
                                          const float* __restrict__ ab,
                                          size_t idx, int bcol, size_t SA) {
    float4 v = *(const float4*)(A + idx);
    if (NP >= 2) {
        float4 t = *(const float4*)(A + SA + idx);
        v.x += t.x; v.y += t.y; v.z += t.z; v.w += t.w;
    }
    if (NP >= 4) {
        float4 t = *(const float4*)(A + 2 * SA + idx);
        float4 u = *(const float4*)(A + 3 * SA + idx);
        v.x += t.x + u.x; v.y += t.y + u.y; v.z += t.z + u.z; v.w += t.w + u.w;
    }
    if (NP > 0) {
        float4 bb = *(const float4*)(ab + bcol);
        v.x += bb.x; v.y += bb.y; v.z += bb.z; v.w += bb.w;
        if (RELUA) {
            v.x = fmaxf(v.x, 0.f); v.y = fmaxf(v.y, 0.f);
            v.z = fmaxf(v.z, 0.f); v.w = fmaxf(v.w, 0.f);
        }
    }
    return v;
}

__device__ __forceinline__ float4 sum2b(const float* __restrict__ P, size_t idx, size_t S,
                                        const float* __restrict__ bias, int bi) {
    float4 a = *(const float4*)(P + idx);
    float4 b = *(const float4*)(P + S + idx);
    float4 c = *(const float4*)(bias + bi);
    a.x += b.x + c.x; a.y += b.y + c.y; a.z += b.z + c.z; a.w += b.w + c.w;
    return a;
}

// ---------------- tensor-core GEMM worker (128-thread group) ----------------
// C(part z)[M,N] = A[M,K] @ B[N,K]^T via split-bf16 HMMA. Tile 64x64, k-chunk 32.
// 4 warps in 2x2 grid, warp tile 32x32.
template <int NP, bool RELUA>
__device__ void gemm_phase(const float* __restrict__ A, const float* __restrict__ ab,
                           const float* __restrict__ B, float* __restrict__ C,
                           int N, int K, int ntn, int nsplit, int KS, size_t SA,
                           GemmSmem* sg, int ltid, int barid, int grp) {
    const int ntpz = ntn * 16;
    const int ntiles = ntpz * nsplit;
    const int warp = ltid >> 5;
    const int lane = ltid & 31;
    const int warp_m = (warp >> 1) * 32;
    const int warp_n = (warp & 1) * 32;
    const int lrow = lane & 15;
    const int lblk = lane >> 4;
    const int quad = lane >> 2;
    const int pr = lane & 3;

    const unsigned aAh = smem_u32(sg->Ah);
    const unsigned aAl = smem_u32(sg->Al);
    const unsigned aBh = smem_u32(sg->Bh);
    const unsigned aBl = smem_u32(sg->Bl);

    for (int tile = grp; tile < ntiles; tile += NGRP) {
        int z = tile / ntpz;
        int rem = tile - z * ntpz;
        int m = rem / ntn;
        int n = rem - m * ntn;
        int bm0 = m * 64;
        int bn0 = n * 64;
        int k0s = z * KS;

        float acc[2][4][4];
        #pragma unroll
        for (int i = 0; i < 2; i++) {
            #pragma unroll
            for (int j = 0; j < 4; j++) {
                #pragma unroll
                for (int r = 0; r < 4; r++) { acc[i][j][r] = 0.f; }
            }
        }

        const int nch = KS / 32;
        float4 pa[4], pb[4];
        // prefetch chunk 0 into registers
        #pragma unroll
        for (int it = 0; it < 4; it++) {
            int f = ltid + it * 128;
            int row = f >> 3;
            int c4 = (f & 7) * 4;
            int kc = k0s + c4;
            pa[it] = loadPre<NP, RELUA>(A, ab, (size_t)(bm0 + row) * K + kc, kc, SA);
            pb[it] = *(const float4*)&B[(size_t)(bn0 + row) * K + kc];
        }

        for (int ch = 0; ch < nch; ch++) {
            // stage: split-convert registers -> smem
            #pragma unroll
            for (int it = 0; it < 4; it++) {
                int f = ltid + it * 128;
                int row = f >> 3;
                int c4 = (f & 7) * 4;
                int off = row * LDS_PAD + c4;
                uint2 hi, lo;
                split4(pa[it], hi, lo);
                *(uint2*)(sg->Ah + off) = hi;
                *(uint2*)(sg->Al + off) = lo;
                split4(pb[it], hi, lo);
                *(uint2*)(sg->Bh + off) = hi;
                *(uint2*)(sg->Bl + off) = lo;
            }
            GBAR(barid);

            // prefetch next chunk while MMAs run
            if (ch + 1 < nch) {
                int kb = k0s + (ch + 1) * 32;
                #pragma unroll
                for (int it = 0; it < 4; it++) {
                    int f = ltid + it * 128;
                    int row = f >> 3;
                    int c4 = (f & 7) * 4;
                    int kc = kb + c4;
                    pa[it] = loadPre<NP, RELUA>(A, ab, (size_t)(bm0 + row) * K + kc, kc, SA);
                    pb[it] = *(const float4*)&B[(size_t)(bn0 + row) * K + kc];
                }
            }

            // compute: two k16 steps
            #pragma unroll
            for (int ks16 = 0; ks16 < 2; ks16++) {
                int ko = ks16 * 16;
                unsigned ah[2][4], al[2][4], bh[2][4], bl[2][4];
                #pragma unroll
                for (int i = 0; i < 2; i++) {
                    unsigned o = (unsigned)(((warp_m + i * 16 + lrow) * LDS_PAD + ko + lblk * 8) * 2);
                    ldsm4(ah[i][0], ah[i][1], ah[i][2], ah[i][3], aAh + o);
                    ldsm4(al[i][0], al[i][1], al[i][2], al[i][3], aAl + o);
                }
                #pragma unroll
                for (int j = 0; j < 2; j++) {
                    unsigned o = (unsigned)(((warp_n + j * 16 + lrow) * LDS_PAD + ko + lblk * 8) * 2);
                    ldsm4(bh[j][0], bh[j][1], bh[j][2], bh[j][3], aBh + o);
                    ldsm4(bl[j][0], bl[j][1], bl[j][2], bl[j][3], aBl + o);
                }
                #pragma unroll
                for (int mi = 0; mi < 2; mi++) {
                    #pragma unroll
                    for (int nj = 0; nj < 2; nj++) {
                        #pragma unroll
                        for (int h = 0; h < 2; h++) {
                            int ni = nj * 2 + h;
                            mma_bf16(acc[mi][ni][0], acc[mi][ni][1], acc[mi][ni][2], acc[mi][ni][3],
                                     ah[mi][0], ah[mi][1], ah[mi][2], ah[mi][3],
                                     bh[nj][h], bh[nj][2 + h]);
                            mma_bf16(acc[mi][ni][0], acc[mi][ni][1], acc[mi][ni][2], acc[mi][ni][3],
                                     ah[mi][0], ah[mi][1], ah[mi][2], ah[mi][3],
                                     bl[nj][h], bl[nj][2 + h]);
                            mma_bf16(acc[mi][ni][0], acc[mi][ni][1], acc[mi][ni][2], acc[mi][ni][3],
                                     al[mi][0], al[mi][1], al[mi][2], al[mi][3],
                                     bh[nj][h], bh[nj][2 + h]);
                        }
                    }
                }
            }
            GBAR(barid);
        }

        // epilogue: write fp32 partial tile
        float* Cout = C + (size_t)z * BC * N;
        #pragma unroll
        for (int mi = 0; mi < 2; mi++) {
            #pragma unroll
            for (int ni = 0; ni < 4; ni++) {
                int mrow = bm0 + warp_m + mi * 16 + quad;
                int ncol = bn0 + warp_n + ni * 8 + pr * 2;
                float2 r0;
                r0.x = acc[mi][ni][0];
                r0.y = acc[mi][ni][1];
                float2 r1;
                r1.x = acc[mi][ni][2];
                r1.y = acc[mi][ni][3];
                *(float2*)&Cout[(size_t)mrow * N + ncol] = r0;
                *(float2*)&Cout[(size_t)(mrow + 8) * N + ncol] = r1;
            }
        }
    }
}

// ---------------- attention worker (128-thread group) ----------------
__device__ void attn_phase(AttnSmem* s, const float* __restrict__ bqkv,
                           int ltid, int barid, int grp) {
    constexpr size_t SQ = (size_t)BC * QKVn;
    for (int u = grp; u < Bn * Hn * 2; u += NGRP) {
        int b = u >> 3;
        int h = (u >> 1) & 3;
        int half = u & 1;
        int q0 = half * 16;
        #pragma unroll
        for (int it = 0; it < 4; it++) {
            int f = ltid + it * 128;
            int c = f >> 4;
            int d4 = (f & 15) * 4;
            size_t base = (size_t)(b * Cn + c) * QKVn + h * HDn + d4;
            float4 kv = sum2b(g_qkvp, base + Rn, SQ, bqkv, Rn + h * HDn + d4);
            float4 vv = sum2b(g_qkvp, base + 2 * Rn, SQ, bqkv, 2 * Rn + h * HDn + d4);
            s->ks[c * 65 + d4 + 0] = kv.x; s->ks[c * 65 + d4 + 1] = kv.y;
            s->ks[c * 65 + d4 + 2] = kv.z; s->ks[c * 65 + d4 + 3] = kv.w;
            s->vs[c * 65 + d4 + 0] = vv.x; s->vs[c * 65 + d4 + 1] = vv.y;
            s->vs[c * 65 + d4 + 2] = vv.z; s->vs[c * 65 + d4 + 3] = vv.w;
        }
        #pragma unroll
        for (int it = 0; it < 2; it++) {
            int f = ltid + it * 128;
            int c = f >> 4;
            int d4 = (f & 15) * 4;
            size_t base = (size_t)(b * Cn + q0 + c) * QKVn + h * HDn + d4;
            float4 qv = sum2b(g_qkvp, base, SQ, bqkv, h * HDn + d4);
            s->qs[c * 65 + d4 + 0] = qv.x; s->qs[c * 65 + d4 + 1] = qv.y;
            s->qs[c * 65 + d4 + 2] = qv.z; s->qs[c * 65 + d4 + 3] = qv.w;
        }
        GBAR(barid);
        #pragma unroll
        for (int r = 0; r < 4; r++) {
            int i = ltid + r * 128;
            int k = i & 31;
            int q = i >> 5;
            float sum = 0.f;
            #pragma unroll
            for (int d = 0; d < HDn; d++) { sum = fmaf(s->qs[q * 65 + d], s->ks[k * 65 + d], sum); }
            s->sc[q * 33 + k] = sum * 0.125f;
        }
        GBAR(barid);
        if (ltid < 16) {
            float mx = -1e30f;
            #pragma unroll
            for (int k = 0; k < Cn; k++) { mx = fmaxf(mx, s->sc[ltid * 33 + k]); }
            float sum = 0.f;
            #pragma unroll
            for (int k = 0; k < Cn; k++) {
                float e = expf(s->sc[ltid * 33 + k] - mx);
                s->sc[ltid * 33 + k] = e;
                sum += e;
            }
            float inv = 1.f / sum;
            #pragma unroll
            for (int k = 0; k < Cn; k++) { s->sc[ltid * 33 + k] *= inv; }
        }
        GBAR(barid);
        #pragma unroll
        for (int r = 0; r < 8; r++) {
            int i = ltid + r * 128;
            int d = i & 63;
            int q = i >> 6;
            float sum = 0.f;
            #pragma unroll
            for (int k = 0; k < Cn; k++) { sum = fmaf(s->sc[q * 33 + k], s->vs[k * 65 + d], sum); }
            g_att[(size_t)(b * Cn + q0 + q) * Rn + h * HDn + d] = sum;
        }
        GBAR(barid);   // smem reused by next unit
    }
}

// ---------------- LayerNorm worker: one warp per row ----------------
template <int NPA, int NPP>
__device__ void ln_phase(const float* __restrict__ a, const float* __restrict__ ab,
                         const float* __restrict__ p, const float* __restrict__ pb,
                         const float* __restrict__ g, const float* __restrict__ be,
                         float* __restrict__ out) {
    int row = blockIdx.x * (NTHR / 32) + (threadIdx.x >> 5);
    if (row >= BC) { return; }
    const size_t S = (size_t)BC * Rn;
    int lane = threadIdx.x & 31;
    float v[8];
    #pragma unroll
    for (int j = 0; j < 8; j++) {
        int c = lane + 32 * j;
        size_t o = (size_t)row * Rn + c;
        float x = a[o];
        if (NPA == 4) { x += a[S + o] + a[2 * S + o] + a[3 * S + o] + ab[c]; }
        float y = p[o];
        if (NPP >= 2) { y += p[S + o]; }
        if (NPP >= 4) { y += p[2 * S + o] + p[3 * S + o]; }
        v[j] = x + y + pb[c];
    }
    float sum = 0.f;
    #pragma unroll
    for (int j = 0; j < 8; j++) { sum += v[j]; }
    #pragma unroll
    for (int off = 16; off > 0; off >>= 1) { sum += __shfl_xor_sync(0xffffffffu, sum, off); }
    float mean = sum * (1.f / Rn);
    float q = 0.f;
    #pragma unroll
    for (int j = 0; j < 8; j++) { float d = v[j] - mean; q = fmaf(d, d, q); }
    #pragma unroll
    for (int off = 16; off > 0; off >>= 1) { q += __shfl_xor_sync(0xffffffffu, q, off); }
    float rstd = rsqrtf(q * (1.f / Rn) + 1e-5f);
    #pragma unroll
    for (int j = 0; j < 8; j++) {
        int c = lane + 32 * j;
        out[(size_t)row * Rn + c] = (v[j] - mean) * rstd * g[c] + be[c];
    }
}

// ---------------- megakernel ----------------
__global__ __launch_bounds__(NTHR, 2)
void mega_kernel(const float* __restrict__ embs, const int* __restrict__ indices,
                 const int* __restrict__ mask, const float* __restrict__ host_cat,
                 const float* __restrict__ virus_cat, const float* __restrict__ extra_meta,
                 const float* __restrict__ fw,
                 const float* __restrict__ Wr, const float* __restrict__ br,
                 const float* __restrict__ Wqkv, const float* __restrict__ bqkv,
                 const float* __restrict__ Wo, const float* __restrict__ bo,
                 const float* __restrict__ ln1_g, const float* __restrict__ ln1_b,
                 const float* __restrict__ W1, const float* __restrict__ b1,
                 const float* __restrict__ W2, const float* __restrict__ b2,
                 const float* __restrict__ ln2_g, const float* __restrict__ ln2_b,
                 const float* __restrict__ Wc1, const float* __restrict__ bc1,
                 const float* __restrict__ Wc2, const float* __restrict__ bc2,
                 float* __restrict__ out) {
    __shared__ SmemU sm;
    const int tid = threadIdx.x;
    const int sub = tid >> 7;            // group in block: 0/1
    const int ltid = tid & 127;
    const int grp = blockIdx.x * 2 + sub;
    const int barid = 1 + sub;
    const int gid = blockIdx.x * NTHR + tid;

    // ---- P0: softmax weights per (b,c) segment ----
    if (gid < BC) {
        int bc = gid;
        float w[Sn];
        int any = 0;
        #pragma unroll
        for (int s = 0; s < Sn; s++) {
            int m = mask[bc * Sn + s];
            any |= m;
            w[s] = m ? fw[indices[bc * Sn + s]] : -1e30f;
        }
        float mx = -1e30f;
        #pragma unroll
        for (int s = 0; s < Sn; s++) { mx = fmaxf(mx, w[s]); }
        float e[Sn];
        float sum = 0.f;
        #pragma unroll
        for (int s = 0; s < Sn; s++) { e[s] = expf(w[s] - mx); sum += e[s]; }
        float inv = any ? (1.f / sum) : 0.f;
        #pragma unroll
        for (int s = 0; s < Sn; s++) { g_aw[bc * Sn + s] = e[s] * inv; }
    }
    gsync(0);

    // ---- P1: aggregation (HBM-bound) ----
    for (int u = gid; u < BC * (En / 4); u += NBLK * NTHR) {
        int bc = u / (En / 4);
        int col = u - bc * (En / 4);
        float aw[Sn];
        #pragma unroll
        for (int s = 0; s < Sn; s++) { aw[s] = g_aw[bc * Sn + s]; }
        const float4* eb = (const float4*)embs + (size_t)bc * Sn * (En / 4) + col;
        float4 acc;
        acc.x = 0.f; acc.y = 0.f; acc.z = 0.f; acc.w = 0.f;
        #pragma unroll
        for (int s = 0; s < Sn; s++) {
            float4 v = eb[s * (En / 4)];
            acc.x = fmaf(aw[s], v.x, acc.x);
            acc.y = fmaf(aw[s], v.y, acc.y);
            acc.z = fmaf(aw[s], v.z, acc.z);
            acc.w = fmaf(aw[s], v.w, acc.w);
        }
        ((float4*)g_agg)[(size_t)bc * (En / 4) + col] = acc;
    }
    gsync(1);

    // ---- P2: x0 partials = agg @ Wr^T (split 4, KS=320) -> 256 tiles ----
    gemm_phase<0, false>(g_agg, (const float*)0, Wr, g_x0p, Rn, En, 4, 4, 320, (size_t)0,
                         &sm.g[sub], ltid, barid, grp);
    gsync(2);

    // ---- P3: qkv partials = (sum4 x0p + br) @ Wqkv^T (split 2, KS=128) -> 384 tiles ----
    gemm_phase<4, false>(g_x0p, br, Wqkv, g_qkvp, QKVn, Rn, 12, 2, 128, (size_t)BC * Rn,
                         &sm.g[sub], ltid, barid, grp);
    gsync(3);

    // ---- P4: attention (256 units) ----
    attn_phase(&sm.a[sub], bqkv, ltid, barid, grp);
    gsync(4);

    // ---- P5: oproj partials = att @ Wo^T (split 2, KS=128) -> 128 tiles ----
    gemm_phase<0, false>(g_att, (const float*)0, Wo, g_opp, Rn, Rn, 4, 2, 128, (size_t)0,
                         &sm.g[sub], ltid, barid, grp);
    gsync(5);

    // ---- P6: x1 = LN(sum4 x0p + br + sum2 opp + bo) ----
    ln_phase<4, 2>(g_x0p, br, g_opp, bo, ln1_g, ln1_b, g_x1);
    gsync(6);

    // ---- P7: ff1 partials = x1 @ W1^T (split 2, KS=128) -> 256 tiles ----
    gemm_phase<0, false>(g_x1, (const float*)0, W1, g_ff1p, FFn, Rn, 8, 2, 128, (size_t)0,
                         &sm.g[sub], ltid, barid, grp);
    gsync(7);

    // ---- P8: ff2 partials = relu(sum2 ff1p + b1) @ W2^T (split 2, KS=256) -> 128 tiles ----
    gemm_phase<2, true>(g_ff1p, b1, W2, g_fpp, Rn, FFn, 4, 2, 256, (size_t)BC * FFn,
                        &sm.g[sub], ltid, barid, grp);
    gsync(8);

    // ---- P9: x2 = LN(x1 + sum2 fpp + b2) ----
    ln_phase<1, 2>(g_x1, (const float*)0, g_fpp, b2, ln2_g, ln2_b, g_x2);
    gsync(9);

    // ---- P10: head layer 1: h[b][j] = relu(feat . Wc1[j] + bc1[j]) ----
    {
        int lane = ltid & 31;
        int w = ltid >> 5;
        for (int u = grp; u < Bn * 4; u += NGRP) {
            int b = u >> 2;
            int j0 = (u & 3) * 32;
            const float* xb = g_x2 + (size_t)b * Cn * Rn;
            const float* hc = host_cat + b * 64;
            const float* vc = virus_cat + b * 32;
            const float* mt = extra_meta + b * 3;
            for (int jj = w; jj < 32; jj += 4) {
                int j = j0 + jj;
                const float* wr = Wc1 + (size_t)j * HEAD_IN;
                float s = 0.f;
                for (int i = lane; i < Cn * Rn; i += 32) { s = fmaf(wr[i], xb[i], s); }
                for (int i = lane; i < 64; i += 32) { s = fmaf(wr[Cn * Rn + i], hc[i], s); }
                s = fmaf(wr[Cn * Rn + 64 + lane], vc[lane], s);
                if (lane < 3) { s = fmaf(wr[Cn * Rn + 96 + lane], mt[lane], s); }
                #pragma unroll
                for (int off = 16; off > 0; off >>= 1) { s += __shfl_down_sync(0xffffffffu, s, off); }
                if (lane == 0) { g_h[b * 128 + j] = fmaxf(s + bc1[j], 0.f); }
            }
        }
    }
    gsync(10);

    // ---- P11: logits ----
    {
        int gwarp = blockIdx.x * (NTHR / 32) + (tid >> 5);
        int lane = tid & 31;
        if (gwarp < Bn) {
            float v = 0.f;
            #pragma unroll
            for (int r = 0; r < 4; r++) {
                int i = lane + 32 * r;
                v = fmaf(g_h[gwarp * 128 + i], Wc2[i], v);
            }
            #pragma unroll
            for (int off = 16; off > 0; off >>= 1) { v += __shfl_xor_sync(0xffffffffu, v, off); }
            if (lane == 0) { out[gwarp] = v + bc2[0]; }
        }
    }
}

// ---------------- launch ----------------
extern "C" void kernel_launch(void* const* d_in, const int* in_sizes, int n_in,
                              void* d_out, int out_size) {
    const float* embs        = (const float*)d_in[0];
    const int*   indices     = (const int*)d_in[1];
    const int*   mask        = (const int*)d_in[2];     // bool -> int32
    const float* host_cat    = (const float*)d_in[3];
    const float* virus_cat   = (const float*)d_in[4];
    const float* extra_meta  = (const float*)d_in[5];
    const float* func_weights= (const float*)d_in[6];
    const float* Wr          = (const float*)d_in[7];
    const float* br          = (const float*)d_in[8];
    const float* Wqkv        = (const float*)d_in[9];
    const float* bqkv        = (const float*)d_in[10];
    const float* Wo          = (const float*)d_in[11];
    const float* bo          = (const float*)d_in[12];
    const float* ln1_g       = (const float*)d_in[13];
    const float* ln1_b       = (const float*)d_in[14];
    const float* W1          = (const float*)d_in[15];
    const float* b1          = (const float*)d_in[16];
    const float* W2          = (const float*)d_in[17];
    const float* b2          = (const float*)d_in[18];
    const float* ln2_g       = (const float*)d_in[19];
    const float* ln2_b       = (const float*)d_in[20];
    const float* Wc1         = (const float*)d_in[21];
    const float* bc1         = (const float*)d_in[22];
    const float* Wc2         = (const float*)d_in[23];
    const float* bc2         = (const float*)d_in[24];
    float* out = (float*)d_out;

    mega_kernel<<<NBLK, NTHR>>>(embs, indices, mask, host_cat, virus_cat, extra_meta,
                                func_weights, Wr, br, Wqkv, bqkv, Wo, bo,
                                ln1_g, ln1_b, W1, b1, W2, b2, ln2_g, ln2_b,
                                Wc1, bc1, Wc2, bc2, out);
}

// round 11
// speedup vs baseline: 2.3325x; 1.8491x over previous
#include <cuda_runtime.h>
#include <cuda_bf16.h>
#include <cstdint>
#include <math.h>

// ---------------- problem constants ----------------
static constexpr int Bn = 32, Cn = 32, Sn = 16, En = 1280, Rn = 256;
static constexpr int Hn = 4, HDn = 64, FFn = 512;
static constexpr int BC = Bn * Cn;               // 1024 tokens
static constexpr int HEAD_IN = Cn * Rn + 64 + 32 + 3;  // 8291
static constexpr int QKVn = 3 * Rn;              // 768
static constexpr int HK = 8192;                  // head GEMM K (aligned part)

static constexpr int NBLK = 592;                 // persistent blocks (4 per SM)
static constexpr int NTHR = 128;                 // one worker group per block
static constexpr int NGRP = NBLK;

static constexpr int LDS_PAD = 40;               // bf16 elems per smem row (32 + 8 pad)
static constexpr int BUFB = 64 * LDS_PAD * 2;    // bytes per smem buffer (5120)

// ---------------- device scratch ----------------
__device__ float g_aw[BC * Sn];
__device__ __align__(16) float g_agg[BC * En];
__device__ __align__(16) float g_x0p[8 * BC * Rn];    // x0 partials (split 8)
__device__ __align__(16) float g_qkvp[2 * BC * QKVn]; // qkv partials (split 2)
__device__ __align__(16) float g_att[BC * Rn];
__device__ __align__(16) float g_opp[4 * BC * Rn];    // oproj partials (split 4)
__device__ __align__(16) float g_x1[BC * Rn];
__device__ __align__(16) float g_ff1p[4 * BC * FFn];  // ff1 partials (split 4)
__device__ __align__(16) float g_fpp[4 * BC * Rn];    // ff2 partials (split 4)
__device__ __align__(16) float g_feat[64 * HK];       // rows 0-31 = x2 flat; 32-63 stay zero
__device__ __align__(16) float g_hp[64 * 64 * 128];   // head partials (split 64)
__device__ __align__(16) float g_h[Bn * 128];
__device__ unsigned g_bar[16];                        // monotonic barrier counters

// ---------------- shared memory (union across phases) ----------------
struct GemmSmem {
    unsigned short Ah[2][64 * LDS_PAD];
    unsigned short Al[2][64 * LDS_PAD];
    unsigned short Bh[2][64 * LDS_PAD];
    unsigned short Bl[2][64 * LDS_PAD];
};  // 40960 B
struct AttnSmem {
    float ks[32 * 65];
    float vs[32 * 65];
    float qs[16 * 65];
    float sc[16 * 33];
};  // ~22 KB
union SmemU {
    GemmSmem g;
    AttnSmem a;
};

// ---------------- grid-wide barrier (monotonic, replay-safe) ----------------
__device__ __forceinline__ void gsync(int k) {
    __syncthreads();
    if (threadIdx.x == 0) {
        __threadfence();
        unsigned old = atomicAdd(&g_bar[k], 1u);
        unsigned target = (old / NBLK + 1u) * NBLK;
        volatile unsigned* p = &g_bar[k];
        while (*p < target) { }
        __threadfence();
    }
    __syncthreads();
}

// ---------------- smem address helper ----------------
__device__ __forceinline__ unsigned smem_u32(const void* p) {
    unsigned addr;
    asm("{ .reg .u64 t; cvta.to.shared.u64 t, %1; cvt.u32.u64 %0, t; }"
        : "=r"(addr) : "l"(p));
    return addr;
}

// ---------------- mma / ldmatrix helpers ----------------
__device__ __forceinline__ void ldsm4(unsigned& r0, unsigned& r1, unsigned& r2, unsigned& r3,
                                      unsigned addr) {
    asm volatile("ldmatrix.sync.aligned.m8n8.x4.shared.b16 {%0,%1,%2,%3}, [%4];"
                 : "=r"(r0), "=r"(r1), "=r"(r2), "=r"(r3) : "r"(addr));
}

__device__ __forceinline__ void mma_bf16(float& c0, float& c1, float& c2, float& c3,
                                         unsigned a0, unsigned a1, unsigned a2, unsigned a3,
                                         unsigned b0, unsigned b1) {
    asm volatile(
        "mma.sync.aligned.m16n8k16.row.col.f32.bf16.bf16.f32 "
        "{%0,%1,%2,%3}, {%4,%5,%6,%7}, {%8,%9}, {%0,%1,%2,%3};"
        : "+f"(c0), "+f"(c1), "+f"(c2), "+f"(c3)
        : "r"(a0), "r"(a1), "r"(a2), "r"(a3), "r"(b0), "r"(b1));
}

__device__ __forceinline__ unsigned bf16bits(float x) {
    return (unsigned)__bfloat16_as_ushort(__float2bfloat16_rn(x));
}

// split one float4 into hi/lo packed bf16 pairs (hi = rn(x), lo = rn(x - hi))
__device__ __forceinline__ void split4(float4 v, uint2& hi, uint2& lo) {
    unsigned h0 = bf16bits(v.x), h1 = bf16bits(v.y), h2 = bf16bits(v.z), h3 = bf16bits(v.w);
    float f0 = __bfloat162float(__ushort_as_bfloat16((unsigned short)h0));
    float f1 = __bfloat162float(__ushort_as_bfloat16((unsigned short)h1));
    float f2 = __bfloat162float(__ushort_as_bfloat16((unsigned short)h2));
    float f3 = __bfloat162float(__ushort_as_bfloat16((unsigned short)h3));
    unsigned l0 = bf16bits(v.x - f0), l1 = bf16bits(v.y - f1);
    unsigned l2 = bf16bits(v.z - f2), l3 = bf16bits(v.w - f3);
    hi.x = h0 | (h1 << 16);
    hi.y = h2 | (h3 << 16);
    lo.x = l0 | (l1 << 16);
    lo.y = l2 | (l3 << 16);
}

// ---------------- A-operand preprocessing ----------------
// NP: 0 = plain; 2/4/8 = sum NP split-K partials + bias; RELUA applies relu after.
template <int NP, bool RELUA>
__device__ __forceinline__ float4 loadPre(const float* __restrict__ A,
                                          const float* __restrict__ ab,
                                          size_t idx, int bcol, size_t SA) {
    float4 v = *(const float4*)(A + idx);
    if (NP >= 2) {
        float4 t = *(const float4*)(A + SA + idx);
        v.x += t.x; v.y += t.y; v.z += t.z; v.w += t.w;
    }
    if (NP >= 4) {
        float4 t = *(const float4*)(A + 2 * SA + idx);
        float4 u = *(const float4*)(A + 3 * SA + idx);
        v.x += t.x + u.x; v.y += t.y + u.y; v.z += t.z + u.z; v.w += t.w + u.w;
    }
    if (NP >= 8) {
        #pragma unroll
        for (int z = 4; z < 8; z++) {
            float4 t = *(const float4*)(A + (size_t)z * SA + idx);
            v.x += t.x; v.y += t.y; v.z += t.z; v.w += t.w;
        }
    }
    if (NP > 0) {
        float4 bb = *(const float4*)(ab + bcol);
        v.x += bb.x; v.y += bb.y; v.z += bb.z; v.w += bb.w;
        if (RELUA) {
            v.x = fmaxf(v.x, 0.f); v.y = fmaxf(v.y, 0.f);
            v.z = fmaxf(v.z, 0.f); v.w = fmaxf(v.w, 0.f);
        }
    }
    return v;
}

__device__ __forceinline__ float4 sum2b(const float* __restrict__ P, size_t idx, size_t S,
                                        const float* __restrict__ bias, int bi) {
    float4 a = *(const float4*)(P + idx);
    float4 b = *(const float4*)(P + S + idx);
    float4 c = *(const float4*)(bias + bi);
    a.x += b.x + c.x; a.y += b.y + c.y; a.z += b.z + c.z; a.w += b.w + c.w;
    return a;
}

// ---------------- tensor-core GEMM worker (one 128-thread block) ----------------
// C(part z)[Mrows,N] = A @ B^T via split-bf16 HMMA. Tile 64x64, k-chunk 32,
// double-buffered smem, ONE __syncthreads per chunk.
// BSCALAR: B rows are NOT float4-aligned (stride sB); use scalar loads.
template <int NP, bool RELUA, bool BSCALAR>
__device__ void gemm_phase(const float* __restrict__ A, const float* __restrict__ ab,
                           const float* __restrict__ B, float* __restrict__ C,
                           int N, int K, int sB, int ntm, int ntn, int nsplit, int KS,
                           size_t SA, int Mrows, GemmSmem* sg, int tid, int grp) {
    const int ntpz = ntm * ntn;
    const int ntiles = ntpz * nsplit;
    const int warp = tid >> 5;
    const int lane = tid & 31;
    const int warp_m = (warp >> 1) * 32;
    const int warp_n = (warp & 1) * 32;
    const int lrow = lane & 15;
    const int lblk = lane >> 4;
    const int quad = lane >> 2;
    const int pr = lane & 3;

    const unsigned aAh = smem_u32(sg->Ah[0]);
    const unsigned aAl = smem_u32(sg->Al[0]);
    const unsigned aBh = smem_u32(sg->Bh[0]);
    const unsigned aBl = smem_u32(sg->Bl[0]);

    int buf = 0;
    for (int tile = grp; tile < ntiles; tile += NGRP) {
        int z = tile / ntpz;
        int rem = tile - z * ntpz;
        int m = rem / ntn;
        int n = rem - m * ntn;
        int bm0 = m * 64;
        int bn0 = n * 64;
        int k0s = z * KS;

        float acc[2][4][4];
        #pragma unroll
        for (int i = 0; i < 2; i++) {
            #pragma unroll
            for (int j = 0; j < 4; j++) {
                #pragma unroll
                for (int r = 0; r < 4; r++) { acc[i][j][r] = 0.f; }
            }
        }

        const int nch = KS / 32;
        float4 pa[4], pb[4];
        // prefetch chunk 0 into registers
        #pragma unroll
        for (int it = 0; it < 4; it++) {
            int f = tid + it * 128;
            int row = f >> 3;
            int c4 = (f & 7) * 4;
            int kc = k0s + c4;
            pa[it] = loadPre<NP, RELUA>(A, ab, (size_t)(bm0 + row) * K + kc, kc, SA);
            if (BSCALAR) {
                const float* br_ = B + (size_t)(bn0 + row) * sB + kc;
                pb[it].x = br_[0]; pb[it].y = br_[1]; pb[it].z = br_[2]; pb[it].w = br_[3];
            } else {
                pb[it] = *(const float4*)&B[(size_t)(bn0 + row) * K + kc];
            }
        }

        for (int ch = 0; ch < nch; ch++) {
            // stage prefetched regs into smem buffer `buf`
            #pragma unroll
            for (int it = 0; it < 4; it++) {
                int f = tid + it * 128;
                int row = f >> 3;
                int c4 = (f & 7) * 4;
                int off = row * LDS_PAD + c4;
                uint2 hi, lo;
                split4(pa[it], hi, lo);
                *(uint2*)(sg->Ah[buf] + off) = hi;
                *(uint2*)(sg->Al[buf] + off) = lo;
                split4(pb[it], hi, lo);
                *(uint2*)(sg->Bh[buf] + off) = hi;
                *(uint2*)(sg->Bl[buf] + off) = lo;
            }
            __syncthreads();

            // prefetch next chunk while MMAs run
            if (ch + 1 < nch) {
                int kb = k0s + (ch + 1) * 32;
                #pragma unroll
                for (int it = 0; it < 4; it++) {
                    int f = tid + it * 128;
                    int row = f >> 3;
                    int c4 = (f & 7) * 4;
                    int kc = kb + c4;
                    pa[it] = loadPre<NP, RELUA>(A, ab, (size_t)(bm0 + row) * K + kc, kc, SA);
                    if (BSCALAR) {
                        const float* br_ = B + (size_t)(bn0 + row) * sB + kc;
                        pb[it].x = br_[0]; pb[it].y = br_[1]; pb[it].z = br_[2]; pb[it].w = br_[3];
                    } else {
                        pb[it] = *(const float4*)&B[(size_t)(bn0 + row) * K + kc];
                    }
                }
            }

            // compute: two k16 steps from buffer `buf`
            const unsigned bofs = (unsigned)(buf * BUFB);
            #pragma unroll
            for (int ks16 = 0; ks16 < 2; ks16++) {
                int ko = ks16 * 16;
                unsigned ah[2][4], al[2][4], bh[2][4], bl[2][4];
                #pragma unroll
                for (int i = 0; i < 2; i++) {
                    unsigned o = bofs + (unsigned)(((warp_m + i * 16 + lrow) * LDS_PAD + ko + lblk * 8) * 2);
                    ldsm4(ah[i][0], ah[i][1], ah[i][2], ah[i][3], aAh + o);
                    ldsm4(al[i][0], al[i][1], al[i][2], al[i][3], aAl + o);
                }
                #pragma unroll
                for (int j = 0; j < 2; j++) {
                    unsigned o = bofs + (unsigned)(((warp_n + j * 16 + lrow) * LDS_PAD + ko + lblk * 8) * 2);
                    ldsm4(bh[j][0], bh[j][1], bh[j][2], bh[j][3], aBh + o);
                    ldsm4(bl[j][0], bl[j][1], bl[j][2], bl[j][3], aBl + o);
                }
                #pragma unroll
                for (int mi = 0; mi < 2; mi++) {
                    #pragma unroll
                    for (int nj = 0; nj < 2; nj++) {
                        #pragma unroll
                        for (int h = 0; h < 2; h++) {
                            int ni = nj * 2 + h;
                            mma_bf16(acc[mi][ni][0], acc[mi][ni][1], acc[mi][ni][2], acc[mi][ni][3],
                                     ah[mi][0], ah[mi][1], ah[mi][2], ah[mi][3],
                                     bh[nj][h], bh[nj][2 + h]);
                            mma_bf16(acc[mi][ni][0], acc[mi][ni][1], acc[mi][ni][2], acc[mi][ni][3],
                                     ah[mi][0], ah[mi][1], ah[mi][2], ah[mi][3],
                                     bl[nj][h], bl[nj][2 + h]);
                            mma_bf16(acc[mi][ni][0], acc[mi][ni][1], acc[mi][ni][2], acc[mi][ni][3],
                                     al[mi][0], al[mi][1], al[mi][2], al[mi][3],
                                     bh[nj][h], bh[nj][2 + h]);
                        }
                    }
                }
            }
            buf ^= 1;
        }

        // epilogue: write fp32 partial tile
        float* Cout = C + (size_t)z * Mrows * N;
        #pragma unroll
        for (int mi = 0; mi < 2; mi++) {
            #pragma unroll
            for (int ni = 0; ni < 4; ni++) {
                int mrow = bm0 + warp_m + mi * 16 + quad;
                int ncol = bn0 + warp_n + ni * 8 + pr * 2;
                float2 r0;
                r0.x = acc[mi][ni][0];
                r0.y = acc[mi][ni][1];
                float2 r1;
                r1.x = acc[mi][ni][2];
                r1.y = acc[mi][ni][3];
                *(float2*)&Cout[(size_t)mrow * N + ncol] = r0;
                *(float2*)&Cout[(size_t)(mrow + 8) * N + ncol] = r1;
            }
        }
    }
}

// ---------------- attention worker (one 128-thread block) ----------------
__device__ void attn_phase(AttnSmem* s, const float* __restrict__ bqkv, int tid, int grp) {
    constexpr size_t SQ = (size_t)BC * QKVn;
    for (int u = grp; u < Bn * Hn * 2; u += NGRP) {
        int b = u >> 3;
        int h = (u >> 1) & 3;
        int half = u & 1;
        int q0 = half * 16;
        #pragma unroll
        for (int it = 0; it < 4; it++) {
            int f = tid + it * 128;
            int c = f >> 4;
            int d4 = (f & 15) * 4;
            size_t base = (size_t)(b * Cn + c) * QKVn + h * HDn + d4;
            float4 kv = sum2b(g_qkvp, base + Rn, SQ, bqkv, Rn + h * HDn + d4);
            float4 vv = sum2b(g_qkvp, base + 2 * Rn, SQ, bqkv, 2 * Rn + h * HDn + d4);
            s->ks[c * 65 + d4 + 0] = kv.x; s->ks[c * 65 + d4 + 1] = kv.y;
            s->ks[c * 65 + d4 + 2] = kv.z; s->ks[c * 65 + d4 + 3] = kv.w;
            s->vs[c * 65 + d4 + 0] = vv.x; s->vs[c * 65 + d4 + 1] = vv.y;
            s->vs[c * 65 + d4 + 2] = vv.z; s->vs[c * 65 + d4 + 3] = vv.w;
        }
        #pragma unroll
        for (int it = 0; it < 2; it++) {
            int f = tid + it * 128;
            int c = f >> 4;
            int d4 = (f & 15) * 4;
            size_t base = (size_t)(b * Cn + q0 + c) * QKVn + h * HDn + d4;
            float4 qv = sum2b(g_qkvp, base, SQ, bqkv, h * HDn + d4);
            s->qs[c * 65 + d4 + 0] = qv.x; s->qs[c * 65 + d4 + 1] = qv.y;
            s->qs[c * 65 + d4 + 2] = qv.z; s->qs[c * 65 + d4 + 3] = qv.w;
        }
        __syncthreads();
        #pragma unroll
        for (int r = 0; r < 4; r++) {
            int i = tid + r * 128;
            int k = i & 31;
            int q = i >> 5;
            float sum = 0.f;
            #pragma unroll
            for (int d = 0; d < HDn; d++) { sum = fmaf(s->qs[q * 65 + d], s->ks[k * 65 + d], sum); }
            s->sc[q * 33 + k] = sum * 0.125f;
        }
        __syncthreads();
        if (tid < 16) {
            float mx = -1e30f;
            #pragma unroll
            for (int k = 0; k < Cn; k++) { mx = fmaxf(mx, s->sc[tid * 33 + k]); }
            float sum = 0.f;
            #pragma unroll
            for (int k = 0; k < Cn; k++) {
                float e = expf(s->sc[tid * 33 + k] - mx);
                s->sc[tid * 33 + k] = e;
                sum += e;
            }
            float inv = 1.f / sum;
            #pragma unroll
            for (int k = 0; k < Cn; k++) { s->sc[tid * 33 + k] *= inv; }
        }
        __syncthreads();
        #pragma unroll
        for (int r = 0; r < 8; r++) {
            int i = tid + r * 128;
            int d = i & 63;
            int q = i >> 6;
            float sum = 0.f;
            #pragma unroll
            for (int k = 0; k < Cn; k++) { sum = fmaf(s->sc[q * 33 + k], s->vs[k * 65 + d], sum); }
            g_att[(size_t)(b * Cn + q0 + q) * Rn + h * HDn + d] = sum;
        }
        __syncthreads();   // smem reused by next unit
    }
}

// ---------------- LayerNorm worker: one warp per row ----------------
// NPA: residual partial count in a (1 = plain). NPP: partial count in p.
template <int NPA, int NPP>
__device__ void ln_phase(const float* __restrict__ a, const float* __restrict__ ab,
                         const float* __restrict__ p, const float* __restrict__ pb,
                         const float* __restrict__ g, const float* __restrict__ be,
                         float* __restrict__ out) {
    int row = blockIdx.x * (NTHR / 32) + (threadIdx.x >> 5);
    if (row >= BC) { return; }
    const size_t S = (size_t)BC * Rn;
    int lane = threadIdx.x & 31;
    float v[8];
    #pragma unroll
    for (int j = 0; j < 8; j++) {
        int c = lane + 32 * j;
        size_t o = (size_t)row * Rn + c;
        float x = a[o];
        if (NPA >= 4) { x += a[S + o] + a[2 * S + o] + a[3 * S + o]; }
        if (NPA >= 8) {
            #pragma unroll
            for (int z = 4; z < 8; z++) { x += a[(size_t)z * S + o]; }
        }
        if (NPA > 1) { x += ab[c]; }
        float y = p[o];
        if (NPP >= 2) { y += p[S + o]; }
        if (NPP >= 4) { y += p[2 * S + o] + p[3 * S + o]; }
        v[j] = x + y + pb[c];
    }
    float sum = 0.f;
    #pragma unroll
    for (int j = 0; j < 8; j++) { sum += v[j]; }
    #pragma unroll
    for (int off = 16; off > 0; off >>= 1) { sum += __shfl_xor_sync(0xffffffffu, sum, off); }
    float mean = sum * (1.f / Rn);
    float q = 0.f;
    #pragma unroll
    for (int j = 0; j < 8; j++) { float d = v[j] - mean; q = fmaf(d, d, q); }
    #pragma unroll
    for (int off = 16; off > 0; off >>= 1) { q += __shfl_xor_sync(0xffffffffu, q, off); }
    float rstd = rsqrtf(q * (1.f / Rn) + 1e-5f);
    #pragma unroll
    for (int j = 0; j < 8; j++) {
        int c = lane + 32 * j;
        out[(size_t)row * Rn + c] = (v[j] - mean) * rstd * g[c] + be[c];
    }
}

// ---------------- megakernel ----------------
__global__ __launch_bounds__(NTHR, 4)
void mega_kernel(const float* __restrict__ embs, const int* __restrict__ indices,
                 const int* __restrict__ mask, const float* __restrict__ host_cat,
                 const float* __restrict__ virus_cat, const float* __restrict__ extra_meta,
                 const float* __restrict__ fw,
                 const float* __restrict__ Wr, const float* __restrict__ br,
                 const float* __restrict__ Wqkv, const float* __restrict__ bqkv,
                 const float* __restrict__ Wo, const float* __restrict__ bo,
                 const float* __restrict__ ln1_g, const float* __restrict__ ln1_b,
                 const float* __restrict__ W1, const float* __restrict__ b1,
                 const float* __restrict__ W2, const float* __restrict__ b2,
                 const float* __restrict__ ln2_g, const float* __restrict__ ln2_b,
                 const float* __restrict__ Wc1, const float* __restrict__ bc1,
                 const float* __restrict__ Wc2, const float* __restrict__ bc2,
                 float* __restrict__ out) {
    __shared__ SmemU sm;
    const int tid = threadIdx.x;
    const int grp = blockIdx.x;
    const int gid = blockIdx.x * NTHR + tid;

    // ---- P0: softmax weights per (b,c) segment ----
    if (gid < BC) {
        int bc = gid;
        float w[Sn];
        int any = 0;
        #pragma unroll
        for (int s = 0; s < Sn; s++) {
            int m = mask[bc * Sn + s];
            any |= m;
            w[s] = m ? fw[indices[bc * Sn + s]] : -1e30f;
        }
        float mx = -1e30f;
        #pragma unroll
        for (int s = 0; s < Sn; s++) { mx = fmaxf(mx, w[s]); }
        float e[Sn];
        float sum = 0.f;
        #pragma unroll
        for (int s = 0; s < Sn; s++) { e[s] = expf(w[s] - mx); sum += e[s]; }
        float inv = any ? (1.f / sum) : 0.f;
        #pragma unroll
        for (int s = 0; s < Sn; s++) { g_aw[bc * Sn + s] = e[s] * inv; }
    }
    gsync(0);

    // ---- P1: aggregation (HBM-bound) ----
    for (int u = gid; u < BC * (En / 4); u += NBLK * NTHR) {
        int bc = u / (En / 4);
        int col = u - bc * (En / 4);
        float aw[Sn];
        #pragma unroll
        for (int s = 0; s < Sn; s++) { aw[s] = g_aw[bc * Sn + s]; }
        const float4* eb = (const float4*)embs + (size_t)bc * Sn * (En / 4) + col;
        float4 acc;
        acc.x = 0.f; acc.y = 0.f; acc.z = 0.f; acc.w = 0.f;
        #pragma unroll
        for (int s = 0; s < Sn; s++) {
            float4 v = eb[s * (En / 4)];
            acc.x = fmaf(aw[s], v.x, acc.x);
            acc.y = fmaf(aw[s], v.y, acc.y);
            acc.z = fmaf(aw[s], v.z, acc.z);
            acc.w = fmaf(aw[s], v.w, acc.w);
        }
        ((float4*)g_agg)[(size_t)bc * (En / 4) + col] = acc;
    }
    gsync(1);

    // ---- P2: x0 partials = agg @ Wr^T (split 8, KS=160, 5 chunks) -> 512 tiles ----
    gemm_phase<0, false, false>(g_agg, (const float*)0, Wr, g_x0p, Rn, En, En,
                                16, 4, 8, 160, (size_t)0, BC, &sm.g, tid, grp);
    gsync(2);

    // ---- P3: qkv partials = (sum8 x0p + br) @ Wqkv^T (split 2, KS=128, 4 chunks) -> 384 tiles ----
    gemm_phase<8, false, false>(g_x0p, br, Wqkv, g_qkvp, QKVn, Rn, Rn,
                                16, 12, 2, 128, (size_t)BC * Rn, BC, &sm.g, tid, grp);
    gsync(3);

    // ---- P4: attention (256 units) ----
    attn_phase(&sm.a, bqkv, tid, grp);
    gsync(4);

    // ---- P5: oproj partials = att @ Wo^T (split 4, KS=64, 2 chunks) -> 256 tiles ----
    gemm_phase<0, false, false>(g_att, (const float*)0, Wo, g_opp, Rn, Rn, Rn,
                                16, 4, 4, 64, (size_t)0, BC, &sm.g, tid, grp);
    gsync(5);

    // ---- P6: x1 = LN(sum8 x0p + br + sum4 opp + bo) ----
    ln_phase<8, 4>(g_x0p, br, g_opp, bo, ln1_g, ln1_b, g_x1);
    gsync(6);

    // ---- P7: ff1 partials = x1 @ W1^T (split 4, KS=64, 2 chunks) -> 512 tiles ----
    gemm_phase<0, false, false>(g_x1, (const float*)0, W1, g_ff1p, FFn, Rn, Rn,
                                16, 8, 4, 64, (size_t)0, BC, &sm.g, tid, grp);
    gsync(7);

    // ---- P8: ff2 partials = relu(sum4 ff1p + b1) @ W2^T (split 4, KS=128, 4 chunks) -> 256 tiles ----
    gemm_phase<4, true, false>(g_ff1p, b1, W2, g_fpp, Rn, FFn, FFn,
                               16, 4, 4, 128, (size_t)BC * FFn, BC, &sm.g, tid, grp);
    gsync(8);

    // ---- P9: x2 = LN(x1 + sum4 fpp + b2) -> g_feat rows 0-31 (flat [32, 8192]) ----
    ln_phase<1, 4>(g_x1, (const float*)0, g_fpp, b2, ln2_g, ln2_b, g_feat);
    gsync(9);

    // ---- P10: head GEMM: hp = feat[64, 8192] @ Wc1[:, 0:8192]^T (split 64, KS=128, 4 chunks) ----
    // Wc1 rows stride 8291 (not float4-aligned) -> scalar B loads. Rows 32-63 of feat are zero.
    gemm_phase<0, false, true>(g_feat, (const float*)0, Wc1, g_hp, 128, HK, HEAD_IN,
                               1, 2, 64, 128, (size_t)0, 64, &sm.g, tid, grp);
    gsync(10);

    // ---- P11: head reduce + tail + bias + relu ----
    if (gid < Bn * 128) {
        int b = gid >> 7;
        int j = gid & 127;
        float s = 0.f;
        #pragma unroll 8
        for (int z = 0; z < 64; z++) { s += g_hp[(size_t)z * 64 * 128 + b * 128 + j]; }
        const float* wr = Wc1 + (size_t)j * HEAD_IN + HK;
        const float* hc = host_cat + b * 64;
        for (int i = 0; i < 64; i++) { s = fmaf(wr[i], hc[i], s); }
        const float* vc = virus_cat + b * 32;
        for (int i = 0; i < 32; i++) { s = fmaf(wr[64 + i], vc[i], s); }
        const float* mt = extra_meta + b * 3;
        for (int i = 0; i < 3; i++) { s = fmaf(wr[96 + i], mt[i], s); }
        g_h[b * 128 + j] = fmaxf(s + bc1[j], 0.f);
    }
    gsync(11);

    // ---- P12: logits ----
    {
        int gwarp = blockIdx.x * (NTHR / 32) + (tid >> 5);
        int lane = tid & 31;
        if (gwarp < Bn) {
            float v = 0.f;
            #pragma unroll
            for (int r = 0; r < 4; r++) {
                int i = lane + 32 * r;
                v = fmaf(g_h[gwarp * 128 + i], Wc2[i], v);
            }
            #pragma unroll
            for (int off = 16; off > 0; off >>= 1) { v += __shfl_xor_sync(0xffffffffu, v, off); }
            if (lane == 0) { out[gwarp] = v + bc2[0]; }
        }
    }
}

// ---------------- launch ----------------
extern "C" void kernel_launch(void* const* d_in, const int* in_sizes, int n_in,
                              void* d_out, int out_size) {
    const float* embs        = (const float*)d_in[0];
    const int*   indices     = (const int*)d_in[1];
    const int*   mask        = (const int*)d_in[2];     // bool -> int32
    const float* host_cat    = (const float*)d_in[3];
    const float* virus_cat   = (const float*)d_in[4];
    const float* extra_meta  = (const float*)d_in[5];
    const float* func_weights= (const float*)d_in[6];
    const float* Wr          = (const float*)d_in[7];
    const float* br          = (const float*)d_in[8];
    const float* Wqkv        = (const float*)d_in[9];
    const float* bqkv        = (const float*)d_in[10];
    const float* Wo          = (const float*)d_in[11];
    const float* bo          = (const float*)d_in[12];
    const float* ln1_g       = (const float*)d_in[13];
    const float* ln1_b       = (const float*)d_in[14];
    const float* W1          = (const float*)d_in[15];
    const float* b1          = (const float*)d_in[16];
    const float* W2          = (const float*)d_in[17];
    const float* b2          = (const float*)d_in[18];
    const float* ln2_g       = (const float*)d_in[19];
    const float* ln2_b       = (const float*)d_in[20];
    const float* Wc1         = (const float*)d_in[21];
    const float* bc1         = (const float*)d_in[22];
    const float* Wc2         = (const float*)d_in[23];
    const float* bc2         = (const float*)d_in[24];
    float* out = (float*)d_out;

    mega_kernel<<<NBLK, NTHR>>>(embs, indices, mask, host_cat, virus_cat, extra_meta,
                                func_weights, Wr, br, Wqkv, bqkv, Wo, bo,
                                ln1_g, ln1_b, W1, b1, W2, b2, ln2_g, ln2_b,
                                Wc1, bc1, Wc2, bc2, out);
}

// round 12
// speedup vs baseline: 2.3688x; 1.0155x over previous
#include <cuda_runtime.h>
#include <cuda_bf16.h>
#include <cstdint>
#include <math.h>

// ---------------- problem constants ----------------
static constexpr int Bn = 32, Cn = 32, Sn = 16, En = 1280, Rn = 256;
static constexpr int Hn = 4, HDn = 64, FFn = 512;
static constexpr int BC = Bn * Cn;               // 1024 tokens
static constexpr int HEAD_IN = Cn * Rn + 64 + 32 + 3;  // 8291
static constexpr int QKVn = 3 * Rn;              // 768
static constexpr int HK = 8192;                  // head GEMM K (aligned part)

static constexpr int NBLK = 592;                 // persistent blocks (4 per SM)
static constexpr int NTHR = 128;                 // one worker group per block
static constexpr int NGRP = NBLK;

static constexpr int LDS_PAD = 40;               // bf16 elems per smem row (32 + 8 pad)
static constexpr int BUFB = 64 * LDS_PAD * 2;    // bytes per smem buffer (5120)

// ---------------- device scratch ----------------
__device__ __align__(16) float g_agg[BC * En];
__device__ __align__(16) float g_x0p[8 * BC * Rn];    // x0 partials (split 8)
__device__ __align__(16) float g_qkvp[2 * BC * QKVn]; // qkv partials (split 2)
__device__ __align__(16) float g_att[BC * Rn];
__device__ __align__(16) float g_opp[4 * BC * Rn];    // oproj partials (split 4)
__device__ __align__(16) float g_x1[BC * Rn];
__device__ __align__(16) float g_ff1p[4 * BC * FFn];  // ff1 partials (split 4)
__device__ __align__(16) float g_fpp[4 * BC * Rn];    // ff2 partials (split 4)
__device__ __align__(16) float g_feat[64 * HK];       // rows 0-31 = x2 flat; 32-63 stay zero
__device__ __align__(16) float g_hp[128 * 64 * 128];  // head partials (split 128)
__device__ unsigned g_bar[16];                        // monotonic barrier counters

// pre-split bf16 weights (hi/lo)
__device__ __align__(16) unsigned short g_WrH[Rn * En],    g_WrL[Rn * En];
__device__ __align__(16) unsigned short g_WqH[QKVn * Rn],  g_WqL[QKVn * Rn];
__device__ __align__(16) unsigned short g_WoH[Rn * Rn],    g_WoL[Rn * Rn];
__device__ __align__(16) unsigned short g_W1H[FFn * Rn],   g_W1L[FFn * Rn];
__device__ __align__(16) unsigned short g_W2H[Rn * FFn],   g_W2L[Rn * FFn];
__device__ __align__(16) unsigned short g_WcH[128 * HK],   g_WcL[128 * HK];

// ---------------- shared memory (union across phases) ----------------
struct GemmSmem {
    unsigned short Ah[2][64 * LDS_PAD];
    unsigned short Al[2][64 * LDS_PAD];
    unsigned short Bh[2][64 * LDS_PAD];
    unsigned short Bl[2][64 * LDS_PAD];
};  // 40960 B
struct AttnSmem {
    float ks[32 * 65];
    float vs[32 * 65];
    float qs[16 * 65];
    float sc[16 * 33];
};
union SmemU {
    GemmSmem g;
    AttnSmem a;
};

// ---------------- grid-wide barrier (monotonic, replay-safe) ----------------
__device__ __forceinline__ void gsync(int k) {
    __syncthreads();
    if (threadIdx.x == 0) {
        __threadfence();
        unsigned old = atomicAdd(&g_bar[k], 1u);
        unsigned target = (old / NBLK + 1u) * NBLK;
        volatile unsigned* p = &g_bar[k];
        while (*p < target) { }
        __threadfence();
    }
    __syncthreads();
}

// ---------------- smem address helper ----------------
__device__ __forceinline__ unsigned smem_u32(const void* p) {
    unsigned addr;
    asm("{ .reg .u64 t; cvta.to.shared.u64 t, %1; cvt.u32.u64 %0, t; }"
        : "=r"(addr) : "l"(p));
    return addr;
}

// ---------------- mma / ldmatrix helpers ----------------
__device__ __forceinline__ void ldsm4(unsigned& r0, unsigned& r1, unsigned& r2, unsigned& r3,
                                      unsigned addr) {
    asm volatile("ldmatrix.sync.aligned.m8n8.x4.shared.b16 {%0,%1,%2,%3}, [%4];"
                 : "=r"(r0), "=r"(r1), "=r"(r2), "=r"(r3) : "r"(addr));
}

__device__ __forceinline__ void mma_bf16(float& c0, float& c1, float& c2, float& c3,
                                         unsigned a0, unsigned a1, unsigned a2, unsigned a3,
                                         unsigned b0, unsigned b1) {
    asm volatile(
        "mma.sync.aligned.m16n8k16.row.col.f32.bf16.bf16.f32 "
        "{%0,%1,%2,%3}, {%4,%5,%6,%7}, {%8,%9}, {%0,%1,%2,%3};"
        : "+f"(c0), "+f"(c1), "+f"(c2), "+f"(c3)
        : "r"(a0), "r"(a1), "r"(a2), "r"(a3), "r"(b0), "r"(b1));
}

__device__ __forceinline__ unsigned bf16bits(float x) {
    return (unsigned)__bfloat16_as_ushort(__float2bfloat16_rn(x));
}

// split one float4 into hi/lo packed bf16 pairs (hi = rn(x), lo = rn(x - hi))
__device__ __forceinline__ void split4(float4 v, uint2& hi, uint2& lo) {
    unsigned h0 = bf16bits(v.x), h1 = bf16bits(v.y), h2 = bf16bits(v.z), h3 = bf16bits(v.w);
    float f0 = __bfloat162float(__ushort_as_bfloat16((unsigned short)h0));
    float f1 = __bfloat162float(__ushort_as_bfloat16((unsigned short)h1));
    float f2 = __bfloat162float(__ushort_as_bfloat16((unsigned short)h2));
    float f3 = __bfloat162float(__ushort_as_bfloat16((unsigned short)h3));
    unsigned l0 = bf16bits(v.x - f0), l1 = bf16bits(v.y - f1);
    unsigned l2 = bf16bits(v.z - f2), l3 = bf16bits(v.w - f3);
    hi.x = h0 | (h1 << 16);
    hi.y = h2 | (h3 << 16);
    lo.x = l0 | (l1 << 16);
    lo.y = l2 | (l3 << 16);
}

// ---------------- A-operand preprocessing ----------------
template <int NP, bool RELUA>
__device__ __forceinline__ float4 loadPre(const float* __restrict__ A,
                                          const float* __restrict__ ab,
                                          size_t idx, int bcol, size_t SA) {
    float4 v = *(const float4*)(A + idx);
    if (NP >= 2) {
        float4 t = *(const float4*)(A + SA + idx);
        v.x += t.x; v.y += t.y; v.z += t.z; v.w += t.w;
    }
    if (NP >= 4) {
        float4 t = *(const float4*)(A + 2 * SA + idx);
        float4 u = *(const float4*)(A + 3 * SA + idx);
        v.x += t.x + u.x; v.y += t.y + u.y; v.z += t.z + u.z; v.w += t.w + u.w;
    }
    if (NP >= 8) {
        #pragma unroll
        for (int z = 4; z < 8; z++) {
            float4 t = *(const float4*)(A + (size_t)z * SA + idx);
            v.x += t.x; v.y += t.y; v.z += t.z; v.w += t.w;
        }
    }
    if (NP > 0) {
        float4 bb = *(const float4*)(ab + bcol);
        v.x += bb.x; v.y += bb.y; v.z += bb.z; v.w += bb.w;
        if (RELUA) {
            v.x = fmaxf(v.x, 0.f); v.y = fmaxf(v.y, 0.f);
            v.z = fmaxf(v.z, 0.f); v.w = fmaxf(v.w, 0.f);
        }
    }
    return v;
}

__device__ __forceinline__ float4 sum2b(const float* __restrict__ P, size_t idx, size_t S,
                                        const float* __restrict__ bias, int bi) {
    float4 a = *(const float4*)(P + idx);
    float4 b = *(const float4*)(P + S + idx);
    float4 c = *(const float4*)(bias + bi);
    a.x += b.x + c.x; a.y += b.y + c.y; a.z += b.z + c.z; a.w += b.w + c.w;
    return a;
}

// ---------------- weight split-conversion helpers ----------------
__device__ void conv_w(const float* __restrict__ src, unsigned short* __restrict__ dh,
                       unsigned short* __restrict__ dl, int n4, int gid0, int gstride) {
    for (int i = gid0; i < n4; i += gstride) {
        float4 v = ((const float4*)src)[i];
        uint2 hi, lo;
        split4(v, hi, lo);
        *(uint2*)(dh + (size_t)i * 4) = hi;
        *(uint2*)(dl + (size_t)i * 4) = lo;
    }
}

// ---------------- tensor-core GEMM worker (one 128-thread block) ----------------
// C(part z)[Mrows,N] = A @ B^T. A fp32 (+fused preproc), B pre-split bf16 hi/lo.
// Tile 64x64, k-chunk 32, double-buffered smem, one __syncthreads per chunk.
template <int NP, bool RELUA>
__device__ void gemm_phase(const float* __restrict__ A, const float* __restrict__ ab,
                           const unsigned short* __restrict__ BH,
                           const unsigned short* __restrict__ BL,
                           float* __restrict__ C,
                           int N, int K, int ntm, int ntn, int nsplit, int KS,
                           size_t SA, int Mrows, GemmSmem* sg, int tid, int grp) {
    const int ntpz = ntm * ntn;
    const int ntiles = ntpz * nsplit;
    const int warp = tid >> 5;
    const int lane = tid & 31;
    const int warp_m = (warp >> 1) * 32;
    const int warp_n = (warp & 1) * 32;
    const int lrow = lane & 15;
    const int lblk = lane >> 4;
    const int quad = lane >> 2;
    const int pr = lane & 3;

    const unsigned aAh = smem_u32(sg->Ah[0]);
    const unsigned aAl = smem_u32(sg->Al[0]);
    const unsigned aBh = smem_u32(sg->Bh[0]);
    const unsigned aBl = smem_u32(sg->Bl[0]);

    int buf = 0;
    for (int tile = grp; tile < ntiles; tile += NGRP) {
        int z = tile / ntpz;
        int rem = tile - z * ntpz;
        int m = rem / ntn;
        int n = rem - m * ntn;
        int bm0 = m * 64;
        int bn0 = n * 64;
        int k0s = z * KS;

        float acc[2][4][4];
        #pragma unroll
        for (int i = 0; i < 2; i++) {
            #pragma unroll
            for (int j = 0; j < 4; j++) {
                #pragma unroll
                for (int r = 0; r < 4; r++) { acc[i][j][r] = 0.f; }
            }
        }

        const int nch = KS / 32;
        float4 pa[4];
        uint2 pbh[4], pbl[4];
        // prefetch chunk 0
        #pragma unroll
        for (int it = 0; it < 4; it++) {
            int f = tid + it * 128;
            int row = f >> 3;
            int c4 = (f & 7) * 4;
            int kc = k0s + c4;
            pa[it] = loadPre<NP, RELUA>(A, ab, (size_t)(bm0 + row) * K + kc, kc, SA);
            size_t bo_ = (size_t)(bn0 + row) * K + kc;
            pbh[it] = *(const uint2*)(BH + bo_);
            pbl[it] = *(const uint2*)(BL + bo_);
        }

        for (int ch = 0; ch < nch; ch++) {
            // stage prefetched regs into smem buffer `buf`
            #pragma unroll
            for (int it = 0; it < 4; it++) {
                int f = tid + it * 128;
                int row = f >> 3;
                int c4 = (f & 7) * 4;
                int off = row * LDS_PAD + c4;
                uint2 hi, lo;
                split4(pa[it], hi, lo);
                *(uint2*)(sg->Ah[buf] + off) = hi;
                *(uint2*)(sg->Al[buf] + off) = lo;
                *(uint2*)(sg->Bh[buf] + off) = pbh[it];
                *(uint2*)(sg->Bl[buf] + off) = pbl[it];
            }
            __syncthreads();

            // prefetch next chunk while MMAs run
            if (ch + 1 < nch) {
                int kb = k0s + (ch + 1) * 32;
                #pragma unroll
                for (int it = 0; it < 4; it++) {
                    int f = tid + it * 128;
                    int row = f >> 3;
                    int c4 = (f & 7) * 4;
                    int kc = kb + c4;
                    pa[it] = loadPre<NP, RELUA>(A, ab, (size_t)(bm0 + row) * K + kc, kc, SA);
                    size_t bo_ = (size_t)(bn0 + row) * K + kc;
                    pbh[it] = *(const uint2*)(BH + bo_);
                    pbl[it] = *(const uint2*)(BL + bo_);
                }
            }

            // compute: two k16 steps
            const unsigned bofs = (unsigned)(buf * BUFB);
            #pragma unroll
            for (int ks16 = 0; ks16 < 2; ks16++) {
                int ko = ks16 * 16;
                unsigned ah[2][4], al[2][4], bh[2][4], bl[2][4];
                #pragma unroll
                for (int i = 0; i < 2; i++) {
                    unsigned o = bofs + (unsigned)(((warp_m + i * 16 + lrow) * LDS_PAD + ko + lblk * 8) * 2);
                    ldsm4(ah[i][0], ah[i][1], ah[i][2], ah[i][3], aAh + o);
                    ldsm4(al[i][0], al[i][1], al[i][2], al[i][3], aAl + o);
                }
                #pragma unroll
                for (int j = 0; j < 2; j++) {
                    unsigned o = bofs + (unsigned)(((warp_n + j * 16 + lrow) * LDS_PAD + ko + lblk * 8) * 2);
                    ldsm4(bh[j][0], bh[j][1], bh[j][2], bh[j][3], aBh + o);
                    ldsm4(bl[j][0], bl[j][1], bl[j][2], bl[j][3], aBl + o);
                }
                #pragma unroll
                for (int mi = 0; mi < 2; mi++) {
                    #pragma unroll
                    for (int nj = 0; nj < 2; nj++) {
                        #pragma unroll
                        for (int h = 0; h < 2; h++) {
                            int ni = nj * 2 + h;
                            mma_bf16(acc[mi][ni][0], acc[mi][ni][1], acc[mi][ni][2], acc[mi][ni][3],
                                     ah[mi][0], ah[mi][1], ah[mi][2], ah[mi][3],
                                     bh[nj][h], bh[nj][2 + h]);
                            mma_bf16(acc[mi][ni][0], acc[mi][ni][1], acc[mi][ni][2], acc[mi][ni][3],
                                     ah[mi][0], ah[mi][1], ah[mi][2], ah[mi][3],
                                     bl[nj][h], bl[nj][2 + h]);
                            mma_bf16(acc[mi][ni][0], acc[mi][ni][1], acc[mi][ni][2], acc[mi][ni][3],
                                     al[mi][0], al[mi][1], al[mi][2], al[mi][3],
                                     bh[nj][h], bh[nj][2 + h]);
                        }
                    }
                }
            }
            buf ^= 1;
        }

        // epilogue: write fp32 partial tile
        float* Cout = C + (size_t)z * Mrows * N;
        #pragma unroll
        for (int mi = 0; mi < 2; mi++) {
            #pragma unroll
            for (int ni = 0; ni < 4; ni++) {
                int mrow = bm0 + warp_m + mi * 16 + quad;
                int ncol = bn0 + warp_n + ni * 8 + pr * 2;
                float2 r0;
                r0.x = acc[mi][ni][0];
                r0.y = acc[mi][ni][1];
                float2 r1;
                r1.x = acc[mi][ni][2];
                r1.y = acc[mi][ni][3];
                *(float2*)&Cout[(size_t)mrow * N + ncol] = r0;
                *(float2*)&Cout[(size_t)(mrow + 8) * N + ncol] = r1;
            }
        }
    }
}

// ---------------- attention worker (one 128-thread block) ----------------
__device__ void attn_phase(AttnSmem* s, const float* __restrict__ bqkv, int tid, int grp) {
    constexpr size_t SQ = (size_t)BC * QKVn;
    for (int u = grp; u < Bn * Hn * 2; u += NGRP) {
        int b = u >> 3;
        int h = (u >> 1) & 3;
        int half = u & 1;
        int q0 = half * 16;
        #pragma unroll
        for (int it = 0; it < 4; it++) {
            int f = tid + it * 128;
            int c = f >> 4;
            int d4 = (f & 15) * 4;
            size_t base = (size_t)(b * Cn + c) * QKVn + h * HDn + d4;
            float4 kv = sum2b(g_qkvp, base + Rn, SQ, bqkv, Rn + h * HDn + d4);
            float4 vv = sum2b(g_qkvp, base + 2 * Rn, SQ, bqkv, 2 * Rn + h * HDn + d4);
            s->ks[c * 65 + d4 + 0] = kv.x; s->ks[c * 65 + d4 + 1] = kv.y;
            s->ks[c * 65 + d4 + 2] = kv.z; s->ks[c * 65 + d4 + 3] = kv.w;
            s->vs[c * 65 + d4 + 0] = vv.x; s->vs[c * 65 + d4 + 1] = vv.y;
            s->vs[c * 65 + d4 + 2] = vv.z; s->vs[c * 65 + d4 + 3] = vv.w;
        }
        #pragma unroll
        for (int it = 0; it < 2; it++) {
            int f = tid + it * 128;
            int c = f >> 4;
            int d4 = (f & 15) * 4;
            size_t base = (size_t)(b * Cn + q0 + c) * QKVn + h * HDn + d4;
            float4 qv = sum2b(g_qkvp, base, SQ, bqkv, h * HDn + d4);
            s->qs[c * 65 + d4 + 0] = qv.x; s->qs[c * 65 + d4 + 1] = qv.y;
            s->qs[c * 65 + d4 + 2] = qv.z; s->qs[c * 65 + d4 + 3] = qv.w;
        }
        __syncthreads();
        #pragma unroll
        for (int r = 0; r < 4; r++) {
            int i = tid + r * 128;
            int k = i & 31;
            int q = i >> 5;
            float sum = 0.f;
            #pragma unroll
            for (int d = 0; d < HDn; d++) { sum = fmaf(s->qs[q * 65 + d], s->ks[k * 65 + d], sum); }
            s->sc[q * 33 + k] = sum * 0.125f;
        }
        __syncthreads();
        if (tid < 16) {
            float mx = -1e30f;
            #pragma unroll
            for (int k = 0; k < Cn; k++) { mx = fmaxf(mx, s->sc[tid * 33 + k]); }
            float sum = 0.f;
            #pragma unroll
            for (int k = 0; k < Cn; k++) {
                float e = expf(s->sc[tid * 33 + k] - mx);
                s->sc[tid * 33 + k] = e;
                sum += e;
            }
            float inv = 1.f / sum;
            #pragma unroll
            for (int k = 0; k < Cn; k++) { s->sc[tid * 33 + k] *= inv; }
        }
        __syncthreads();
        #pragma unroll
        for (int r = 0; r < 8; r++) {
            int i = tid + r * 128;
            int d = i & 63;
            int q = i >> 6;
            float sum = 0.f;
            #pragma unroll
            for (int k = 0; k < Cn; k++) { sum = fmaf(s->sc[q * 33 + k], s->vs[k * 65 + d], sum); }
            g_att[(size_t)(b * Cn + q0 + q) * Rn + h * HDn + d] = sum;
        }
        __syncthreads();   // smem reused by next unit
    }
}

// ---------------- LayerNorm worker: one warp per row ----------------
template <int NPA, int NPP>
__device__ void ln_phase(const float* __restrict__ a, const float* __restrict__ ab,
                         const float* __restrict__ p, const float* __restrict__ pb,
                         const float* __restrict__ g, const float* __restrict__ be,
                         float* __restrict__ out) {
    int row = blockIdx.x * (NTHR / 32) + (threadIdx.x >> 5);
    if (row >= BC) { return; }
    const size_t S = (size_t)BC * Rn;
    int lane = threadIdx.x & 31;
    float v[8];
    #pragma unroll
    for (int j = 0; j < 8; j++) {
        int c = lane + 32 * j;
        size_t o = (size_t)row * Rn + c;
        float x = a[o];
        if (NPA >= 4) { x += a[S + o] + a[2 * S + o] + a[3 * S + o]; }
        if (NPA >= 8) {
            #pragma unroll
            for (int z = 4; z < 8; z++) { x += a[(size_t)z * S + o]; }
        }
        if (NPA > 1) { x += ab[c]; }
        float y = p[o];
        if (NPP >= 2) { y += p[S + o]; }
        if (NPP >= 4) { y += p[2 * S + o] + p[3 * S + o]; }
        v[j] = x + y + pb[c];
    }
    float sum = 0.f;
    #pragma unroll
    for (int j = 0; j < 8; j++) { sum += v[j]; }
    #pragma unroll
    for (int off = 16; off > 0; off >>= 1) { sum += __shfl_xor_sync(0xffffffffu, sum, off); }
    float mean = sum * (1.f / Rn);
    float q = 0.f;
    #pragma unroll
    for (int j = 0; j < 8; j++) { float d = v[j] - mean; q = fmaf(d, d, q); }
    #pragma unroll
    for (int off = 16; off > 0; off >>= 1) { q += __shfl_xor_sync(0xffffffffu, q, off); }
    float rstd = rsqrtf(q * (1.f / Rn) + 1e-5f);
    #pragma unroll
    for (int j = 0; j < 8; j++) {
        int c = lane + 32 * j;
        out[(size_t)row * Rn + c] = (v[j] - mean) * rstd * g[c] + be[c];
    }
}

// ---------------- megakernel ----------------
__global__ __launch_bounds__(NTHR, 4)
void mega_kernel(const float* __restrict__ embs, const int* __restrict__ indices,
                 const int* __restrict__ mask, const float* __restrict__ host_cat,
                 const float* __restrict__ virus_cat, const float* __restrict__ extra_meta,
                 const float* __restrict__ fw,
                 const float* __restrict__ Wr, const float* __restrict__ br,
                 const float* __restrict__ Wqkv, const float* __restrict__ bqkv,
                 const float* __restrict__ Wo, const float* __restrict__ bo,
                 const float* __restrict__ ln1_g, const float* __restrict__ ln1_b,
                 const float* __restrict__ W1, const float* __restrict__ b1,
                 const float* __restrict__ W2, const float* __restrict__ b2,
                 const float* __restrict__ ln2_g, const float* __restrict__ ln2_b,
                 const float* __restrict__ Wc1, const float* __restrict__ bc1,
                 const float* __restrict__ Wc2, const float* __restrict__ bc2,
                 float* __restrict__ out) {
    __shared__ SmemU sm;
    __shared__ float s_red[4];
    const int tid = threadIdx.x;
    const int grp = blockIdx.x;
    const int gid = blockIdx.x * NTHR + tid;
    const int lane = tid & 31;

    // ---- P0: aggregation with warp-inline softmax  +  weight pre-split ----
    // Each warp iteration covers 32 consecutive units of ONE (b,c) segment
    // (En/4 = 320 = 10 warps exactly; strides are warp-aligned).
    for (int u = gid; u < BC * (En / 4); u += NBLK * NTHR) {
        int bc = u / (En / 4);
        int col = u - bc * (En / 4);
        // warp-cooperative softmax over the 16 slots (lanes 0-15 own slots; 16-31 mirror)
        int s16 = lane & 15;
        int mval = mask[bc * Sn + s16];
        float wv = mval ? fw[indices[bc * Sn + s16]] : -1e30f;
        unsigned anyb = __ballot_sync(0xffffffffu, mval != 0);
        float mx = wv;
        #pragma unroll
        for (int off = 8; off > 0; off >>= 1) { mx = fmaxf(mx, __shfl_xor_sync(0xffffffffu, mx, off)); }
        float e = expf(wv - mx);
        float esum = e;
        #pragma unroll
        for (int off = 8; off > 0; off >>= 1) { esum += __shfl_xor_sync(0xffffffffu, esum, off); }
        float myw = (anyb & 0xffffu) ? (e / esum) : 0.f;   // weight for slot s16, held by this lane

        const float4* eb = (const float4*)embs + (size_t)bc * Sn * (En / 4) + col;
        float4 acc;
        acc.x = 0.f; acc.y = 0.f; acc.z = 0.f; acc.w = 0.f;
        #pragma unroll
        for (int s = 0; s < Sn; s++) {
            float a = __shfl_sync(0xffffffffu, myw, s);
            float4 v = eb[s * (En / 4)];
            acc.x = fmaf(a, v.x, acc.x);
            acc.y = fmaf(a, v.y, acc.y);
            acc.z = fmaf(a, v.z, acc.z);
            acc.w = fmaf(a, v.w, acc.w);
        }
        ((float4*)g_agg)[(size_t)bc * (En / 4) + col] = acc;
    }
    // weight conversions (independent of agg)
    {
        const int gs = NBLK * NTHR;
        conv_w(Wr,   g_WrH, g_WrL, Rn * En / 4,   gid, gs);
        conv_w(Wqkv, g_WqH, g_WqL, QKVn * Rn / 4, gid, gs);
        conv_w(Wo,   g_WoH, g_WoL, Rn * Rn / 4,   gid, gs);
        conv_w(W1,   g_W1H, g_W1L, FFn * Rn / 4,  gid, gs);
        conv_w(W2,   g_W2H, g_W2L, Rn * FFn / 4,  gid, gs);
        // Wc1[:, 0:8192] -> compact stride-8192 arrays (src rows stride 8291, scalar loads)
        for (int i = gid; i < 128 * (HK / 4); i += gs) {
            int row = i >> 11;
            int c4 = (i & 2047) * 4;
            const float* sp = Wc1 + (size_t)row * HEAD_IN + c4;
            float4 v;
            v.x = sp[0]; v.y = sp[1]; v.z = sp[2]; v.w = sp[3];
            uint2 hi, lo;
            split4(v, hi, lo);
            *(uint2*)(g_WcH + (size_t)row * HK + c4) = hi;
            *(uint2*)(g_WcL + (size_t)row * HK + c4) = lo;
        }
    }
    gsync(0);

    // ---- P2: x0 partials = agg @ Wr^T (split 8, KS=160, 5 chunks) -> 512 tiles ----
    gemm_phase<0, false>(g_agg, (const float*)0, g_WrH, g_WrL, g_x0p, Rn, En,
                         16, 4, 8, 160, (size_t)0, BC, &sm.g, tid, grp);
    gsync(1);

    // ---- P3: qkv partials = (sum8 x0p + br) @ Wqkv^T (split 2, KS=128) -> 384 tiles ----
    gemm_phase<8, false>(g_x0p, br, g_WqH, g_WqL, g_qkvp, QKVn, Rn,
                         16, 12, 2, 128, (size_t)BC * Rn, BC, &sm.g, tid, grp);
    gsync(2);

    // ---- P4: attention (256 units) ----
    attn_phase(&sm.a, bqkv, tid, grp);
    gsync(3);

    // ---- P5: oproj partials = att @ Wo^T (split 4, KS=64, 2 chunks) -> 256 tiles ----
    gemm_phase<0, false>(g_att, (const float*)0, g_WoH, g_WoL, g_opp, Rn, Rn,
                         16, 4, 4, 64, (size_t)0, BC, &sm.g, tid, grp);
    gsync(4);

    // ---- P6: x1 = LN(sum8 x0p + br + sum4 opp + bo) ----
    ln_phase<8, 4>(g_x0p, br, g_opp, bo, ln1_g, ln1_b, g_x1);
    gsync(5);

    // ---- P7: ff1 partials = x1 @ W1^T (split 4, KS=64, 2 chunks) -> 512 tiles ----
    gemm_phase<0, false>(g_x1, (const float*)0, g_W1H, g_W1L, g_ff1p, FFn, Rn,
                         16, 8, 4, 64, (size_t)0, BC, &sm.g, tid, grp);
    gsync(6);

    // ---- P8: ff2 partials = relu(sum4 ff1p + b1) @ W2^T (split 4, KS=128) -> 256 tiles ----
    gemm_phase<4, true>(g_ff1p, b1, g_W2H, g_W2L, g_fpp, Rn, FFn,
                        16, 4, 4, 128, (size_t)BC * FFn, BC, &sm.g, tid, grp);
    gsync(7);

    // ---- P9: x2 = LN(x1 + sum4 fpp + b2) -> g_feat rows 0-31 (flat [32, 8192]) ----
    ln_phase<1, 4>(g_x1, (const float*)0, g_fpp, b2, ln2_g, ln2_b, g_feat);
    gsync(8);

    // ---- P10: head GEMM: hp = feat[64, 8192] @ Wc1h[128, 8192]^T (split 128, KS=64, 2 chunks) ----
    gemm_phase<0, false>(g_feat, (const float*)0, g_WcH, g_WcL, g_hp, 128, HK,
                         1, 2, 128, 64, (size_t)0, 64, &sm.g, tid, grp);
    gsync(9);

    // ---- P11: head reduce + tail + bias + relu + logits (block b = batch b) ----
    if (grp < Bn) {
        int b = grp;
        int j = tid;   // 128 threads = 128 hidden units
        float s = 0.f;
        #pragma unroll 8
        for (int z = 0; z < 128; z++) { s += g_hp[(size_t)z * (64 * 128) + b * 128 + j]; }
        const float* wr = Wc1 + (size_t)j * HEAD_IN + HK;
        const float* hc = host_cat + b * 64;
        for (int i = 0; i < 64; i++) { s = fmaf(wr[i], hc[i], s); }
        const float* vc = virus_cat + b * 32;
        for (int i = 0; i < 32; i++) { s = fmaf(wr[64 + i], vc[i], s); }
        const float* mt = extra_meta + b * 3;
        for (int i = 0; i < 3; i++) { s = fmaf(wr[96 + i], mt[i], s); }
        float hval = fmaxf(s + bc1[j], 0.f);
        float v = hval * Wc2[j];
        #pragma unroll
        for (int off = 16; off > 0; off >>= 1) { v += __shfl_xor_sync(0xffffffffu, v, off); }
        if (lane == 0) { s_red[tid >> 5] = v; }
        __syncthreads();
        if (tid == 0) { out[b] = s_red[0] + s_red[1] + s_red[2] + s_red[3] + bc2[0]; }
    }
}

// ---------------- launch ----------------
extern "C" void kernel_launch(void* const* d_in, const int* in_sizes, int n_in,
                              void* d_out, int out_size) {
    const float* embs        = (const float*)d_in[0];
    const int*   indices     = (const int*)d_in[1];
    const int*   mask        = (const int*)d_in[2];     // bool -> int32
    const float* host_cat    = (const float*)d_in[3];
    const float* virus_cat   = (const float*)d_in[4];
    const float* extra_meta  = (const float*)d_in[5];
    const float* func_weights= (const float*)d_in[6];
    const float* Wr          = (const float*)d_in[7];
    const float* br          = (const float*)d_in[8];
    const float* Wqkv        = (const float*)d_in[9];
    const float* bqkv        = (const float*)d_in[10];
    const float* Wo          = (const float*)d_in[11];
    const float* bo          = (const float*)d_in[12];
    const float* ln1_g       = (const float*)d_in[13];
    const float* ln1_b       = (const float*)d_in[14];
    const float* W1          = (const float*)d_in[15];
    const float* b1          = (const float*)d_in[16];
    const float* W2          = (const float*)d_in[17];
    const float* b2          = (const float*)d_in[18];
    const float* ln2_g       = (const float*)d_in[19];
    const float* ln2_b       = (const float*)d_in[20];
    const float* Wc1         = (const float*)d_in[21];
    const float* bc1         = (const float*)d_in[22];
    const float* Wc2         = (const float*)d_in[23];
    const float* bc2         = (const float*)d_in[24];
    float* out = (float*)d_out;

    mega_kernel<<<NBLK, NTHR>>>(embs, indices, mask, host_cat, virus_cat, extra_meta,
                                func_weights, Wr, br, Wqkv, bqkv, Wo, bo,
                                ln1_g, ln1_b, W1, b1, W2, b2, ln2_g, ln2_b,
                                Wc1, bc1, Wc2, bc2, out);
}

// round 13
// speedup vs baseline: 2.4108x; 1.0177x over previous
#include <cuda_runtime.h>
#include <cuda_bf16.h>
#include <cstdint>
#include <math.h>

// ---------------- problem constants ----------------
static constexpr int Bn = 32, Cn = 32, Sn = 16, En = 1280, Rn = 256;
static constexpr int Hn = 4, HDn = 64, FFn = 512;
static constexpr int BC = Bn * Cn;               // 1024 tokens
static constexpr int HEAD_IN = Cn * Rn + 64 + 32 + 3;  // 8291
static constexpr int QKVn = 3 * Rn;              // 768
static constexpr int HK = 8192;                  // head GEMM K (aligned part)

static constexpr int NBLK = 592;                 // persistent blocks (4 per SM)
static constexpr int NTHR = 128;                 // one worker group per block
static constexpr int NGRP = NBLK;

static constexpr int LDS_PAD = 40;               // bf16 elems per smem row (32 + 8 pad)
static constexpr int BUFB = 64 * LDS_PAD * 2;    // bytes per smem buffer (5120)

// ---------------- device scratch (fp32) ----------------
__device__ __align__(16) float g_x0p[8 * BC * Rn];    // x0 partials (split 8)
__device__ __align__(16) float g_qkvp[2 * BC * QKVn]; // qkv partials (split 2)
__device__ __align__(16) float g_opp[8 * BC * Rn];    // oproj partials (split 8)
__device__ __align__(16) float g_x1[BC * Rn];
__device__ __align__(16) float g_ff1p[4 * BC * FFn];  // ff1 partials (split 4)
__device__ __align__(16) float g_fpp[8 * BC * Rn];    // ff2 partials (split 8)
__device__ __align__(16) float g_hp[128 * 64 * 128];  // head partials (split 128)
__device__ unsigned g_bar[16];                        // monotonic barrier counters

// ---------------- pre-split bf16 activations (hi/lo) ----------------
__device__ __align__(16) unsigned short g_aggH[BC * En],  g_aggL[BC * En];
__device__ __align__(16) unsigned short g_attH[BC * Rn],  g_attL[BC * Rn];
__device__ __align__(16) unsigned short g_x1H[BC * Rn],   g_x1L[BC * Rn];
__device__ __align__(16) unsigned short g_featH[64 * HK], g_featL[64 * HK]; // rows 32-63 stay 0

// ---------------- pre-split bf16 weights (hi/lo) ----------------
__device__ __align__(16) unsigned short g_WrH[Rn * En],    g_WrL[Rn * En];
__device__ __align__(16) unsigned short g_WqH[QKVn * Rn],  g_WqL[QKVn * Rn];
__device__ __align__(16) unsigned short g_WoH[Rn * Rn],    g_WoL[Rn * Rn];
__device__ __align__(16) unsigned short g_W1H[FFn * Rn],   g_W1L[FFn * Rn];
__device__ __align__(16) unsigned short g_W2H[Rn * FFn],   g_W2L[Rn * FFn];
__device__ __align__(16) unsigned short g_WcH[128 * HK],   g_WcL[128 * HK];

// ---------------- shared memory (union across phases) ----------------
struct GemmSmem {
    unsigned short Ah[2][64 * LDS_PAD];
    unsigned short Al[2][64 * LDS_PAD];
    unsigned short Bh[2][64 * LDS_PAD];
    unsigned short Bl[2][64 * LDS_PAD];
};  // 40960 B
struct AttnSmem {
    float ks[32 * 65];
    float vs[32 * 65];
    float qs[16 * 65];
    float sc[16 * 33];
};
union SmemU {
    GemmSmem g;
    AttnSmem a;
};

// ---------------- grid-wide barrier (monotonic, replay-safe) ----------------
__device__ __forceinline__ void gsync(int k) {
    __syncthreads();
    if (threadIdx.x == 0) {
        __threadfence();
        unsigned old = atomicAdd(&g_bar[k], 1u);
        unsigned target = (old / NBLK + 1u) * NBLK;
        volatile unsigned* p = &g_bar[k];
        while (*p < target) { }
        __threadfence();
    }
    __syncthreads();
}

// ---------------- smem address helper ----------------
__device__ __forceinline__ unsigned smem_u32(const void* p) {
    unsigned addr;
    asm("{ .reg .u64 t; cvta.to.shared.u64 t, %1; cvt.u32.u64 %0, t; }"
        : "=r"(addr) : "l"(p));
    return addr;
}

// ---------------- cp.async helpers ----------------
__device__ __forceinline__ void cp16(unsigned dst, const void* src) {
    asm volatile("cp.async.cg.shared.global [%0], [%1], 16;" :: "r"(dst), "l"(src));
}
#define CP_COMMIT() asm volatile("cp.async.commit_group;" ::: "memory")
#define CP_WAIT0()  asm volatile("cp.async.wait_group 0;" ::: "memory")

// ---------------- mma / ldmatrix helpers ----------------
__device__ __forceinline__ void ldsm4(unsigned& r0, unsigned& r1, unsigned& r2, unsigned& r3,
                                      unsigned addr) {
    asm volatile("ldmatrix.sync.aligned.m8n8.x4.shared.b16 {%0,%1,%2,%3}, [%4];"
                 : "=r"(r0), "=r"(r1), "=r"(r2), "=r"(r3) : "r"(addr));
}

__device__ __forceinline__ void mma_bf16(float& c0, float& c1, float& c2, float& c3,
                                         unsigned a0, unsigned a1, unsigned a2, unsigned a3,
                                         unsigned b0, unsigned b1) {
    asm volatile(
        "mma.sync.aligned.m16n8k16.row.col.f32.bf16.bf16.f32 "
        "{%0,%1,%2,%3}, {%4,%5,%6,%7}, {%8,%9}, {%0,%1,%2,%3};"
        : "+f"(c0), "+f"(c1), "+f"(c2), "+f"(c3)
        : "r"(a0), "r"(a1), "r"(a2), "r"(a3), "r"(b0), "r"(b1));
}

__device__ __forceinline__ unsigned bf16bits(float x) {
    return (unsigned)__bfloat16_as_ushort(__float2bfloat16_rn(x));
}
__device__ __forceinline__ float bf16val(unsigned b) {
    return __bfloat162float(__ushort_as_bfloat16((unsigned short)b));
}

// split one float4 into hi/lo packed bf16 pairs (hi = rn(x), lo = rn(x - hi))
__device__ __forceinline__ void split4(float4 v, uint2& hi, uint2& lo) {
    unsigned h0 = bf16bits(v.x), h1 = bf16bits(v.y), h2 = bf16bits(v.z), h3 = bf16bits(v.w);
    unsigned l0 = bf16bits(v.x - bf16val(h0)), l1 = bf16bits(v.y - bf16val(h1));
    unsigned l2 = bf16bits(v.z - bf16val(h2)), l3 = bf16bits(v.w - bf16val(h3));
    hi.x = h0 | (h1 << 16);
    hi.y = h2 | (h3 << 16);
    lo.x = l0 | (l1 << 16);
    lo.y = l2 | (l3 << 16);
}

// scalar split-write
__device__ __forceinline__ void splitw(float v, unsigned short* __restrict__ H,
                                       unsigned short* __restrict__ L, size_t idx) {
    unsigned h = bf16bits(v);
    H[idx] = (unsigned short)h;
    L[idx] = (unsigned short)bf16bits(v - bf16val(h));
}

// ---------------- A-operand preprocessing (split-K partial sum + bias + relu) ----------------
template <int NP, bool RELUA>
__device__ __forceinline__ float4 loadPre(const float* __restrict__ A,
                                          const float* __restrict__ ab,
                                          size_t idx, int bcol, size_t SA) {
    float4 v = *(const float4*)(A + idx);
    if (NP >= 2) {
        float4 t = *(const float4*)(A + SA + idx);
        v.x += t.x; v.y += t.y; v.z += t.z; v.w += t.w;
    }
    if (NP >= 4) {
        float4 t = *(const float4*)(A + 2 * SA + idx);
        float4 u = *(const float4*)(A + 3 * SA + idx);
        v.x += t.x + u.x; v.y += t.y + u.y; v.z += t.z + u.z; v.w += t.w + u.w;
    }
    if (NP >= 8) {
        #pragma unroll
        for (int z = 4; z < 8; z++) {
            float4 t = *(const float4*)(A + (size_t)z * SA + idx);
            v.x += t.x; v.y += t.y; v.z += t.z; v.w += t.w;
        }
    }
    if (NP > 0) {
        float4 bb = *(const float4*)(ab + bcol);
        v.x += bb.x; v.y += bb.y; v.z += bb.z; v.w += bb.w;
        if (RELUA) {
            v.x = fmaxf(v.x, 0.f); v.y = fmaxf(v.y, 0.f);
            v.z = fmaxf(v.z, 0.f); v.w = fmaxf(v.w, 0.f);
        }
    }
    return v;
}

__device__ __forceinline__ float4 sum2b(const float* __restrict__ P, size_t idx, size_t S,
                                        const float* __restrict__ bias, int bi) {
    float4 a = *(const float4*)(P + idx);
    float4 b = *(const float4*)(P + S + idx);
    float4 c = *(const float4*)(bias + bi);
    a.x += b.x + c.x; a.y += b.y + c.y; a.z += b.z + c.z; a.w += b.w + c.w;
    return a;
}

// ---------------- weight split-conversion ----------------
__device__ void conv_w(const float* __restrict__ src, unsigned short* __restrict__ dh,
                       unsigned short* __restrict__ dl, int n4, int gid0, int gstride) {
    for (int i = gid0; i < n4; i += gstride) {
        float4 v = ((const float4*)src)[i];
        uint2 hi, lo;
        split4(v, hi, lo);
        *(uint2*)(dh + (size_t)i * 4) = hi;
        *(uint2*)(dl + (size_t)i * 4) = lo;
    }
}

// ---------------- shared MMA chunk (identical math to R10-12) ----------------
__device__ __forceinline__ void mma_chunk(unsigned aAh, unsigned aAl, unsigned aBh, unsigned aBl,
                                          unsigned bofs, int warp_m, int warp_n,
                                          int lrow, int lblk, float (&acc)[2][4][4]) {
    #pragma unroll
    for (int ks16 = 0; ks16 < 2; ks16++) {
        int ko = ks16 * 16;
        unsigned ah[2][4], al[2][4], bh[2][4], bl[2][4];
        #pragma unroll
        for (int i = 0; i < 2; i++) {
            unsigned o = bofs + (unsigned)(((warp_m + i * 16 + lrow) * LDS_PAD + ko + lblk * 8) * 2);
            ldsm4(ah[i][0], ah[i][1], ah[i][2], ah[i][3], aAh + o);
            ldsm4(al[i][0], al[i][1], al[i][2], al[i][3], aAl + o);
        }
        #pragma unroll
        for (int j = 0; j < 2; j++) {
            unsigned o = bofs + (unsigned)(((warp_n + j * 16 + lrow) * LDS_PAD + ko + lblk * 8) * 2);
            ldsm4(bh[j][0], bh[j][1], bh[j][2], bh[j][3], aBh + o);
            ldsm4(bl[j][0], bl[j][1], bl[j][2], bl[j][3], aBl + o);
        }
        #pragma unroll
        for (int mi = 0; mi < 2; mi++) {
            #pragma unroll
            for (int nj = 0; nj < 2; nj++) {
                #pragma unroll
                for (int h = 0; h < 2; h++) {
                    int ni = nj * 2 + h;
                    mma_bf16(acc[mi][ni][0], acc[mi][ni][1], acc[mi][ni][2], acc[mi][ni][3],
                             ah[mi][0], ah[mi][1], ah[mi][2], ah[mi][3],
                             bh[nj][h], bh[nj][2 + h]);
                    mma_bf16(acc[mi][ni][0], acc[mi][ni][1], acc[mi][ni][2], acc[mi][ni][3],
                             ah[mi][0], ah[mi][1], ah[mi][2], ah[mi][3],
                             bl[nj][h], bl[nj][2 + h]);
                    mma_bf16(acc[mi][ni][0], acc[mi][ni][1], acc[mi][ni][2], acc[mi][ni][3],
                             al[mi][0], al[mi][1], al[mi][2], al[mi][3],
                             bh[nj][h], bh[nj][2 + h]);
                }
            }
        }
    }
}

__device__ __forceinline__ void gemm_epilogue(float* __restrict__ Cout, int N,
                                              int bm0, int bn0, int warp_m, int warp_n,
                                              int quad, int pr, float (&acc)[2][4][4]) {
    #pragma unroll
    for (int mi = 0; mi < 2; mi++) {
        #pragma unroll
        for (int ni = 0; ni < 4; ni++) {
            int mrow = bm0 + warp_m + mi * 16 + quad;
            int ncol = bn0 + warp_n + ni * 8 + pr * 2;
            float2 r0; r0.x = acc[mi][ni][0]; r0.y = acc[mi][ni][1];
            float2 r1; r1.x = acc[mi][ni][2]; r1.y = acc[mi][ni][3];
            *(float2*)&Cout[(size_t)mrow * N + ncol] = r0;
            *(float2*)&Cout[(size_t)(mrow + 8) * N + ncol] = r1;
        }
    }
}

// ---------------- GEMM (SS): A and B pre-split bf16, both via cp.async ----------------
__device__ void gemm_ss(const unsigned short* __restrict__ AH, const unsigned short* __restrict__ AL,
                        const unsigned short* __restrict__ BH, const unsigned short* __restrict__ BL,
                        float* __restrict__ C, int N, int K, int ntm, int ntn, int nsplit,
                        int KS, int Mrows, GemmSmem* sg, int tid, int grp) {
    const int ntpz = ntm * ntn;
    const int ntiles = ntpz * nsplit;
    const int warp = tid >> 5, lane = tid & 31;
    const int warp_m = (warp >> 1) * 32, warp_n = (warp & 1) * 32;
    const int lrow = lane & 15, lblk = lane >> 4;
    const int quad = lane >> 2, pr = lane & 3;

    const unsigned aAh = smem_u32(sg->Ah[0]);
    const unsigned aAl = smem_u32(sg->Al[0]);
    const unsigned aBh = smem_u32(sg->Bh[0]);
    const unsigned aBl = smem_u32(sg->Bl[0]);

    const int r0 = tid >> 2, ck0 = (tid & 3) * 8;
    const int r1 = (tid + 128) >> 2, ck1 = ((tid + 128) & 3) * 8;

    int buf = 0;
    for (int tile = grp; tile < ntiles; tile += NGRP) {
        int z = tile / ntpz;
        int rem = tile - z * ntpz;
        int m = rem / ntn, n = rem - m * ntn;
        int bm0 = m * 64, bn0 = n * 64, k0s = z * KS;

        float acc[2][4][4];
        #pragma unroll
        for (int i = 0; i < 2; i++)
            #pragma unroll
            for (int j = 0; j < 4; j++)
                #pragma unroll
                for (int r = 0; r < 4; r++) { acc[i][j][r] = 0.f; }

        const int nch = KS / 32;
        // issue chunk 0 into current buf
        {
            unsigned d = (unsigned)(buf * BUFB);
            unsigned d0 = d + (unsigned)((r0 * LDS_PAD + ck0) * 2);
            unsigned d1 = d + (unsigned)((r1 * LDS_PAD + ck1) * 2);
            size_t sa0 = (size_t)(bm0 + r0) * K + k0s + ck0;
            size_t sa1 = (size_t)(bm0 + r1) * K + k0s + ck1;
            size_t sb0 = (size_t)(bn0 + r0) * K + k0s + ck0;
            size_t sb1 = (size_t)(bn0 + r1) * K + k0s + ck1;
            cp16(aAh + d0, AH + sa0); cp16(aAl + d0, AL + sa0);
            cp16(aBh + d0, BH + sb0); cp16(aBl + d0, BL + sb0);
            cp16(aAh + d1, AH + sa1); cp16(aAl + d1, AL + sa1);
            cp16(aBh + d1, BH + sb1); cp16(aBl + d1, BL + sb1);
            CP_COMMIT();
        }
        for (int ch = 0; ch < nch; ch++) {
            CP_WAIT0();
            __syncthreads();
            if (ch + 1 < nch) {
                int kc = k0s + (ch + 1) * 32;
                unsigned d = (unsigned)((buf ^ 1) * BUFB);
                unsigned d0 = d + (unsigned)((r0 * LDS_PAD + ck0) * 2);
                unsigned d1 = d + (unsigned)((r1 * LDS_PAD + ck1) * 2);
                size_t sa0 = (size_t)(bm0 + r0) * K + kc + ck0;
                size_t sa1 = (size_t)(bm0 + r1) * K + kc + ck1;
                size_t sb0 = (size_t)(bn0 + r0) * K + kc + ck0;
                size_t sb1 = (size_t)(bn0 + r1) * K + kc + ck1;
                cp16(aAh + d0, AH + sa0); cp16(aAl + d0, AL + sa0);
                cp16(aBh + d0, BH + sb0); cp16(aBl + d0, BL + sb0);
                cp16(aAh + d1, AH + sa1); cp16(aAl + d1, AL + sa1);
                cp16(aBh + d1, BH + sb1); cp16(aBl + d1, BL + sb1);
                CP_COMMIT();
            }
            mma_chunk(aAh, aAl, aBh, aBl, (unsigned)(buf * BUFB),
                      warp_m, warp_n, lrow, lblk, acc);
            buf ^= 1;
        }
        gemm_epilogue(C + (size_t)z * Mrows * N, N, bm0, bn0, warp_m, warp_n, quad, pr, acc);
    }
}

// ---------------- GEMM (RS): A fp32 partial-fused (register path), B via cp.async ----------------
template <int NP, bool RELUA>
__device__ void gemm_rs(const float* __restrict__ A, const float* __restrict__ ab,
                        const unsigned short* __restrict__ BH, const unsigned short* __restrict__ BL,
                        float* __restrict__ C, int N, int K, int ntm, int ntn, int nsplit,
                        int KS, size_t SA, int Mrows, GemmSmem* sg, int tid, int grp) {
    const int ntpz = ntm * ntn;
    const int ntiles = ntpz * nsplit;
    const int warp = tid >> 5, lane = tid & 31;
    const int warp_m = (warp >> 1) * 32, warp_n = (warp & 1) * 32;
    const int lrow = lane & 15, lblk = lane >> 4;
    const int quad = lane >> 2, pr = lane & 3;

    const unsigned aAh = smem_u32(sg->Ah[0]);
    const unsigned aAl = smem_u32(sg->Al[0]);
    const unsigned aBh = smem_u32(sg->Bh[0]);
    const unsigned aBl = smem_u32(sg->Bl[0]);

    const int r0 = tid >> 2, ck0 = (tid & 3) * 8;
    const int r1 = (tid + 128) >> 2, ck1 = ((tid + 128) & 3) * 8;

    int buf = 0;
    for (int tile = grp; tile < ntiles; tile += NGRP) {
        int z = tile / ntpz;
        int rem = tile - z * ntpz;
        int m = rem / ntn, n = rem - m * ntn;
        int bm0 = m * 64, bn0 = n * 64, k0s = z * KS;

        float acc[2][4][4];
        #pragma unroll
        for (int i = 0; i < 2; i++)
            #pragma unroll
            for (int j = 0; j < 4; j++)
                #pragma unroll
                for (int r = 0; r < 4; r++) { acc[i][j][r] = 0.f; }

        const int nch = KS / 32;
        float4 pa[4];
        // prefetch A chunk0 + issue B chunk0
        #pragma unroll
        for (int it = 0; it < 4; it++) {
            int f = tid + it * 128;
            int row = f >> 3, c4 = (f & 7) * 4;
            int kc = k0s + c4;
            pa[it] = loadPre<NP, RELUA>(A, ab, (size_t)(bm0 + row) * K + kc, kc, SA);
        }
        {
            unsigned d = (unsigned)(buf * BUFB);
            unsigned d0 = d + (unsigned)((r0 * LDS_PAD + ck0) * 2);
            unsigned d1 = d + (unsigned)((r1 * LDS_PAD + ck1) * 2);
            size_t sb0 = (size_t)(bn0 + r0) * K + k0s + ck0;
            size_t sb1 = (size_t)(bn0 + r1) * K + k0s + ck1;
            cp16(aBh + d0, BH + sb0); cp16(aBl + d0, BL + sb0);
            cp16(aBh + d1, BH + sb1); cp16(aBl + d1, BL + sb1);
            CP_COMMIT();
        }
        for (int ch = 0; ch < nch; ch++) {
            // stage A regs into buf
            #pragma unroll
            for (int it = 0; it < 4; it++) {
                int f = tid + it * 128;
                int row = f >> 3, c4 = (f & 7) * 4;
                int off = buf * (64 * LDS_PAD) + row * LDS_PAD + c4;
                uint2 hi, lo;
                split4(pa[it], hi, lo);
                *(uint2*)(sg->Ah[0] + off) = hi;
                *(uint2*)(sg->Al[0] + off) = lo;
            }
            CP_WAIT0();
            __syncthreads();
            if (ch + 1 < nch) {
                int kc = k0s + (ch + 1) * 32;
                #pragma unroll
                for (int it = 0; it < 4; it++) {
                    int f = tid + it * 128;
                    int row = f >> 3, c4 = (f & 7) * 4;
                    pa[it] = loadPre<NP, RELUA>(A, ab, (size_t)(bm0 + row) * K + kc + c4, kc + c4, SA);
                }
                unsigned d = (unsigned)((buf ^ 1) * BUFB);
                unsigned d0 = d + (unsigned)((r0 * LDS_PAD + ck0) * 2);
                unsigned d1 = d + (unsigned)((r1 * LDS_PAD + ck1) * 2);
                size_t sb0 = (size_t)(bn0 + r0) * K + kc + ck0;
                size_t sb1 = (size_t)(bn0 + r1) * K + kc + ck1;
                cp16(aBh + d0, BH + sb0); cp16(aBl + d0, BL + sb0);
                cp16(aBh + d1, BH + sb1); cp16(aBl + d1, BL + sb1);
                CP_COMMIT();
            }
            mma_chunk(aAh, aAl, aBh, aBl, (unsigned)(buf * BUFB),
                      warp_m, warp_n, lrow, lblk, acc);
            buf ^= 1;
        }
        gemm_epilogue(C + (size_t)z * Mrows * N, N, bm0, bn0, warp_m, warp_n, quad, pr, acc);
    }
}

// ---------------- attention worker ----------------
__device__ void attn_phase(AttnSmem* s, const float* __restrict__ bqkv, int tid, int grp) {
    constexpr size_t SQ = (size_t)BC * QKVn;
    for (int u = grp; u < Bn * Hn * 2; u += NGRP) {
        int b = u >> 3, h = (u >> 1) & 3, half = u & 1;
        int q0 = half * 16;
        #pragma unroll
        for (int it = 0; it < 4; it++) {
            int f = tid + it * 128;
            int c = f >> 4, d4 = (f & 15) * 4;
            size_t base = (size_t)(b * Cn + c) * QKVn + h * HDn + d4;
            float4 kv = sum2b(g_qkvp, base + Rn, SQ, bqkv, Rn + h * HDn + d4);
            float4 vv = sum2b(g_qkvp, base + 2 * Rn, SQ, bqkv, 2 * Rn + h * HDn + d4);
            s->ks[c * 65 + d4 + 0] = kv.x; s->ks[c * 65 + d4 + 1] = kv.y;
            s->ks[c * 65 + d4 + 2] = kv.z; s->ks[c * 65 + d4 + 3] = kv.w;
            s->vs[c * 65 + d4 + 0] = vv.x; s->vs[c * 65 + d4 + 1] = vv.y;
            s->vs[c * 65 + d4 + 2] = vv.z; s->vs[c * 65 + d4 + 3] = vv.w;
        }
        #pragma unroll
        for (int it = 0; it < 2; it++) {
            int f = tid + it * 128;
            int c = f >> 4, d4 = (f & 15) * 4;
            size_t base = (size_t)(b * Cn + q0 + c) * QKVn + h * HDn + d4;
            float4 qv = sum2b(g_qkvp, base, SQ, bqkv, h * HDn + d4);
            s->qs[c * 65 + d4 + 0] = qv.x; s->qs[c * 65 + d4 + 1] = qv.y;
            s->qs[c * 65 + d4 + 2] = qv.z; s->qs[c * 65 + d4 + 3] = qv.w;
        }
        __syncthreads();
        #pragma unroll
        for (int r = 0; r < 4; r++) {
            int i = tid + r * 128;
            int k = i & 31, q = i >> 5;
            float sum = 0.f;
            #pragma unroll
            for (int d = 0; d < HDn; d++) { sum = fmaf(s->qs[q * 65 + d], s->ks[k * 65 + d], sum); }
            s->sc[q * 33 + k] = sum * 0.125f;
        }
        __syncthreads();
        if (tid < 16) {
            float mx = -1e30f;
            #pragma unroll
            for (int k = 0; k < Cn; k++) { mx = fmaxf(mx, s->sc[tid * 33 + k]); }
            float sum = 0.f;
            #pragma unroll
            for (int k = 0; k < Cn; k++) {
                float e = expf(s->sc[tid * 33 + k] - mx);
                s->sc[tid * 33 + k] = e;
                sum += e;
            }
            float inv = 1.f / sum;
            #pragma unroll
            for (int k = 0; k < Cn; k++) { s->sc[tid * 33 + k] *= inv; }
        }
        __syncthreads();
        #pragma unroll
        for (int r = 0; r < 8; r++) {
            int i = tid + r * 128;
            int d = i & 63, q = i >> 6;
            float sum = 0.f;
            #pragma unroll
            for (int k = 0; k < Cn; k++) { sum = fmaf(s->sc[q * 33 + k], s->vs[k * 65 + d], sum); }
            splitw(sum, g_attH, g_attL, (size_t)(b * Cn + q0 + q) * Rn + h * HDn + d);
        }
        __syncthreads();   // smem reused by next unit
    }
}

// ---------------- LayerNorm worker: one warp per row ----------------
// NPA: residual partial count in a (1 = plain). NPP: partial count in p. WF32: also write fp32.
template <int NPA, int NPP, bool WF32>
__device__ void ln_phase(const float* __restrict__ a, const float* __restrict__ ab,
                         const float* __restrict__ p, const float* __restrict__ pb,
                         const float* __restrict__ g, const float* __restrict__ be,
                         float* __restrict__ outF,
                         unsigned short* __restrict__ outH, unsigned short* __restrict__ outL) {
    int row = blockIdx.x * (NTHR / 32) + (threadIdx.x >> 5);
    if (row >= BC) { return; }
    const size_t S = (size_t)BC * Rn;
    int lane = threadIdx.x & 31;
    float v[8];
    #pragma unroll
    for (int j = 0; j < 8; j++) {
        int c = lane + 32 * j;
        size_t o = (size_t)row * Rn + c;
        float x = a[o];
        if (NPA >= 4) { x += a[S + o] + a[2 * S + o] + a[3 * S + o]; }
        if (NPA >= 8) {
            #pragma unroll
            for (int z = 4; z < 8; z++) { x += a[(size_t)z * S + o]; }
        }
        if (NPA > 1) { x += ab[c]; }
        float y = p[o];
        if (NPP >= 2) { y += p[S + o]; }
        if (NPP >= 4) { y += p[2 * S + o] + p[3 * S + o]; }
        if (NPP >= 8) {
            #pragma unroll
            for (int z = 4; z < 8; z++) { y += p[(size_t)z * S + o]; }
        }
        v[j] = x + y + pb[c];
    }
    float sum = 0.f;
    #pragma unroll
    for (int j = 0; j < 8; j++) { sum += v[j]; }
    #pragma unroll
    for (int off = 16; off > 0; off >>= 1) { sum += __shfl_xor_sync(0xffffffffu, sum, off); }
    float mean = sum * (1.f / Rn);
    float q = 0.f;
    #pragma unroll
    for (int j = 0; j < 8; j++) { float d = v[j] - mean; q = fmaf(d, d, q); }
    #pragma unroll
    for (int off = 16; off > 0; off >>= 1) { q += __shfl_xor_sync(0xffffffffu, q, off); }
    float rstd = rsqrtf(q * (1.f / Rn) + 1e-5f);
    #pragma unroll
    for (int j = 0; j < 8; j++) {
        int c = lane + 32 * j;
        float r = (v[j] - mean) * rstd * g[c] + be[c];
        size_t o = (size_t)row * Rn + c;
        if (WF32) { outF[o] = r; }
        splitw(r, outH, outL, o);
    }
}

// ---------------- megakernel ----------------
__global__ __launch_bounds__(NTHR, 4)
void mega_kernel(const float* __restrict__ embs, const int* __restrict__ indices,
                 const int* __restrict__ mask, const float* __restrict__ host_cat,
                 const float* __restrict__ virus_cat, const float* __restrict__ extra_meta,
                 const float* __restrict__ fw,
                 const float* __restrict__ Wr, const float* __restrict__ br,
                 const float* __restrict__ Wqkv, const float* __restrict__ bqkv,
                 const float* __restrict__ Wo, const float* __restrict__ bo,
                 const float* __restrict__ ln1_g, const float* __restrict__ ln1_b,
                 const float* __restrict__ W1, const float* __restrict__ b1,
                 const float* __restrict__ W2, const float* __restrict__ b2,
                 const float* __restrict__ ln2_g, const float* __restrict__ ln2_b,
                 const float* __restrict__ Wc1, const float* __restrict__ bc1,
                 const float* __restrict__ Wc2, const float* __restrict__ bc2,
                 float* __restrict__ out) {
    __shared__ SmemU sm;
    __shared__ float s_red[4];
    const int tid = threadIdx.x;
    const int grp = blockIdx.x;
    const int gid = blockIdx.x * NTHR + tid;
    const int lane = tid & 31;

    // ---- P0: aggregation (warp-inline softmax, split bf16 output) + Wr conversion ----
    for (int u = gid; u < BC * (En / 4); u += NBLK * NTHR) {
        int bc = u / (En / 4);
        int col = u - bc * (En / 4);
        int s16 = lane & 15;
        int mval = mask[bc * Sn + s16];
        float wv = mval ? fw[indices[bc * Sn + s16]] : -1e30f;
        unsigned anyb = __ballot_sync(0xffffffffu, mval != 0);
        float mx = wv;
        #pragma unroll
        for (int off = 8; off > 0; off >>= 1) { mx = fmaxf(mx, __shfl_xor_sync(0xffffffffu, mx, off)); }
        float e = expf(wv - mx);
        float esum = e;
        #pragma unroll
        for (int off = 8; off > 0; off >>= 1) { esum += __shfl_xor_sync(0xffffffffu, esum, off); }
        float myw = (anyb & 0xffffu) ? (e / esum) : 0.f;

        const float4* eb = (const float4*)embs + (size_t)bc * Sn * (En / 4) + col;
        float4 acc;
        acc.x = 0.f; acc.y = 0.f; acc.z = 0.f; acc.w = 0.f;
        #pragma unroll
        for (int s = 0; s < Sn; s++) {
            float a = __shfl_sync(0xffffffffu, myw, s);
            float4 v = eb[s * (En / 4)];
            acc.x = fmaf(a, v.x, acc.x);
            acc.y = fmaf(a, v.y, acc.y);
            acc.z = fmaf(a, v.z, acc.z);
            acc.w = fmaf(a, v.w, acc.w);
        }
        uint2 hi, lo;
        split4(acc, hi, lo);
        *(uint2*)(g_aggH + (size_t)bc * En + col * 4) = hi;
        *(uint2*)(g_aggL + (size_t)bc * En + col * 4) = lo;
    }
    conv_w(Wr, g_WrH, g_WrL, Rn * En / 4, gid, NBLK * NTHR);
    gsync(0);

    // ---- P2: x0 partials = agg @ Wr^T (SS, split 8, KS=160, 5 chunks, 512 tiles) ----
    gemm_ss(g_aggH, g_aggL, g_WrH, g_WrL, g_x0p, Rn, En, 16, 4, 8, 160, BC, &sm.g, tid, grp);
    if (grp >= 512) {   // idle groups convert Wqkv (needed at P3)
        conv_w(Wqkv, g_WqH, g_WqL, QKVn * Rn / 4, (grp - 512) * NTHR + tid, 80 * NTHR);
    }
    gsync(1);

    // ---- P3: qkv partials = (sum8 x0p + br) @ Wqkv^T (RS, split 2, KS=128, 384 tiles) ----
    gemm_rs<8, false>(g_x0p, br, g_WqH, g_WqL, g_qkvp, QKVn, Rn, 16, 12, 2, 128,
                      (size_t)BC * Rn, BC, &sm.g, tid, grp);
    if (grp >= 384) {   // idle groups convert Wo (needed at P5)
        conv_w(Wo, g_WoH, g_WoL, Rn * Rn / 4, (grp - 384) * NTHR + tid, 208 * NTHR);
    }
    gsync(2);

    // ---- P4: attention (256 units); idle groups convert W1, W2, Wc1 ----
    attn_phase(&sm.a, bqkv, tid, grp);
    if (grp >= 256) {
        int base = (grp - 256) * NTHR + tid;
        int stride = 336 * NTHR;
        conv_w(W1, g_W1H, g_W1L, FFn * Rn / 4, base, stride);
        conv_w(W2, g_W2H, g_W2L, Rn * FFn / 4, base, stride);
        for (int i = base; i < 128 * (HK / 4); i += stride) {
            int row = i >> 11;
            int c4 = (i & 2047) * 4;
            const float* sp = Wc1 + (size_t)row * HEAD_IN + c4;
            float4 v;
            v.x = sp[0]; v.y = sp[1]; v.z = sp[2]; v.w = sp[3];
            uint2 hi, lo;
            split4(v, hi, lo);
            *(uint2*)(g_WcH + (size_t)row * HK + c4) = hi;
            *(uint2*)(g_WcL + (size_t)row * HK + c4) = lo;
        }
    }
    gsync(3);

    // ---- P5: oproj partials = att @ Wo^T (SS, split 8, KS=32, 1 chunk, 512 tiles) ----
    gemm_ss(g_attH, g_attL, g_WoH, g_WoL, g_opp, Rn, Rn, 16, 4, 8, 32, BC, &sm.g, tid, grp);
    gsync(4);

    // ---- P6: x1 = LN(sum8 x0p + br + sum8 opp + bo), write fp32 + split ----
    ln_phase<8, 8, true>(g_x0p, br, g_opp, bo, ln1_g, ln1_b, g_x1, g_x1H, g_x1L);
    gsync(5);

    // ---- P7: ff1 partials = x1 @ W1^T (SS, split 4, KS=64, 2 chunks, 512 tiles) ----
    gemm_ss(g_x1H, g_x1L, g_W1H, g_W1L, g_ff1p, FFn, Rn, 16, 8, 4, 64, BC, &sm.g, tid, grp);
    gsync(6);

    // ---- P8: ff2 partials = relu(sum4 ff1p + b1) @ W2^T (RS, split 8, KS=64, 512 tiles) ----
    gemm_rs<4, true>(g_ff1p, b1, g_W2H, g_W2L, g_fpp, Rn, FFn, 16, 4, 8, 64,
                     (size_t)BC * FFn, BC, &sm.g, tid, grp);
    gsync(7);

    // ---- P9: x2 = LN(x1 + sum8 fpp + b2) -> feat split rows 0-31 ([32, 8192] flat) ----
    ln_phase<1, 8, false>(g_x1, (const float*)0, g_fpp, b2, ln2_g, ln2_b,
                          (float*)0, g_featH, g_featL);
    gsync(8);

    // ---- P10: head GEMM: hp = feat[64, 8192] @ Wc1h[128, 8192]^T (SS, split 128, KS=64) ----
    gemm_ss(g_featH, g_featL, g_WcH, g_WcL, g_hp, 128, HK, 1, 2, 128, 64, 64, &sm.g, tid, grp);
    gsync(9);

    // ---- P11: head reduce + tail + bias + relu + logits (block b = batch b) ----
    if (grp < Bn) {
        int b = grp;
        int j = tid;
        float s = 0.f;
        #pragma unroll 16
        for (int z = 0; z < 128; z++) { s += g_hp[(size_t)z * (64 * 128) + b * 128 + j]; }
        const float* wr = Wc1 + (size_t)j * HEAD_IN + HK;
        const float* hc = host_cat + b * 64;
        #pragma unroll 8
        for (int i = 0; i < 64; i++) { s = fmaf(wr[i], hc[i], s); }
        const float* vc = virus_cat + b * 32;
        #pragma unroll 8
        for (int i = 0; i < 32; i++) { s = fmaf(wr[64 + i], vc[i], s); }
        const float* mt = extra_meta + b * 3;
        for (int i = 0; i < 3; i++) { s = fmaf(wr[96 + i], mt[i], s); }
        float hval = fmaxf(s + bc1[j], 0.f);
        float v = hval * Wc2[j];
        #pragma unroll
        for (int off = 16; off > 0; off >>= 1) { v += __shfl_xor_sync(0xffffffffu, v, off); }
        if (lane == 0) { s_red[tid >> 5] = v; }
        __syncthreads();
        if (tid == 0) { out[b] = s_red[0] + s_red[1] + s_red[2] + s_red[3] + bc2[0]; }
    }
}

// ---------------- launch ----------------
extern "C" void kernel_launch(void* const* d_in, const int* in_sizes, int n_in,
                              void* d_out, int out_size) {
    const float* embs        = (const float*)d_in[0];
    const int*   indices     = (const int*)d_in[1];
    const int*   mask        = (const int*)d_in[2];     // bool -> int32
    const float* host_cat    = (const float*)d_in[3];
    const float* virus_cat   = (const float*)d_in[4];
    const float* extra_meta  = (const float*)d_in[5];
    const float* func_weights= (const float*)d_in[6];
    const float* Wr          = (const float*)d_in[7];
    const float* br          = (const float*)d_in[8];
    const float* Wqkv        = (const float*)d_in[9];
    const float* bqkv        = (const float*)d_in[10];
    const float* Wo          = (const float*)d_in[11];
    const float* bo          = (const float*)d_in[12];
    const float* ln1_g       = (const float*)d_in[13];
    const float* ln1_b       = (const float*)d_in[14];
    const float* W1          = (const float*)d_in[15];
    const float* b1          = (const float*)d_in[16];
    const float* W2          = (const float*)d_in[17];
    const float* b2          = (const float*)d_in[18];
    const float* ln2_g       = (const float*)d_in[19];
    const float* ln2_b       = (const float*)d_in[20];
    const float* Wc1         = (const float*)d_in[21];
    const float* bc1         = (const float*)d_in[22];
    const float* Wc2         = (const float*)d_in[23];
    const float* bc2         = (const float*)d_in[24];
    float* out = (float*)d_out;

    mega_kernel<<<NBLK, NTHR>>>(embs, indices, mask, host_cat, virus_cat, extra_meta,
                                func_weights, Wr, br, Wqkv, bqkv, Wo, bo,
                                ln1_g, ln1_b, W1, b1, W2, b2, ln2_g, ln2_b,
                                Wc1, bc1, Wc2, bc2, out);
}

// round 14
// speedup vs baseline: 2.4184x; 1.0032x over previous
#include <cuda_runtime.h>
#include <cuda_bf16.h>
#include <cstdint>
#include <math.h>

// ---------------- problem constants ----------------
static constexpr int Bn = 32, Cn = 32, Sn = 16, En = 1280, Rn = 256;
static constexpr int Hn = 4, HDn = 64, FFn = 512;
static constexpr int BC = Bn * Cn;               // 1024 tokens
static constexpr int HEAD_IN = Cn * Rn + 64 + 32 + 3;  // 8291
static constexpr int QKVn = 3 * Rn;              // 768
static constexpr int HK = 8192;                  // head GEMM K (aligned part)

static constexpr int NBLK = 592;                 // persistent blocks (4 per SM)
static constexpr int NTHR = 128;                 // one worker group per block
static constexpr int NGRP = NBLK;

static constexpr int LDS_PAD = 40;               // bf16 elems per smem row (32 + 8 pad)
static constexpr int BUFB = 64 * LDS_PAD * 2;    // bytes per smem buffer (5120)

// ---------------- device scratch (fp32) ----------------
__device__ __align__(16) float g_x0p[8 * BC * Rn];    // x0 partials (split 8)
__device__ __align__(16) float g_x0[BC * Rn];         // prereduced x0 (sum8 + br)
__device__ __align__(16) float g_qkvp[2 * BC * QKVn]; // qkv partials (split 2)
__device__ __align__(16) float g_opp[8 * BC * Rn];    // oproj partials (split 8)
__device__ __align__(16) float g_x1[BC * Rn];
__device__ __align__(16) float g_ff1p[4 * BC * FFn];  // ff1 partials (split 4)
__device__ __align__(16) float g_fpp[8 * BC * Rn];    // ff2 partials (split 8)
__device__ __align__(16) float g_hp[128 * 64 * 128];  // head partials (split 128)
__device__ unsigned g_bar[16];                        // monotonic barrier counters

// ---------------- pre-split bf16 activations (hi/lo) ----------------
__device__ __align__(16) unsigned short g_aggH[BC * En],  g_aggL[BC * En];
__device__ __align__(16) unsigned short g_x0H[BC * Rn],   g_x0L[BC * Rn];
__device__ __align__(16) unsigned short g_attH[BC * Rn],  g_attL[BC * Rn];
__device__ __align__(16) unsigned short g_x1H[BC * Rn],   g_x1L[BC * Rn];
__device__ __align__(16) unsigned short g_ff1H[BC * FFn], g_ff1L[BC * FFn];
__device__ __align__(16) unsigned short g_featH[64 * HK], g_featL[64 * HK]; // rows 32-63 stay 0

// ---------------- pre-split bf16 weights (hi/lo) ----------------
__device__ __align__(16) unsigned short g_WrH[Rn * En],    g_WrL[Rn * En];
__device__ __align__(16) unsigned short g_WqH[QKVn * Rn],  g_WqL[QKVn * Rn];
__device__ __align__(16) unsigned short g_WoH[Rn * Rn],    g_WoL[Rn * Rn];
__device__ __align__(16) unsigned short g_W1H[FFn * Rn],   g_W1L[FFn * Rn];
__device__ __align__(16) unsigned short g_W2H[Rn * FFn],   g_W2L[Rn * FFn];
__device__ __align__(16) unsigned short g_WcH[128 * HK],   g_WcL[128 * HK];

// ---------------- shared memory (union across phases) ----------------
struct GemmSmem {
    unsigned short Ah[2][64 * LDS_PAD];
    unsigned short Al[2][64 * LDS_PAD];
    unsigned short Bh[2][64 * LDS_PAD];
    unsigned short Bl[2][64 * LDS_PAD];
};  // 40960 B
struct AttnSmem {
    float ks[32 * 65];
    float vs[32 * 65];
    float qs[16 * 65];
    float sc[16 * 33];
};
union SmemU {
    GemmSmem g;
    AttnSmem a;
};

// ---------------- grid-wide barrier (monotonic, replay-safe) ----------------
__device__ __forceinline__ void gsync(int k) {
    __syncthreads();
    if (threadIdx.x == 0) {
        __threadfence();
        unsigned old = atomicAdd(&g_bar[k], 1u);
        unsigned target = (old / NBLK + 1u) * NBLK;
        volatile unsigned* p = &g_bar[k];
        while (*p < target) { }
        __threadfence();
    }
    __syncthreads();
}

// ---------------- smem address helper ----------------
__device__ __forceinline__ unsigned smem_u32(const void* p) {
    unsigned addr;
    asm("{ .reg .u64 t; cvta.to.shared.u64 t, %1; cvt.u32.u64 %0, t; }"
        : "=r"(addr) : "l"(p));
    return addr;
}

// ---------------- cp.async helpers ----------------
__device__ __forceinline__ void cp16(unsigned dst, const void* src) {
    asm volatile("cp.async.cg.shared.global [%0], [%1], 16;" :: "r"(dst), "l"(src));
}
#define CP_COMMIT() asm volatile("cp.async.commit_group;" ::: "memory")
#define CP_WAIT0()  asm volatile("cp.async.wait_group 0;" ::: "memory")

// ---------------- mma / ldmatrix helpers ----------------
__device__ __forceinline__ void ldsm4(unsigned& r0, unsigned& r1, unsigned& r2, unsigned& r3,
                                      unsigned addr) {
    asm volatile("ldmatrix.sync.aligned.m8n8.x4.shared.b16 {%0,%1,%2,%3}, [%4];"
                 : "=r"(r0), "=r"(r1), "=r"(r2), "=r"(r3) : "r"(addr));
}

__device__ __forceinline__ void mma_bf16(float& c0, float& c1, float& c2, float& c3,
                                         unsigned a0, unsigned a1, unsigned a2, unsigned a3,
                                         unsigned b0, unsigned b1) {
    asm volatile(
        "mma.sync.aligned.m16n8k16.row.col.f32.bf16.bf16.f32 "
        "{%0,%1,%2,%3}, {%4,%5,%6,%7}, {%8,%9}, {%0,%1,%2,%3};"
        : "+f"(c0), "+f"(c1), "+f"(c2), "+f"(c3)
        : "r"(a0), "r"(a1), "r"(a2), "r"(a3), "r"(b0), "r"(b1));
}

__device__ __forceinline__ unsigned bf16bits(float x) {
    return (unsigned)__bfloat16_as_ushort(__float2bfloat16_rn(x));
}
__device__ __forceinline__ float bf16val(unsigned b) {
    return __bfloat162float(__ushort_as_bfloat16((unsigned short)b));
}

// split one float4 into hi/lo packed bf16 pairs (hi = rn(x), lo = rn(x - hi))
__device__ __forceinline__ void split4(float4 v, uint2& hi, uint2& lo) {
    unsigned h0 = bf16bits(v.x), h1 = bf16bits(v.y), h2 = bf16bits(v.z), h3 = bf16bits(v.w);
    unsigned l0 = bf16bits(v.x - bf16val(h0)), l1 = bf16bits(v.y - bf16val(h1));
    unsigned l2 = bf16bits(v.z - bf16val(h2)), l3 = bf16bits(v.w - bf16val(h3));
    hi.x = h0 | (h1 << 16);
    hi.y = h2 | (h3 << 16);
    lo.x = l0 | (l1 << 16);
    lo.y = l2 | (l3 << 16);
}

// scalar split-write
__device__ __forceinline__ void splitw(float v, unsigned short* __restrict__ H,
                                       unsigned short* __restrict__ L, size_t idx) {
    unsigned h = bf16bits(v);
    H[idx] = (unsigned short)h;
    L[idx] = (unsigned short)bf16bits(v - bf16val(h));
}

__device__ __forceinline__ float4 sum2b(const float* __restrict__ P, size_t idx, size_t S,
                                        const float* __restrict__ bias, int bi) {
    float4 a = *(const float4*)(P + idx);
    float4 b = *(const float4*)(P + S + idx);
    float4 c = *(const float4*)(bias + bi);
    a.x += b.x + c.x; a.y += b.y + c.y; a.z += b.z + c.z; a.w += b.w + c.w;
    return a;
}

// ---------------- weight split-conversion ----------------
__device__ void conv_w(const float* __restrict__ src, unsigned short* __restrict__ dh,
                       unsigned short* __restrict__ dl, int n4, int gid0, int gstride) {
    for (int i = gid0; i < n4; i += gstride) {
        float4 v = ((const float4*)src)[i];
        uint2 hi, lo;
        split4(v, hi, lo);
        *(uint2*)(dh + (size_t)i * 4) = hi;
        *(uint2*)(dl + (size_t)i * 4) = lo;
    }
}

// ---------------- shared MMA chunk ----------------
__device__ __forceinline__ void mma_chunk(unsigned aAh, unsigned aAl, unsigned aBh, unsigned aBl,
                                          unsigned bofs, int warp_m, int warp_n,
                                          int lrow, int lblk, float (&acc)[2][4][4]) {
    #pragma unroll
    for (int ks16 = 0; ks16 < 2; ks16++) {
        int ko = ks16 * 16;
        unsigned ah[2][4], al[2][4], bh[2][4], bl[2][4];
        #pragma unroll
        for (int i = 0; i < 2; i++) {
            unsigned o = bofs + (unsigned)(((warp_m + i * 16 + lrow) * LDS_PAD + ko + lblk * 8) * 2);
            ldsm4(ah[i][0], ah[i][1], ah[i][2], ah[i][3], aAh + o);
            ldsm4(al[i][0], al[i][1], al[i][2], al[i][3], aAl + o);
        }
        #pragma unroll
        for (int j = 0; j < 2; j++) {
            unsigned o = bofs + (unsigned)(((warp_n + j * 16 + lrow) * LDS_PAD + ko + lblk * 8) * 2);
            ldsm4(bh[j][0], bh[j][1], bh[j][2], bh[j][3], aBh + o);
            ldsm4(bl[j][0], bl[j][1], bl[j][2], bl[j][3], aBl + o);
        }
        #pragma unroll
        for (int mi = 0; mi < 2; mi++) {
            #pragma unroll
            for (int nj = 0; nj < 2; nj++) {
                #pragma unroll
                for (int h = 0; h < 2; h++) {
                    int ni = nj * 2 + h;
                    mma_bf16(acc[mi][ni][0], acc[mi][ni][1], acc[mi][ni][2], acc[mi][ni][3],
                             ah[mi][0], ah[mi][1], ah[mi][2], ah[mi][3],
                             bh[nj][h], bh[nj][2 + h]);
                    mma_bf16(acc[mi][ni][0], acc[mi][ni][1], acc[mi][ni][2], acc[mi][ni][3],
                             ah[mi][0], ah[mi][1], ah[mi][2], ah[mi][3],
                             bl[nj][h], bl[nj][2 + h]);
                    mma_bf16(acc[mi][ni][0], acc[mi][ni][1], acc[mi][ni][2], acc[mi][ni][3],
                             al[mi][0], al[mi][1], al[mi][2], al[mi][3],
                             bh[nj][h], bh[nj][2 + h]);
                }
            }
        }
    }
}

__device__ __forceinline__ void gemm_epilogue(float* __restrict__ Cout, int N,
                                              int bm0, int bn0, int warp_m, int warp_n,
                                              int quad, int pr, float (&acc)[2][4][4]) {
    #pragma unroll
    for (int mi = 0; mi < 2; mi++) {
        #pragma unroll
        for (int ni = 0; ni < 4; ni++) {
            int mrow = bm0 + warp_m + mi * 16 + quad;
            int ncol = bn0 + warp_n + ni * 8 + pr * 2;
            float2 r0; r0.x = acc[mi][ni][0]; r0.y = acc[mi][ni][1];
            float2 r1; r1.x = acc[mi][ni][2]; r1.y = acc[mi][ni][3];
            *(float2*)&Cout[(size_t)mrow * N + ncol] = r0;
            *(float2*)&Cout[(size_t)(mrow + 8) * N + ncol] = r1;
        }
    }
}

// ---------------- GEMM (SS): A and B pre-split bf16, both via cp.async ----------------
__device__ void gemm_ss(const unsigned short* __restrict__ AH, const unsigned short* __restrict__ AL,
                        const unsigned short* __restrict__ BH, const unsigned short* __restrict__ BL,
                        float* __restrict__ C, int N, int K, int ntm, int ntn, int nsplit,
                        int KS, int Mrows, GemmSmem* sg, int tid, int grp) {
    const int ntpz = ntm * ntn;
    const int ntiles = ntpz * nsplit;
    const int warp = tid >> 5, lane = tid & 31;
    const int warp_m = (warp >> 1) * 32, warp_n = (warp & 1) * 32;
    const int lrow = lane & 15, lblk = lane >> 4;
    const int quad = lane >> 2, pr = lane & 3;

    const unsigned aAh = smem_u32(sg->Ah[0]);
    const unsigned aAl = smem_u32(sg->Al[0]);
    const unsigned aBh = smem_u32(sg->Bh[0]);
    const unsigned aBl = smem_u32(sg->Bl[0]);

    const int r0 = tid >> 2, ck0 = (tid & 3) * 8;
    const int r1 = (tid + 128) >> 2, ck1 = ((tid + 128) & 3) * 8;

    int buf = 0;
    for (int tile = grp; tile < ntiles; tile += NGRP) {
        int z = tile / ntpz;
        int rem = tile - z * ntpz;
        int m = rem / ntn, n = rem - m * ntn;
        int bm0 = m * 64, bn0 = n * 64, k0s = z * KS;

        float acc[2][4][4];
        #pragma unroll
        for (int i = 0; i < 2; i++)
            #pragma unroll
            for (int j = 0; j < 4; j++)
                #pragma unroll
                for (int r = 0; r < 4; r++) { acc[i][j][r] = 0.f; }

        const int nch = KS / 32;
        {
            unsigned d = (unsigned)(buf * BUFB);
            unsigned d0 = d + (unsigned)((r0 * LDS_PAD + ck0) * 2);
            unsigned d1 = d + (unsigned)((r1 * LDS_PAD + ck1) * 2);
            size_t sa0 = (size_t)(bm0 + r0) * K + k0s + ck0;
            size_t sa1 = (size_t)(bm0 + r1) * K + k0s + ck1;
            size_t sb0 = (size_t)(bn0 + r0) * K + k0s + ck0;
            size_t sb1 = (size_t)(bn0 + r1) * K + k0s + ck1;
            cp16(aAh + d0, AH + sa0); cp16(aAl + d0, AL + sa0);
            cp16(aBh + d0, BH + sb0); cp16(aBl + d0, BL + sb0);
            cp16(aAh + d1, AH + sa1); cp16(aAl + d1, AL + sa1);
            cp16(aBh + d1, BH + sb1); cp16(aBl + d1, BL + sb1);
            CP_COMMIT();
        }
        for (int ch = 0; ch < nch; ch++) {
            CP_WAIT0();
            __syncthreads();
            if (ch + 1 < nch) {
                int kc = k0s + (ch + 1) * 32;
                unsigned d = (unsigned)((buf ^ 1) * BUFB);
                unsigned d0 = d + (unsigned)((r0 * LDS_PAD + ck0) * 2);
                unsigned d1 = d + (unsigned)((r1 * LDS_PAD + ck1) * 2);
                size_t sa0 = (size_t)(bm0 + r0) * K + kc + ck0;
                size_t sa1 = (size_t)(bm0 + r1) * K + kc + ck1;
                size_t sb0 = (size_t)(bn0 + r0) * K + kc + ck0;
                size_t sb1 = (size_t)(bn0 + r1) * K + kc + ck1;
                cp16(aAh + d0, AH + sa0); cp16(aAl + d0, AL + sa0);
                cp16(aBh + d0, BH + sb0); cp16(aBl + d0, BL + sb0);
                cp16(aAh + d1, AH + sa1); cp16(aAl + d1, AL + sa1);
                cp16(aBh + d1, BH + sb1); cp16(aBl + d1, BL + sb1);
                CP_COMMIT();
            }
            mma_chunk(aAh, aAl, aBh, aBl, (unsigned)(buf * BUFB),
                      warp_m, warp_n, lrow, lblk, acc);
            buf ^= 1;
        }
        gemm_epilogue(C + (size_t)z * Mrows * N, N, bm0, bn0, warp_m, warp_n, quad, pr, acc);
    }
}

// ---------------- attention worker ----------------
__device__ void attn_phase(AttnSmem* s, const float* __restrict__ bqkv, int tid, int grp) {
    constexpr size_t SQ = (size_t)BC * QKVn;
    for (int u = grp; u < Bn * Hn * 2; u += NGRP) {
        int b = u >> 3, h = (u >> 1) & 3, half = u & 1;
        int q0 = half * 16;
        #pragma unroll
        for (int it = 0; it < 4; it++) {
            int f = tid + it * 128;
            int c = f >> 4, d4 = (f & 15) * 4;
            size_t base = (size_t)(b * Cn + c) * QKVn + h * HDn + d4;
            float4 kv = sum2b(g_qkvp, base + Rn, SQ, bqkv, Rn + h * HDn + d4);
            float4 vv = sum2b(g_qkvp, base + 2 * Rn, SQ, bqkv, 2 * Rn + h * HDn + d4);
            s->ks[c * 65 + d4 + 0] = kv.x; s->ks[c * 65 + d4 + 1] = kv.y;
            s->ks[c * 65 + d4 + 2] = kv.z; s->ks[c * 65 + d4 + 3] = kv.w;
            s->vs[c * 65 + d4 + 0] = vv.x; s->vs[c * 65 + d4 + 1] = vv.y;
            s->vs[c * 65 + d4 + 2] = vv.z; s->vs[c * 65 + d4 + 3] = vv.w;
        }
        #pragma unroll
        for (int it = 0; it < 2; it++) {
            int f = tid + it * 128;
            int c = f >> 4, d4 = (f & 15) * 4;
            size_t base = (size_t)(b * Cn + q0 + c) * QKVn + h * HDn + d4;
            float4 qv = sum2b(g_qkvp, base, SQ, bqkv, h * HDn + d4);
            s->qs[c * 65 + d4 + 0] = qv.x; s->qs[c * 65 + d4 + 1] = qv.y;
            s->qs[c * 65 + d4 + 2] = qv.z; s->qs[c * 65 + d4 + 3] = qv.w;
        }
        __syncthreads();
        #pragma unroll
        for (int r = 0; r < 4; r++) {
            int i = tid + r * 128;
            int k = i & 31, q = i >> 5;
            float sum = 0.f;
            #pragma unroll
            for (int d = 0; d < HDn; d++) { sum = fmaf(s->qs[q * 65 + d], s->ks[k * 65 + d], sum); }
            s->sc[q * 33 + k] = sum * 0.125f;
        }
        __syncthreads();
        if (tid < 16) {
            float mx = -1e30f;
            #pragma unroll
            for (int k = 0; k < Cn; k++) { mx = fmaxf(mx, s->sc[tid * 33 + k]); }
            float sum = 0.f;
            #pragma unroll
            for (int k = 0; k < Cn; k++) {
                float e = expf(s->sc[tid * 33 + k] - mx);
                s->sc[tid * 33 + k] = e;
                sum += e;
            }
            float inv = 1.f / sum;
            #pragma unroll
            for (int k = 0; k < Cn; k++) { s->sc[tid * 33 + k] *= inv; }
        }
        __syncthreads();
        #pragma unroll
        for (int r = 0; r < 8; r++) {
            int i = tid + r * 128;
            int d = i & 63, q = i >> 6;
            float sum = 0.f;
            #pragma unroll
            for (int k = 0; k < Cn; k++) { sum = fmaf(s->sc[q * 33 + k], s->vs[k * 65 + d], sum); }
            splitw(sum, g_attH, g_attL, (size_t)(b * Cn + q0 + q) * Rn + h * HDn + d);
        }
        __syncthreads();   // smem reused by next unit
    }
}

// ---------------- LayerNorm worker: one warp per row ----------------
// NPA: residual partial count in a (1 = plain). NPP: partial count in p. WF32: also write fp32.
template <int NPA, int NPP, bool WF32>
__device__ void ln_phase(const float* __restrict__ a, const float* __restrict__ ab,
                         const float* __restrict__ p, const float* __restrict__ pb,
                         const float* __restrict__ g, const float* __restrict__ be,
                         float* __restrict__ outF,
                         unsigned short* __restrict__ outH, unsigned short* __restrict__ outL) {
    int row = blockIdx.x * (NTHR / 32) + (threadIdx.x >> 5);
    if (row >= BC) { return; }
    const size_t S = (size_t)BC * Rn;
    int lane = threadIdx.x & 31;
    float v[8];
    #pragma unroll
    for (int j = 0; j < 8; j++) {
        int c = lane + 32 * j;
        size_t o = (size_t)row * Rn + c;
        float x = a[o];
        if (NPA >= 4) { x += a[S + o] + a[2 * S + o] + a[3 * S + o]; }
        if (NPA >= 8) {
            #pragma unroll
            for (int z = 4; z < 8; z++) { x += a[(size_t)z * S + o]; }
        }
        if (NPA > 1) { x += ab[c]; }
        float y = p[o];
        if (NPP >= 2) { y += p[S + o]; }
        if (NPP >= 4) { y += p[2 * S + o] + p[3 * S + o]; }
        if (NPP >= 8) {
            #pragma unroll
            for (int z = 4; z < 8; z++) { y += p[(size_t)z * S + o]; }
        }
        v[j] = x + y + pb[c];
    }
    float sum = 0.f;
    #pragma unroll
    for (int j = 0; j < 8; j++) { sum += v[j]; }
    #pragma unroll
    for (int off = 16; off > 0; off >>= 1) { sum += __shfl_xor_sync(0xffffffffu, sum, off); }
    float mean = sum * (1.f / Rn);
    float q = 0.f;
    #pragma unroll
    for (int j = 0; j < 8; j++) { float d = v[j] - mean; q = fmaf(d, d, q); }
    #pragma unroll
    for (int off = 16; off > 0; off >>= 1) { q += __shfl_xor_sync(0xffffffffu, q, off); }
    float rstd = rsqrtf(q * (1.f / Rn) + 1e-5f);
    #pragma unroll
    for (int j = 0; j < 8; j++) {
        int c = lane + 32 * j;
        float r = (v[j] - mean) * rstd * g[c] + be[c];
        size_t o = (size_t)row * Rn + c;
        if (WF32) { outF[o] = r; }
        splitw(r, outH, outL, o);
    }
}

// ---------------- megakernel ----------------
__global__ __launch_bounds__(NTHR, 4)
void mega_kernel(const float* __restrict__ embs, const int* __restrict__ indices,
                 const int* __restrict__ mask, const float* __restrict__ host_cat,
                 const float* __restrict__ virus_cat, const float* __restrict__ extra_meta,
                 const float* __restrict__ fw,
                 const float* __restrict__ Wr, const float* __restrict__ br,
                 const float* __restrict__ Wqkv, const float* __restrict__ bqkv,
                 const float* __restrict__ Wo, const float* __restrict__ bo,
                 const float* __restrict__ ln1_g, const float* __restrict__ ln1_b,
                 const float* __restrict__ W1, const float* __restrict__ b1,
                 const float* __restrict__ W2, const float* __restrict__ b2,
                 const float* __restrict__ ln2_g, const float* __restrict__ ln2_b,
                 const float* __restrict__ Wc1, const float* __restrict__ bc1,
                 const float* __restrict__ Wc2, const float* __restrict__ bc2,
                 float* __restrict__ out) {
    __shared__ SmemU sm;
    __shared__ float s_red[4];
    const int tid = threadIdx.x;
    const int grp = blockIdx.x;
    const int gid = blockIdx.x * NTHR + tid;
    const int lane = tid & 31;

    // ---- P0: aggregation (warp-inline softmax, split bf16 output) + Wr conversion ----
    for (int u = gid; u < BC * (En / 4); u += NBLK * NTHR) {
        int bc = u / (En / 4);
        int col = u - bc * (En / 4);
        int s16 = lane & 15;
        int mval = mask[bc * Sn + s16];
        float wv = mval ? fw[indices[bc * Sn + s16]] : -1e30f;
        unsigned anyb = __ballot_sync(0xffffffffu, mval != 0);
        float mx = wv;
        #pragma unroll
        for (int off = 8; off > 0; off >>= 1) { mx = fmaxf(mx, __shfl_xor_sync(0xffffffffu, mx, off)); }
        float e = expf(wv - mx);
        float esum = e;
        #pragma unroll
        for (int off = 8; off > 0; off >>= 1) { esum += __shfl_xor_sync(0xffffffffu, esum, off); }
        float myw = (anyb & 0xffffu) ? (e / esum) : 0.f;

        const float4* eb = (const float4*)embs + (size_t)bc * Sn * (En / 4) + col;
        float4 acc;
        acc.x = 0.f; acc.y = 0.f; acc.z = 0.f; acc.w = 0.f;
        #pragma unroll
        for (int s = 0; s < Sn; s++) {
            float a = __shfl_sync(0xffffffffu, myw, s);
            float4 v = eb[s * (En / 4)];
            acc.x = fmaf(a, v.x, acc.x);
            acc.y = fmaf(a, v.y, acc.y);
            acc.z = fmaf(a, v.z, acc.z);
            acc.w = fmaf(a, v.w, acc.w);
        }
        uint2 hi, lo;
        split4(acc, hi, lo);
        *(uint2*)(g_aggH + (size_t)bc * En + col * 4) = hi;
        *(uint2*)(g_aggL + (size_t)bc * En + col * 4) = lo;
    }
    conv_w(Wr, g_WrH, g_WrL, Rn * En / 4, gid, NBLK * NTHR);
    gsync(0);

    // ---- P2: x0 partials = agg @ Wr^T (SS, split 8, KS=160, 5 chunks, 512 tiles) ----
    gemm_ss(g_aggH, g_aggL, g_WrH, g_WrL, g_x0p, Rn, En, 16, 4, 8, 160, BC, &sm.g, tid, grp);
    if (grp >= 512) {   // idle groups convert Wqkv (needed at P3)
        conv_w(Wqkv, g_WqH, g_WqL, QKVn * Rn / 4, (grp - 512) * NTHR + tid, 80 * NTHR);
    }
    gsync(1);

    // ---- R1: x0 = sum8(x0p) + br  -> fp32 + bf16 split ----
    {
        constexpr size_t S = (size_t)BC * Rn;
        for (int i = gid; i < BC * Rn / 4; i += NBLK * NTHR) {
            size_t o = (size_t)i * 4;
            float4 v = *(const float4*)(g_x0p + o);
            #pragma unroll
            for (int z = 1; z < 8; z++) {
                float4 t = *(const float4*)(g_x0p + (size_t)z * S + o);
                v.x += t.x; v.y += t.y; v.z += t.z; v.w += t.w;
            }
            float4 bb = *(const float4*)(br + (i & 63) * 4);
            v.x += bb.x; v.y += bb.y; v.z += bb.z; v.w += bb.w;
            *(float4*)(g_x0 + o) = v;
            uint2 hi, lo;
            split4(v, hi, lo);
            *(uint2*)(g_x0H + o) = hi;
            *(uint2*)(g_x0L + o) = lo;
        }
    }
    gsync(2);

    // ---- P3: qkv partials = x0 @ Wqkv^T (SS, split 2, KS=128, 384 tiles) ----
    gemm_ss(g_x0H, g_x0L, g_WqH, g_WqL, g_qkvp, QKVn, Rn, 16, 12, 2, 128, BC, &sm.g, tid, grp);
    if (grp >= 384) {   // idle groups convert Wo (needed at P5)
        conv_w(Wo, g_WoH, g_WoL, Rn * Rn / 4, (grp - 384) * NTHR + tid, 208 * NTHR);
    }
    gsync(3);

    // ---- P4: attention (256 units); idle groups convert W1, W2, Wc1 ----
    attn_phase(&sm.a, bqkv, tid, grp);
    if (grp >= 256) {
        int base = (grp - 256) * NTHR + tid;
        int stride = 336 * NTHR;
        conv_w(W1, g_W1H, g_W1L, FFn * Rn / 4, base, stride);
        conv_w(W2, g_W2H, g_W2L, Rn * FFn / 4, base, stride);
        for (int i = base; i < 128 * (HK / 4); i += stride) {
            int row = i >> 11;
            int c4 = (i & 2047) * 4;
            const float* sp = Wc1 + (size_t)row * HEAD_IN + c4;
            float4 v;
            v.x = sp[0]; v.y = sp[1]; v.z = sp[2]; v.w = sp[3];
            uint2 hi, lo;
            split4(v, hi, lo);
            *(uint2*)(g_WcH + (size_t)row * HK + c4) = hi;
            *(uint2*)(g_WcL + (size_t)row * HK + c4) = lo;
        }
    }
    gsync(4);

    // ---- P5: oproj partials = att @ Wo^T (SS, split 8, KS=32, 1 chunk, 512 tiles) ----
    gemm_ss(g_attH, g_attL, g_WoH, g_WoL, g_opp, Rn, Rn, 16, 4, 8, 32, BC, &sm.g, tid, grp);
    gsync(5);

    // ---- P6: x1 = LN(x0 + sum8 opp + bo), write fp32 + split ----
    ln_phase<1, 8, true>(g_x0, (const float*)0, g_opp, bo, ln1_g, ln1_b, g_x1, g_x1H, g_x1L);
    gsync(6);

    // ---- P7: ff1 partials = x1 @ W1^T (SS, split 4, KS=64, 2 chunks, 512 tiles) ----
    gemm_ss(g_x1H, g_x1L, g_W1H, g_W1L, g_ff1p, FFn, Rn, 16, 8, 4, 64, BC, &sm.g, tid, grp);
    gsync(7);

    // ---- R2: ff1s = relu(sum4(ff1p) + b1) -> bf16 split ----
    {
        constexpr size_t S = (size_t)BC * FFn;
        for (int i = gid; i < BC * FFn / 4; i += NBLK * NTHR) {
            size_t o = (size_t)i * 4;
            float4 v = *(const float4*)(g_ff1p + o);
            #pragma unroll
            for (int z = 1; z < 4; z++) {
                float4 t = *(const float4*)(g_ff1p + (size_t)z * S + o);
                v.x += t.x; v.y += t.y; v.z += t.z; v.w += t.w;
            }
            float4 bb = *(const float4*)(b1 + (i & 127) * 4);
            v.x = fmaxf(v.x + bb.x, 0.f);
            v.y = fmaxf(v.y + bb.y, 0.f);
            v.z = fmaxf(v.z + bb.z, 0.f);
            v.w = fmaxf(v.w + bb.w, 0.f);
            uint2 hi, lo;
            split4(v, hi, lo);
            *(uint2*)(g_ff1H + o) = hi;
            *(uint2*)(g_ff1L + o) = lo;
        }
    }
    gsync(8);

    // ---- P8: ff2 partials = ff1s @ W2^T (SS, split 8, KS=64, 2 chunks, 512 tiles) ----
    gemm_ss(g_ff1H, g_ff1L, g_W2H, g_W2L, g_fpp, Rn, FFn, 16, 4, 8, 64, BC, &sm.g, tid, grp);
    gsync(9);

    // ---- P9: x2 = LN(x1 + sum8 fpp + b2) -> feat split rows 0-31 ([32, 8192] flat) ----
    ln_phase<1, 8, false>(g_x1, (const float*)0, g_fpp, b2, ln2_g, ln2_b,
                          (float*)0, g_featH, g_featL);
    gsync(10);

    // ---- P10: head GEMM: hp = feat[64, 8192] @ Wc1h[128, 8192]^T (SS, split 128, KS=64) ----
    gemm_ss(g_featH, g_featL, g_WcH, g_WcL, g_hp, 128, HK, 1, 2, 128, 64, 64, &sm.g, tid, grp);
    gsync(11);

    // ---- P11: head reduce + tail + bias + relu + logits (block b = batch b) ----
    if (grp < Bn) {
        int b = grp;
        int j = tid;
        float s = 0.f;
        #pragma unroll 16
        for (int z = 0; z < 128; z++) { s += g_hp[(size_t)z * (64 * 128) + b * 128 + j]; }
        const float* wr = Wc1 + (size_t)j * HEAD_IN + HK;
        const float* hc = host_cat + b * 64;
        #pragma unroll 8
        for (int i = 0; i < 64; i++) { s = fmaf(wr[i], hc[i], s); }
        const float* vc = virus_cat + b * 32;
        #pragma unroll 8
        for (int i = 0; i < 32; i++) { s = fmaf(wr[64 + i], vc[i], s); }
        const float* mt = extra_meta + b * 3;
        for (int i = 0; i < 3; i++) { s = fmaf(wr[96 + i], mt[i], s); }
        float hval = fmaxf(s + bc1[j], 0.f);
        float v = hval * Wc2[j];
        #pragma unroll
        for (int off = 16; off > 0; off >>= 1) { v += __shfl_xor_sync(0xffffffffu, v, off); }
        if (lane == 0) { s_red[tid >> 5] = v; }
        __syncthreads();
        if (tid == 0) { out[b] = s_red[0] + s_red[1] + s_red[2] + s_red[3] + bc2[0]; }
    }
}

// ---------------- launch ----------------
extern "C" void kernel_launch(void* const* d_in, const int* in_sizes, int n_in,
                              void* d_out, int out_size) {
    const float* embs        = (const float*)d_in[0];
    const int*   indices     = (const int*)d_in[1];
    const int*   mask        = (const int*)d_in[2];     // bool -> int32
    const float* host_cat    = (const float*)d_in[3];
    const float* virus_cat   = (const float*)d_in[4];
    const float* extra_meta  = (const float*)d_in[5];
    const float* func_weights= (const float*)d_in[6];
    const float* Wr          = (const float*)d_in[7];
    const float* br          = (const float*)d_in[8];
    const float* Wqkv        = (const float*)d_in[9];
    const float* bqkv        = (const float*)d_in[10];
    const float* Wo          = (const float*)d_in[11];
    const float* bo          = (const float*)d_in[12];
    const float* ln1_g       = (const float*)d_in[13];
    const float* ln1_b       = (const float*)d_in[14];
    const float* W1          = (const float*)d_in[15];
    const float* b1          = (const float*)d_in[16];
    const float* W2          = (const float*)d_in[17];
    const float* b2          = (const float*)d_in[18];
    const float* ln2_g       = (const float*)d_in[19];
    const float* ln2_b       = (const float*)d_in[20];
    const float* Wc1         = (const float*)d_in[21];
    const float* bc1         = (const float*)d_in[22];
    const float* Wc2         = (const float*)d_in[23];
    const float* bc2         = (const float*)d_in[24];
    float* out = (float*)d_out;

    mega_kernel<<<NBLK, NTHR>>>(embs, indices, mask, host_cat, virus_cat, extra_meta,
                                func_weights, Wr, br, Wqkv, bqkv, Wo, bo,
                                ln1_g, ln1_b, W1, b1, W2, b2, ln2_g, ln2_b,
                                Wc1, bc1, Wc2, bc2, out);
}